// round 9
// baseline (speedup 1.0000x reference)
#include <cuda_runtime.h>
#include <cuda_bf16.h>
#include <math.h>
#include <stdint.h>

// ---------------- problem constants ----------------
#define S_LEN   2048
#define HID     3584
#define NHQ     16
#define NKV     8
#define DH      256
#define GROUPS  2
#define WINDOW  1024
#define BANDW   1152
#define SOFTCAP 50.0f
#define SCALING 0.0625f

typedef __nv_bfloat16 bf16;

// ---------------- device scratch ----------------
__device__ float g_Q [(size_t)S_LEN * NHQ * DH];
__device__ float g_K [(size_t)S_LEN * NKV * DH];
__device__ float g_V [(size_t)S_LEN * NKV * DH];
__device__ float g_S [(size_t)NHQ * S_LEN * BANDW];
__device__ float g_AO[(size_t)S_LEN * NHQ * DH];

// int8 operand slices + row scales
__device__ int8_t g_hq1 [(size_t)S_LEN * HID],      g_hq2 [(size_t)S_LEN * HID];
__device__ int8_t g_wqq1[(size_t)NHQ * DH * HID],   g_wqq2[(size_t)NHQ * DH * HID];
__device__ int8_t g_wkq1[(size_t)NKV * DH * HID],   g_wkq2[(size_t)NKV * DH * HID];
__device__ int8_t g_wvq1[(size_t)NKV * DH * HID],   g_wvq2[(size_t)NKV * DH * HID];
__device__ int8_t g_woq1[(size_t)HID * NHQ * DH],   g_woq2[(size_t)HID * NHQ * DH];
__device__ int8_t g_Qq1 [(size_t)S_LEN * NHQ * DH], g_Qq2 [(size_t)S_LEN * NHQ * DH];
__device__ int8_t g_Kq1 [(size_t)S_LEN * NKV * DH], g_Kq2 [(size_t)S_LEN * NKV * DH];
__device__ int8_t g_AOq1[(size_t)S_LEN * NHQ * DH], g_AOq2[(size_t)S_LEN * NHQ * DH];

__device__ float g_s_hs[S_LEN], g_s_wq[NHQ * DH], g_s_wk[NKV * DH], g_s_wv[NKV * DH];
__device__ float g_s_wo[HID],  g_s_AO[S_LEN];
__device__ float g_sQ[S_LEN * NHQ], g_sK[S_LEN * NKV];

// bf16 split buffers (PV path only)
__device__ bf16 g_VtH[(size_t)NKV * DH * S_LEN], g_VtL[(size_t)NKV * DH * S_LEN];
__device__ bf16 g_PH [(size_t)NHQ * S_LEN * BANDW], g_PL[(size_t)NHQ * S_LEN * BANDW];

// ---------------- helpers ----------------
__device__ __forceinline__ uint32_t smem_u32(const void* p) {
    uint32_t a;
    asm("{ .reg .u64 t; cvta.to.shared.u64 t, %1; cvt.u32.u64 %0, t; }" : "=r"(a) : "l"(p));
    return a;
}
__device__ __forceinline__ void cp16(uint32_t saddr, const void* g) {
    asm volatile("cp.async.cg.shared.global [%0], [%1], 16;" :: "r"(saddr), "l"(g) : "memory");
}
#define CP_COMMIT() asm volatile("cp.async.commit_group;" ::: "memory")

#define LDSM4(r0, r1, r2, r3, addr) \
    asm volatile("ldmatrix.sync.aligned.m8n8.x4.shared.b16 {%0,%1,%2,%3}, [%4];" \
        : "=r"(r0), "=r"(r1), "=r"(r2), "=r"(r3) : "r"(addr))

__device__ __forceinline__ void hmma(float* c,
    uint32_t a0, uint32_t a1, uint32_t a2, uint32_t a3,
    uint32_t b0, uint32_t b1)
{
    asm volatile(
        "mma.sync.aligned.m16n8k16.row.col.f32.bf16.bf16.f32 "
        "{%0,%1,%2,%3}, {%4,%5,%6,%7}, {%8,%9}, {%0,%1,%2,%3};"
        : "+f"(c[0]), "+f"(c[1]), "+f"(c[2]), "+f"(c[3])
        : "r"(a0), "r"(a1), "r"(a2), "r"(a3), "r"(b0), "r"(b1));
}

__device__ __forceinline__ void imma(int* c, const uint32_t* a, uint32_t b0, uint32_t b1)
{
    asm volatile(
        "mma.sync.aligned.m16n8k32.row.col.s32.s8.s8.s32 "
        "{%0,%1,%2,%3}, {%4,%5,%6,%7}, {%8,%9}, {%0,%1,%2,%3};"
        : "+r"(c[0]), "+r"(c[1]), "+r"(c[2]), "+r"(c[3])
        : "r"(a[0]), "r"(a[1]), "r"(a[2]), "r"(a[3]), "r"(b0), "r"(b1));
}

// ================================================================
// int8 NT GEMM: C = sA sB (A_int * B_int^T), 128x128 CTA tile
// 256 threads, 8 warps (2 x 4), warp tile 64x32. K % 64 == 0.
// Stage (32 KB, K-chunk 64): A1[128][64B] A2 B1 B2, row pitch 64B,
// 16B segs swizzled seg^((row>>1)&3). 3-stage cp.async pipeline.
// ================================================================
#define ISTAGE  32768
#define INST    3
#define ISMEM   (INST * ISTAGE)

__device__ __forceinline__ void stage_cp_i8(
    const int8_t* __restrict__ A1, const int8_t* __restrict__ A2, int lda,
    const int8_t* __restrict__ B1, const int8_t* __restrict__ B2, int ldb,
    int k0, uint32_t smb, int buf, int tid)
{
    uint32_t sb = smb + buf * ISTAGE;
#pragma unroll
    for (int i = 0; i < 2; ++i) {
        int si  = tid + i * 256;      // 0..511 16B chunks per array
        int row = si >> 2;            // 0..127
        int seg = si & 3;             // 16B segment within 64B row
        uint32_t soff = row * 64 + ((seg ^ ((row >> 1) & 3)) << 4);
        size_t goA = (size_t)row * lda + k0 + seg * 16;
        size_t goB = (size_t)row * ldb + k0 + seg * 16;
        cp16(sb +     0 + soff, A1 + goA);
        cp16(sb +  8192 + soff, A2 + goA);
        cp16(sb + 16384 + soff, B1 + goB);
        cp16(sb + 24576 + soff, B2 + goB);
    }
}

__device__ void igemm_tile(
    const int8_t* __restrict__ A1, const int8_t* __restrict__ A2,
    const float* __restrict__ sA, int sAs, int lda,
    const int8_t* __restrict__ B1, const int8_t* __restrict__ B2,
    const float* __restrict__ sB, int sBs, int ldb,
    float* __restrict__ C, int ldc, int K)
{
    extern __shared__ char smem[];
    const uint32_t smb = smem_u32(smem);
    const int tid  = threadIdx.x;
    const int lane = tid & 31;
    const int wid  = tid >> 5;
    const int wm   = wid >> 2;        // 0..1 (64-row block)
    const int wn   = wid & 3;         // 0..3 (32-col block)
    const int la   = lane & 7;
    const int grp  = lane >> 3;

    int acc1[4][4][4], acc2[4][4][4];
#pragma unroll
    for (int mi = 0; mi < 4; ++mi)
#pragma unroll
        for (int nb = 0; nb < 4; ++nb)
#pragma unroll
            for (int q = 0; q < 4; ++q) { acc1[mi][nb][q] = 0; acc2[mi][nb][q] = 0; }

    // ldmatrix per-lane address precompute (identical geometry to bf16 path)
    uint32_t offA[4], swA[4];
#pragma unroll
    for (int mi = 0; mi < 4; ++mi) {
        int r = wm * 64 + mi * 16 + la + (grp & 1) * 8;
        offA[mi] = r * 64;
        swA[mi]  = (r >> 1) & 3;
    }
    const int segselA = grp >> 1;
    uint32_t offB[2], swB[2];
#pragma unroll
    for (int p = 0; p < 2; ++p) {
        int r = wn * 32 + p * 16 + la + (grp >> 1) * 8;
        offB[p] = r * 64;
        swB[p]  = (r >> 1) & 3;
    }
    const int segselB = grp & 1;

    const int nK = K >> 6;
    stage_cp_i8(A1, A2, lda, B1, B2, ldb, 0, smb, 0, tid);
    CP_COMMIT();
    if (nK > 1) stage_cp_i8(A1, A2, lda, B1, B2, ldb, 64, smb, 1, tid);
    CP_COMMIT();

    int buf = 0;
    for (int ki = 0; ki < nK; ++ki) {
        __syncthreads();
        if (ki + 2 < nK)
            stage_cp_i8(A1, A2, lda, B1, B2, ldb, (ki + 2) << 6, smb, (ki + 2) % INST, tid);
        CP_COMMIT();
        asm volatile("cp.async.wait_group %0;" :: "n"(2) : "memory");
        __syncthreads();

        const uint32_t s1 = smb + buf * ISTAGE;
        const uint32_t s2 = s1 + 8192;
        const uint32_t t1 = s1 + 16384;
        const uint32_t t2 = s1 + 24576;

#pragma unroll
        for (int ks = 0; ks < 2; ++ks) {            // two k32 sub-iters per stage
            uint32_t a1f[4][4], a2f[4][4];
#pragma unroll
            for (int mi = 0; mi < 4; ++mi) {
                uint32_t aoff = offA[mi] + ((((uint32_t)(ks * 2 + segselA) ^ swA[mi])) << 4);
                LDSM4(a1f[mi][0], a1f[mi][1], a1f[mi][2], a1f[mi][3], s1 + aoff);
                LDSM4(a2f[mi][0], a2f[mi][1], a2f[mi][2], a2f[mi][3], s2 + aoff);
            }
#pragma unroll
            for (int p = 0; p < 2; ++p) {
                uint32_t boff = offB[p] + ((((uint32_t)(ks * 2 + segselB) ^ swB[p])) << 4);
                uint32_t b10, b11, b12, b13, b20, b21, b22, b23;
                LDSM4(b10, b11, b12, b13, t1 + boff);
                LDSM4(b20, b21, b22, b23, t2 + boff);
#pragma unroll
                for (int mi = 0; mi < 4; ++mi) {
                    imma(acc1[mi][2 * p],     a1f[mi], b10, b11);
                    imma(acc2[mi][2 * p],     a1f[mi], b20, b21);
                    imma(acc2[mi][2 * p],     a2f[mi], b10, b11);
                    imma(acc1[mi][2 * p + 1], a1f[mi], b12, b13);
                    imma(acc2[mi][2 * p + 1], a1f[mi], b22, b23);
                    imma(acc2[mi][2 * p + 1], a2f[mi], b12, b13);
                }
            }
        }
        buf = (buf + 1) % INST;
    }

    // epilogue: C = sA[m] * sB[n] * (16384*acc1 + 128*acc2)
    const int g  = lane >> 2;
    const int t4 = lane & 3;
#pragma unroll
    for (int mi = 0; mi < 4; ++mi) {
        int R0 = wm * 64 + mi * 16 + g;
        int R1 = R0 + 8;
        float sa0 = sA[(size_t)R0 * sAs];
        float sa1 = sA[(size_t)R1 * sAs];
#pragma unroll
        for (int nb = 0; nb < 4; ++nb) {
            int col = wn * 32 + nb * 8 + t4 * 2;
            float sb0 = sB[(size_t)col * sBs];
            float sb1 = sB[(size_t)(col + 1) * sBs];
            const int* q1 = acc1[mi][nb];
            const int* q2 = acc2[mi][nb];
            float v0 = fmaf(16384.f, (float)q1[0], 128.f * (float)q2[0]);
            float v1 = fmaf(16384.f, (float)q1[1], 128.f * (float)q2[1]);
            float v2 = fmaf(16384.f, (float)q1[2], 128.f * (float)q2[2]);
            float v3 = fmaf(16384.f, (float)q1[3], 128.f * (float)q2[3]);
            *(float2*)(C + (size_t)R0 * ldc + col) = make_float2(v0 * sa0 * sb0, v1 * sa0 * sb1);
            *(float2*)(C + (size_t)R1 * ldc + col) = make_float2(v2 * sa1 * sb0, v3 * sa1 * sb1);
        }
    }
}

__global__ void __launch_bounds__(256, 1)
k_igemm(const int8_t* A1, const int8_t* A2, const float* sA, int lda,
        const int8_t* B1, const int8_t* B2, const float* sB, int ldb,
        float* C, int ldc, int K)
{
    size_t m0 = (size_t)blockIdx.y * 128, n0 = (size_t)blockIdx.x * 128;
    igemm_tile(A1 + m0 * lda, A2 + m0 * lda, sA + m0, 1, lda,
               B1 + n0 * ldb, B2 + n0 * ldb, sB + n0, 1, ldb,
               C + m0 * ldc + n0, ldc, K);
}

__global__ void __launch_bounds__(256, 1)
k_attn_s_i8()
{
    int h = blockIdx.z, r = blockIdx.y, cx = blockIdx.x;
    int cbase = (r - 8 > 0) ? (r - 8) : 0;
    int ct = cbase + cx;
    if (ct > r) return;
    int kvh = h / GROUPS;
    size_t aoff = (size_t)r * 128 * (NHQ * DH) + (size_t)h * DH;
    size_t boff = (size_t)ct * 128 * (NKV * DH) + (size_t)kvh * DH;
    float* C = g_S + ((size_t)h * S_LEN + (size_t)r * 128) * BANDW + (size_t)cx * 128;
    igemm_tile(g_Qq1 + aoff, g_Qq2 + aoff, g_sQ + (size_t)r * 128 * NHQ + h, NHQ, NHQ * DH,
               g_Kq1 + boff, g_Kq2 + boff, g_sK + (size_t)ct * 128 * NKV + kvh, NKV, NKV * DH,
               C, BANDW, DH);
}

// ================================================================
// bf16 split GEMM (PV only) — round-6 kernel, EPI=0 fp32 out
// ================================================================
#define STAGE_BYTES 32768
#define NSTAGE      3
#define SMEM_BYTES  (NSTAGE * STAGE_BYTES)

__device__ __forceinline__ void stage_cp(
    const bf16* __restrict__ Ah, const bf16* __restrict__ Al, int lda,
    const bf16* __restrict__ Bh, const bf16* __restrict__ Bl, int ldb,
    int k0, uint32_t smb, int buf, int tid)
{
    uint32_t sb = smb + buf * STAGE_BYTES;
#pragma unroll
    for (int i = 0; i < 4; ++i) {
        int si  = tid + i * 128;
        int row = si >> 2;
        int seg = si & 3;
        uint32_t soff = row * 64 + ((seg ^ ((row >> 1) & 3)) << 4);
        size_t goA = (size_t)row * lda + k0 + seg * 8;
        size_t goB = (size_t)row * ldb + k0 + seg * 8;
        cp16(sb +     0 + soff, Ah + goA);
        cp16(sb +  8192 + soff, Al + goA);
        cp16(sb + 16384 + soff, Bh + goB);
        cp16(sb + 24576 + soff, Bl + goB);
    }
}

__device__ void gemm_hmma_tile(
    const bf16* __restrict__ Ah, const bf16* __restrict__ Al, int lda,
    const bf16* __restrict__ Bh, const bf16* __restrict__ Bl, int ldb,
    float* __restrict__ C, int ldc, int K)
{
    extern __shared__ char smem[];
    const uint32_t smb = smem_u32(smem);
    const int tid  = threadIdx.x;
    const int lane = tid & 31;
    const int wid  = tid >> 5;
    const int wm   = wid >> 1;
    const int wn   = wid & 1;
    const int la   = lane & 7;
    const int grp  = lane >> 3;

    float acc[4][8][4];
#pragma unroll
    for (int mi = 0; mi < 4; ++mi)
#pragma unroll
        for (int ni = 0; ni < 8; ++ni)
#pragma unroll
            for (int q = 0; q < 4; ++q) acc[mi][ni][q] = 0.0f;

    uint32_t offA[4], swA[4];
#pragma unroll
    for (int mi = 0; mi < 4; ++mi) {
        int r = wm * 64 + mi * 16 + la + (grp & 1) * 8;
        offA[mi] = r * 64;
        swA[mi]  = (r >> 1) & 3;
    }
    const int segselA = grp >> 1;
    uint32_t offB[4], swB[4];
#pragma unroll
    for (int p = 0; p < 4; ++p) {
        int r = wn * 64 + p * 16 + la + (grp >> 1) * 8;
        offB[p] = r * 64;
        swB[p]  = (r >> 1) & 3;
    }
    const int segselB = grp & 1;

    const int nK = K >> 5;
    stage_cp(Ah, Al, lda, Bh, Bl, ldb, 0, smb, 0, tid);
    CP_COMMIT();
    if (nK > 1) stage_cp(Ah, Al, lda, Bh, Bl, ldb, 32, smb, 1, tid);
    CP_COMMIT();

    int buf = 0;
    for (int ki = 0; ki < nK; ++ki) {
        __syncthreads();
        if (ki + 2 < nK)
            stage_cp(Ah, Al, lda, Bh, Bl, ldb, (ki + 2) << 5, smb, (ki + 2) % NSTAGE, tid);
        CP_COMMIT();
        asm volatile("cp.async.wait_group %0;" :: "n"(2) : "memory");
        __syncthreads();

        const uint32_t sA  = smb + buf * STAGE_BYTES;
        const uint32_t sAl = sA + 8192;
        const uint32_t sB  = sA + 16384;
        const uint32_t sBl = sA + 24576;

#pragma unroll
        for (int ks = 0; ks < 2; ++ks) {
            uint32_t ah[4][4], al[4][4];
#pragma unroll
            for (int mi = 0; mi < 4; ++mi) {
                uint32_t aoff = offA[mi] + ((((uint32_t)(ks * 2 + segselA) ^ swA[mi])) << 4);
                LDSM4(ah[mi][0], ah[mi][1], ah[mi][2], ah[mi][3], sA + aoff);
                LDSM4(al[mi][0], al[mi][1], al[mi][2], al[mi][3], sAl + aoff);
            }
#pragma unroll
            for (int p = 0; p < 4; ++p) {
                uint32_t boff = offB[p] + ((((uint32_t)(ks * 2 + segselB) ^ swB[p])) << 4);
                uint32_t bh0, bh1, bh2, bh3, bl0, bl1, bl2, bl3;
                LDSM4(bh0, bh1, bh2, bh3, sB  + boff);
                LDSM4(bl0, bl1, bl2, bl3, sBl + boff);
#pragma unroll
                for (int mi = 0; mi < 4; ++mi) {
                    float* c0 = acc[mi][2 * p];
                    float* c1 = acc[mi][2 * p + 1];
                    hmma(c0, ah[mi][0], ah[mi][1], ah[mi][2], ah[mi][3], bh0, bh1);
                    hmma(c0, ah[mi][0], ah[mi][1], ah[mi][2], ah[mi][3], bl0, bl1);
                    hmma(c0, al[mi][0], al[mi][1], al[mi][2], al[mi][3], bh0, bh1);
                    hmma(c1, ah[mi][0], ah[mi][1], ah[mi][2], ah[mi][3], bh2, bh3);
                    hmma(c1, ah[mi][0], ah[mi][1], ah[mi][2], ah[mi][3], bl2, bl3);
                    hmma(c1, al[mi][0], al[mi][1], al[mi][2], al[mi][3], bh2, bh3);
                }
            }
        }
        buf = (buf + 1) % NSTAGE;
    }

    const int g  = lane >> 2;
    const int t4 = lane & 3;
#pragma unroll
    for (int mi = 0; mi < 4; ++mi) {
        int R0 = wm * 64 + mi * 16 + g;
        int R1 = R0 + 8;
#pragma unroll
        for (int ni = 0; ni < 8; ++ni) {
            int col = wn * 64 + ni * 8 + t4 * 2;
            float* a = acc[mi][ni];
            *(float2*)(C + (size_t)R0 * ldc + col) = make_float2(a[0], a[1]);
            *(float2*)(C + (size_t)R1 * ldc + col) = make_float2(a[2], a[3]);
        }
    }
}

__global__ void __launch_bounds__(128, 2)
k_attn_pv()
{
    int h = blockIdx.z, r = blockIdx.y, nx = blockIdx.x;
    int c0 = ((r - 8 > 0) ? (r - 8) : 0) * 128;
    size_t aoff = ((size_t)h * S_LEN + (size_t)r * 128) * BANDW;
    size_t boff = ((size_t)(h / GROUPS) * DH + (size_t)nx * 128) * S_LEN + (size_t)c0;
    float* C = g_AO + (size_t)r * 128 * (NHQ * DH) + (size_t)h * DH + (size_t)nx * 128;
    gemm_hmma_tile(g_PH + aoff, g_PL + aoff, BANDW,
                   g_VtH + boff, g_VtL + boff, S_LEN,
                   C, NHQ * DH, BANDW);
}

// ================================================================
// quantization / elementwise kernels
// ================================================================

// per-row 2-slice int8 quantization; one row per block. K <= 4096.
__global__ void __launch_bounds__(256)
k_quant(const float* __restrict__ x, int K,
        int8_t* __restrict__ q1, int8_t* __restrict__ q2, float* __restrict__ sc)
{
    int row = blockIdx.x;
    const float* xr = x + (size_t)row * K;
    int lane = threadIdx.x & 31, wid = threadIdx.x >> 5;

    float v[16];
    int n = 0;
    float m = 0.0f;
    for (int j = threadIdx.x; j < K; j += 256) {
        float a = xr[j];
        v[n++] = a;
        m = fmaxf(m, fabsf(a));
    }
#pragma unroll
    for (int o = 16; o > 0; o >>= 1) m = fmaxf(m, __shfl_xor_sync(0xFFFFFFFFu, m, o));
    __shared__ float red[8];
    if (lane == 0) red[wid] = m;
    __syncthreads();
    m = red[0];
#pragma unroll
    for (int w = 1; w < 8; ++w) m = fmaxf(m, red[w]);

    float s = fmaxf(m, 1e-30f) * (1.0f / 16256.0f);
    float inv = 1.0f / s;
    if (threadIdx.x == 0) sc[row] = s;

    n = 0;
    for (int j = threadIdx.x; j < K; j += 256) {
        float t = v[n++] * inv;                       // |t| <= 16256
        float i1 = rintf(t * (1.0f / 128.0f));
        i1 = fminf(127.0f, fmaxf(-127.0f, i1));
        float i2 = rintf(t - 128.0f * i1);
        i2 = fminf(127.0f, fmaxf(-127.0f, i2));
        q1[(size_t)row * K + j] = (int8_t)(int)i1;
        q2[(size_t)row * K + j] = (int8_t)(int)i2;
    }
}

// RoPE + per-(s,head)-row quantization of Q and K. One warp per row of 256.
__global__ void __launch_bounds__(256)
k_rope_quant(const float* __restrict__ cosb, const float* __restrict__ sinb)
{
    int wrow = blockIdx.x * 8 + (threadIdx.x >> 5);   // 0 .. S*(NHQ+NKV)-1
    int lane = threadIdx.x & 31;
    int slot = wrow % (NHQ + NKV);
    int s    = wrow / (NHQ + NKV);

    const float* src;
    int8_t *q1, *q2;
    size_t base;
    if (slot < NHQ) {
        base = (size_t)s * (NHQ * DH) + (size_t)slot * DH;
        src = g_Q; q1 = g_Qq1; q2 = g_Qq2;
    } else {
        base = (size_t)s * (NKV * DH) + (size_t)(slot - NHQ) * DH;
        src = g_K; q1 = g_Kq1; q2 = g_Kq2;
    }

    float y0[4], y1[4];
    float m = 0.0f;
#pragma unroll
    for (int j = 0; j < 4; ++j) {
        int d = lane + 32 * j;
        float c0 = cosb[s * DH + d],       s0 = sinb[s * DH + d];
        float c1 = cosb[s * DH + d + 128], s1 = sinb[s * DH + d + 128];
        float x0 = src[base + d];
        float x1 = src[base + d + 128];
        y0[j] = x0 * c0 - x1 * s0;
        y1[j] = x1 * c1 + x0 * s1;
        m = fmaxf(m, fmaxf(fabsf(y0[j]), fabsf(y1[j])));
    }
#pragma unroll
    for (int o = 16; o > 0; o >>= 1) m = fmaxf(m, __shfl_xor_sync(0xFFFFFFFFu, m, o));

    float sv = fmaxf(m, 1e-30f) * (1.0f / 16256.0f);
    float inv = 1.0f / sv;
    if (lane == 0) {
        if (slot < NHQ) g_sQ[s * NHQ + slot] = sv;
        else            g_sK[s * NKV + (slot - NHQ)] = sv;
    }
#pragma unroll
    for (int j = 0; j < 4; ++j) {
        int d = lane + 32 * j;
        float t = y0[j] * inv;
        float i1 = fminf(127.f, fmaxf(-127.f, rintf(t * (1.0f / 128.0f))));
        float i2 = fminf(127.f, fmaxf(-127.f, rintf(t - 128.0f * i1)));
        q1[base + d] = (int8_t)(int)i1;
        q2[base + d] = (int8_t)(int)i2;
        t = y1[j] * inv;
        i1 = fminf(127.f, fmaxf(-127.f, rintf(t * (1.0f / 128.0f))));
        i2 = fminf(127.f, fmaxf(-127.f, rintf(t - 128.0f * i1)));
        q1[base + d + 128] = (int8_t)(int)i1;
        q2[base + d + 128] = (int8_t)(int)i2;
    }
}

// V transpose: Vt[o][s] = V[s][o], split bf16 (PV path)
__global__ void __launch_bounds__(256)
k_vtrans()
{
    __shared__ float t[32][33];
    int bs = blockIdx.x * 32, bo = blockIdx.y * 32;
    int tx = threadIdx.x, ty = threadIdx.y;
#pragma unroll
    for (int j = 0; j < 32; j += 8)
        t[ty + j][tx] = g_V[(size_t)(bs + ty + j) * (NKV * DH) + bo + tx];
    __syncthreads();
#pragma unroll
    for (int j = 0; j < 32; j += 8) {
        float v = t[tx][ty + j];
        size_t o = (size_t)(bo + ty + j) * S_LEN + bs + tx;
        bf16 h = __float2bfloat16(v);
        g_VtH[o] = h;
        g_VtL[o] = __float2bfloat16(v - __bfloat162float(h));
    }
}

// band softmax: softcap tanh + mask + normalize -> split-bf16 P
__global__ void __launch_bounds__(256)
k_softmax()
{
    int row  = blockIdx.x * 8 + (threadIdx.x >> 5);
    int lane = threadIdx.x & 31;
    int h = row >> 11;
    int q = row & 2047;

    size_t base = ((size_t)h * S_LEN + q) * BANDW;
    const float* p = g_S + base;
    int r  = q >> 7;
    int c0 = ((r - 8 > 0) ? (r - 8) : 0) * 128;
    int kmin = (q - (WINDOW - 1) > 0) ? (q - (WINDOW - 1)) : 0;

    float v[36];
    float m = -1e30f;
#pragma unroll
    for (int i = 0; i < 36; ++i) {
        int j = lane + 32 * i;
        int k = c0 + j;
        float tt;
        if (k >= kmin && k <= q) {
            float x = p[j] * (SCALING / SOFTCAP);
            tt = SOFTCAP * tanhf(x);
        } else {
            tt = -1e30f;
        }
        v[i] = tt;
        m = fmaxf(m, tt);
    }
#pragma unroll
    for (int o = 16; o > 0; o >>= 1)
        m = fmaxf(m, __shfl_xor_sync(0xFFFFFFFFu, m, o));

    float l = 0.0f;
#pragma unroll
    for (int i = 0; i < 36; ++i) {
        v[i] = expf(v[i] - m);
        l += v[i];
    }
#pragma unroll
    for (int o = 16; o > 0; o >>= 1)
        l += __shfl_xor_sync(0xFFFFFFFFu, l, o);

    float inv = 1.0f / l;
#pragma unroll
    for (int i = 0; i < 36; ++i) {
        float pv = v[i] * inv;
        bf16 hh = __float2bfloat16(pv);
        g_PH[base + lane + 32 * i] = hh;
        g_PL[base + lane + 32 * i] = __float2bfloat16(pv - __bfloat162float(hh));
    }
}

// ---------------- launch ----------------
extern "C" void kernel_launch(void* const* d_in, const int* in_sizes, int n_in,
                              void* d_out, int out_size)
{
    const float* hs   = (const float*)d_in[0];
    const float* cosb = (const float*)d_in[1];
    const float* sinb = (const float*)d_in[2];
    const float* wq   = (const float*)d_in[3];
    const float* wk   = (const float*)d_in[4];
    const float* wv   = (const float*)d_in[5];
    const float* wo   = (const float*)d_in[6];
    float* out = (float*)d_out;

    void *pQ, *pK, *pV, *pAO;
    void *phq1, *phq2, *pwqq1, *pwqq2, *pwkq1, *pwkq2, *pwvq1, *pwvq2, *pwoq1, *pwoq2;
    void *pAOq1, *pAOq2;
    void *ps_hs, *ps_wq, *ps_wk, *ps_wv, *ps_wo, *ps_AO;
    cudaGetSymbolAddress(&pQ, g_Q);   cudaGetSymbolAddress(&pK, g_K);
    cudaGetSymbolAddress(&pV, g_V);   cudaGetSymbolAddress(&pAO, g_AO);
    cudaGetSymbolAddress(&phq1, g_hq1);   cudaGetSymbolAddress(&phq2, g_hq2);
    cudaGetSymbolAddress(&pwqq1, g_wqq1); cudaGetSymbolAddress(&pwqq2, g_wqq2);
    cudaGetSymbolAddress(&pwkq1, g_wkq1); cudaGetSymbolAddress(&pwkq2, g_wkq2);
    cudaGetSymbolAddress(&pwvq1, g_wvq1); cudaGetSymbolAddress(&pwvq2, g_wvq2);
    cudaGetSymbolAddress(&pwoq1, g_woq1); cudaGetSymbolAddress(&pwoq2, g_woq2);
    cudaGetSymbolAddress(&pAOq1, g_AOq1); cudaGetSymbolAddress(&pAOq2, g_AOq2);
    cudaGetSymbolAddress(&ps_hs, g_s_hs); cudaGetSymbolAddress(&ps_wq, g_s_wq);
    cudaGetSymbolAddress(&ps_wk, g_s_wk); cudaGetSymbolAddress(&ps_wv, g_s_wv);
    cudaGetSymbolAddress(&ps_wo, g_s_wo); cudaGetSymbolAddress(&ps_AO, g_s_AO);

    cudaFuncSetAttribute(k_igemm,     cudaFuncAttributeMaxDynamicSharedMemorySize, ISMEM);
    cudaFuncSetAttribute(k_attn_s_i8, cudaFuncAttributeMaxDynamicSharedMemorySize, ISMEM);
    cudaFuncSetAttribute(k_attn_pv,   cudaFuncAttributeMaxDynamicSharedMemorySize, SMEM_BYTES);

    // quantize inputs (row-wise, 2 int8 slices)
    k_quant<<<S_LEN,    256>>>(hs, HID, (int8_t*)phq1,  (int8_t*)phq2,  (float*)ps_hs);
    k_quant<<<NHQ * DH, 256>>>(wq, HID, (int8_t*)pwqq1, (int8_t*)pwqq2, (float*)ps_wq);
    k_quant<<<NKV * DH, 256>>>(wk, HID, (int8_t*)pwkq1, (int8_t*)pwkq2, (float*)ps_wk);
    k_quant<<<NKV * DH, 256>>>(wv, HID, (int8_t*)pwvq1, (int8_t*)pwvq2, (float*)ps_wv);
    k_quant<<<HID,      256>>>(wo, NHQ * DH, (int8_t*)pwoq1, (int8_t*)pwoq2, (float*)ps_wo);

    // QKV projections (int8 NT)
    k_igemm<<<dim3(NHQ * DH / 128, S_LEN / 128), 256, ISMEM>>>(
        (int8_t*)phq1, (int8_t*)phq2, (float*)ps_hs, HID,
        (int8_t*)pwqq1, (int8_t*)pwqq2, (float*)ps_wq, HID,
        (float*)pQ, NHQ * DH, HID);
    k_igemm<<<dim3(NKV * DH / 128, S_LEN / 128), 256, ISMEM>>>(
        (int8_t*)phq1, (int8_t*)phq2, (float*)ps_hs, HID,
        (int8_t*)pwkq1, (int8_t*)pwkq2, (float*)ps_wk, HID,
        (float*)pK, NKV * DH, HID);
    k_igemm<<<dim3(NKV * DH / 128, S_LEN / 128), 256, ISMEM>>>(
        (int8_t*)phq1, (int8_t*)phq2, (float*)ps_hs, HID,
        (int8_t*)pwvq1, (int8_t*)pwvq2, (float*)ps_wv, HID,
        (float*)pV, NKV * DH, HID);

    // RoPE + quantize Q/K; V transpose (bf16 split)
    k_rope_quant<<<(S_LEN * (NHQ + NKV)) / 8, 256>>>(cosb, sinb);
    k_vtrans<<<dim3(S_LEN / 32, (NKV * DH) / 32), dim3(32, 8)>>>();

    // banded scores (int8 IMMA)
    k_attn_s_i8<<<dim3(9, S_LEN / 128, NHQ), 256, ISMEM>>>();

    // softcap + mask + softmax -> split-bf16 P
    k_softmax<<<(NHQ * S_LEN) / 8, 256>>>();

    // PV (bf16 HMMA) -> fp32 AO
    k_attn_pv<<<dim3(2, S_LEN / 128, NHQ), 128, SMEM_BYTES>>>();

    // quantize AO rows, output projection (int8)
    k_quant<<<S_LEN, 256>>>((const float*)pAO, NHQ * DH, (int8_t*)pAOq1, (int8_t*)pAOq2, (float*)ps_AO);
    k_igemm<<<dim3(HID / 128, S_LEN / 128), 256, ISMEM>>>(
        (int8_t*)pAOq1, (int8_t*)pAOq2, (float*)ps_AO, NHQ * DH,
        (int8_t*)pwoq1, (int8_t*)pwoq2, (float*)ps_wo, NHQ * DH,
        out, HID, NHQ * DH);
}

// round 10
// speedup vs baseline: 2.1911x; 2.1911x over previous
#include <cuda_runtime.h>
#include <cuda_bf16.h>
#include <math.h>
#include <stdint.h>

// ---------------- problem constants ----------------
#define S_LEN   2048
#define HID     3584
#define NHQ     16
#define NKV     8
#define DH      256
#define GROUPS  2
#define WINDOW  1024
#define BANDW   1152
#define SOFTCAP 50.0f
#define SCALING 0.0625f

typedef __nv_bfloat16 bf16;

// ---------------- device scratch ----------------
__device__ float g_Q [(size_t)S_LEN * NHQ * DH];
__device__ float g_K [(size_t)S_LEN * NKV * DH];
__device__ float g_V [(size_t)S_LEN * NKV * DH];
__device__ float g_S [(size_t)NHQ * S_LEN * BANDW];

__device__ bf16 g_hsH[(size_t)S_LEN * HID],      g_hsL[(size_t)S_LEN * HID];
__device__ bf16 g_wqH[(size_t)NHQ * DH * HID],   g_wqL[(size_t)NHQ * DH * HID];
__device__ bf16 g_wkH[(size_t)NKV * DH * HID],   g_wkL[(size_t)NKV * DH * HID];
__device__ bf16 g_wvH[(size_t)NKV * DH * HID],   g_wvL[(size_t)NKV * DH * HID];
__device__ bf16 g_woH[(size_t)HID * NHQ * DH],   g_woL[(size_t)HID * NHQ * DH];
__device__ bf16 g_QH [(size_t)S_LEN * NHQ * DH], g_QL [(size_t)S_LEN * NHQ * DH];
__device__ bf16 g_KH [(size_t)S_LEN * NKV * DH], g_KL [(size_t)S_LEN * NKV * DH];
__device__ bf16 g_VtH[(size_t)NKV * DH * S_LEN], g_VtL[(size_t)NKV * DH * S_LEN];
__device__ bf16 g_PH [(size_t)NHQ * S_LEN * BANDW], g_PL[(size_t)NHQ * S_LEN * BANDW];
__device__ bf16 g_AOH[(size_t)S_LEN * NHQ * DH], g_AOL[(size_t)S_LEN * NHQ * DH];

// ---------------- helpers ----------------
__device__ __forceinline__ uint32_t smem_u32(const void* p) {
    uint32_t a;
    asm("{ .reg .u64 t; cvta.to.shared.u64 t, %1; cvt.u32.u64 %0, t; }" : "=r"(a) : "l"(p));
    return a;
}
__device__ __forceinline__ void cp16(uint32_t saddr, const void* g) {
    asm volatile("cp.async.cg.shared.global [%0], [%1], 16;" :: "r"(saddr), "l"(g) : "memory");
}
#define CP_COMMIT() asm volatile("cp.async.commit_group;" ::: "memory")

#define LDSM4(r0, r1, r2, r3, addr) \
    asm volatile("ldmatrix.sync.aligned.m8n8.x4.shared.b16 {%0,%1,%2,%3}, [%4];" \
        : "=r"(r0), "=r"(r1), "=r"(r2), "=r"(r3) : "r"(addr))

__device__ __forceinline__ void hmma(float* c,
    uint32_t a0, uint32_t a1, uint32_t a2, uint32_t a3,
    uint32_t b0, uint32_t b1)
{
    asm volatile(
        "mma.sync.aligned.m16n8k16.row.col.f32.bf16.bf16.f32 "
        "{%0,%1,%2,%3}, {%4,%5,%6,%7}, {%8,%9}, {%0,%1,%2,%3};"
        : "+f"(c[0]), "+f"(c[1]), "+f"(c[2]), "+f"(c[3])
        : "r"(a0), "r"(a1), "r"(a2), "r"(a3), "r"(b0), "r"(b1));
}

// ================================================================
// 128(M) x 256(N) NT GEMM: C = A*B^T, split-bf16 x3, fp32 accum
// 256 threads, 8 warps (2 M x 4 N), warp tile 64x64. K % 32 == 0.
// Stage (48 KB): Ah[128][64B] Al | Bh[256][64B] Bl, row pitch 64 B,
// 16B segs swizzled seg ^ ((row>>1)&3). 3-stage cp.async pipeline.
// EPI=0: fp32 C.  EPI=1: split-bf16 (Ch, Cl).
// ================================================================
#define STG256  49152
#define NST256  3
#define SMEM256 (NST256 * STG256)

__device__ __forceinline__ void stage_cp256(
    const bf16* __restrict__ Ah, const bf16* __restrict__ Al, int lda,
    const bf16* __restrict__ Bh, const bf16* __restrict__ Bl, int ldb,
    int k0, uint32_t smb, int buf, int tid)
{
    uint32_t sb = smb + buf * STG256;
#pragma unroll
    for (int i = 0; i < 2; ++i) {                 // A: 128 rows
        int si  = tid + i * 256;
        int row = si >> 2;
        int seg = si & 3;
        uint32_t soff = row * 64 + ((seg ^ ((row >> 1) & 3)) << 4);
        size_t go = (size_t)row * lda + k0 + seg * 8;
        cp16(sb +    0 + soff, Ah + go);
        cp16(sb + 8192 + soff, Al + go);
    }
#pragma unroll
    for (int i = 0; i < 4; ++i) {                 // B: 256 rows
        int si  = tid + i * 256;
        int row = si >> 2;
        int seg = si & 3;
        uint32_t soff = row * 64 + ((seg ^ ((row >> 1) & 3)) << 4);
        size_t go = (size_t)row * ldb + k0 + seg * 8;
        cp16(sb + 16384 + soff, Bh + go);
        cp16(sb + 32768 + soff, Bl + go);
    }
}

template <int EPI>
__device__ void gemm_n256(
    const bf16* __restrict__ Ah, const bf16* __restrict__ Al, int lda,
    const bf16* __restrict__ Bh, const bf16* __restrict__ Bl, int ldb,
    float* __restrict__ C, bf16* __restrict__ Ch, bf16* __restrict__ Cl,
    int ldc, int K)
{
    extern __shared__ char smem[];
    const uint32_t smb = smem_u32(smem);
    const int tid  = threadIdx.x;
    const int lane = tid & 31;
    const int wid  = tid >> 5;
    const int wm   = wid >> 2;        // 0..1  (M block of 64)
    const int wn   = wid & 3;         // 0..3  (N block of 64)
    const int la   = lane & 7;
    const int grp  = lane >> 3;

    float acc[4][8][4];
#pragma unroll
    for (int mi = 0; mi < 4; ++mi)
#pragma unroll
        for (int ni = 0; ni < 8; ++ni)
#pragma unroll
            for (int q = 0; q < 4; ++q) acc[mi][ni][q] = 0.0f;

    uint32_t offA[4], swA[4];
#pragma unroll
    for (int mi = 0; mi < 4; ++mi) {
        int r = wm * 64 + mi * 16 + la + (grp & 1) * 8;
        offA[mi] = r * 64;
        swA[mi]  = (r >> 1) & 3;
    }
    const int segselA = grp >> 1;
    uint32_t offB[4], swB[4];
#pragma unroll
    for (int p = 0; p < 4; ++p) {
        int r = wn * 64 + p * 16 + la + (grp >> 1) * 8;
        offB[p] = r * 64;
        swB[p]  = (r >> 1) & 3;
    }
    const int segselB = grp & 1;

    const int nK = K >> 5;
    stage_cp256(Ah, Al, lda, Bh, Bl, ldb, 0, smb, 0, tid);
    CP_COMMIT();
    if (nK > 1) stage_cp256(Ah, Al, lda, Bh, Bl, ldb, 32, smb, 1, tid);
    CP_COMMIT();

    int buf = 0;
    for (int ki = 0; ki < nK; ++ki) {
        __syncthreads();
        if (ki + 2 < nK)
            stage_cp256(Ah, Al, lda, Bh, Bl, ldb, (ki + 2) << 5, smb, (ki + 2) % NST256, tid);
        CP_COMMIT();
        asm volatile("cp.async.wait_group %0;" :: "n"(2) : "memory");
        __syncthreads();

        const uint32_t sA  = smb + buf * STG256;
        const uint32_t sAl = sA + 8192;
        const uint32_t sB  = sA + 16384;
        const uint32_t sBl = sA + 32768;

#pragma unroll
        for (int ks = 0; ks < 2; ++ks) {
            uint32_t ah[4][4], al[4][4];
#pragma unroll
            for (int mi = 0; mi < 4; ++mi) {
                uint32_t aoff = offA[mi] + ((((uint32_t)(ks * 2 + segselA) ^ swA[mi])) << 4);
                LDSM4(ah[mi][0], ah[mi][1], ah[mi][2], ah[mi][3], sA + aoff);
                LDSM4(al[mi][0], al[mi][1], al[mi][2], al[mi][3], sAl + aoff);
            }
#pragma unroll
            for (int p = 0; p < 4; ++p) {
                uint32_t boff = offB[p] + ((((uint32_t)(ks * 2 + segselB) ^ swB[p])) << 4);
                uint32_t bh0, bh1, bh2, bh3, bl0, bl1, bl2, bl3;
                LDSM4(bh0, bh1, bh2, bh3, sB  + boff);
                LDSM4(bl0, bl1, bl2, bl3, sBl + boff);
#pragma unroll
                for (int mi = 0; mi < 4; ++mi) {
                    float* c0 = acc[mi][2 * p];
                    float* c1 = acc[mi][2 * p + 1];
                    hmma(c0, ah[mi][0], ah[mi][1], ah[mi][2], ah[mi][3], bh0, bh1);
                    hmma(c0, ah[mi][0], ah[mi][1], ah[mi][2], ah[mi][3], bl0, bl1);
                    hmma(c0, al[mi][0], al[mi][1], al[mi][2], al[mi][3], bh0, bh1);
                    hmma(c1, ah[mi][0], ah[mi][1], ah[mi][2], ah[mi][3], bh2, bh3);
                    hmma(c1, ah[mi][0], ah[mi][1], ah[mi][2], ah[mi][3], bl2, bl3);
                    hmma(c1, al[mi][0], al[mi][1], al[mi][2], al[mi][3], bh2, bh3);
                }
            }
        }
        buf = (buf + 1) % NST256;
    }

    const int g  = lane >> 2;
    const int t4 = lane & 3;
#pragma unroll
    for (int mi = 0; mi < 4; ++mi) {
        int R0 = wm * 64 + mi * 16 + g;
        int R1 = R0 + 8;
#pragma unroll
        for (int ni = 0; ni < 8; ++ni) {
            int col = wn * 64 + ni * 8 + t4 * 2;
            float* a = acc[mi][ni];
            if (EPI == 0) {
                *(float2*)(C + (size_t)R0 * ldc + col) = make_float2(a[0], a[1]);
                *(float2*)(C + (size_t)R1 * ldc + col) = make_float2(a[2], a[3]);
            } else {
                __nv_bfloat162 h0, h1, l0, l1;
                h0.x = __float2bfloat16(a[0]); h0.y = __float2bfloat16(a[1]);
                h1.x = __float2bfloat16(a[2]); h1.y = __float2bfloat16(a[3]);
                l0.x = __float2bfloat16(a[0] - __bfloat162float(h0.x));
                l0.y = __float2bfloat16(a[1] - __bfloat162float(h0.y));
                l1.x = __float2bfloat16(a[2] - __bfloat162float(h1.x));
                l1.y = __float2bfloat16(a[3] - __bfloat162float(h1.y));
                *(__nv_bfloat162*)(Ch + (size_t)R0 * ldc + col) = h0;
                *(__nv_bfloat162*)(Ch + (size_t)R1 * ldc + col) = h1;
                *(__nv_bfloat162*)(Cl + (size_t)R0 * ldc + col) = l0;
                *(__nv_bfloat162*)(Cl + (size_t)R1 * ldc + col) = l1;
            }
        }
    }
}

__global__ void __launch_bounds__(256, 1)
k_gemm_nt256(const bf16* Ah, const bf16* Al, int lda,
             const bf16* Bh, const bf16* Bl, int ldb,
             float* C, int ldc, int K)
{
    size_t m0 = (size_t)blockIdx.y * 128, n0 = (size_t)blockIdx.x * 256;
    gemm_n256<0>(Ah + m0 * lda, Al + m0 * lda, lda,
                 Bh + n0 * ldb, Bl + n0 * ldb, ldb,
                 C + m0 * ldc + n0, nullptr, nullptr, ldc, K);
}

// PV: per (r, h) one CTA covers the FULL head dim (N = 256)
__global__ void __launch_bounds__(256, 1)
k_attn_pv256()
{
    int r = blockIdx.x, h = blockIdx.y;
    int c0 = ((r - 8 > 0) ? (r - 8) : 0) * 128;
    size_t aoff = ((size_t)h * S_LEN + (size_t)r * 128) * BANDW;
    size_t boff = (size_t)(h / GROUPS) * DH * S_LEN + (size_t)c0;
    size_t coff = (size_t)r * 128 * (NHQ * DH) + (size_t)h * DH;
    gemm_n256<1>(g_PH + aoff, g_PL + aoff, BANDW,
                 g_VtH + boff, g_VtL + boff, S_LEN,
                 nullptr, g_AOH + coff, g_AOL + coff, NHQ * DH, BANDW);
}

// ================================================================
// 128x128 attention-S GEMM (round-7 kernel, fp32 out)
// ================================================================
#define STAGE_BYTES 32768
#define NSTAGE      3
#define SMEM_BYTES  (NSTAGE * STAGE_BYTES)

__device__ __forceinline__ void stage_cp(
    const bf16* __restrict__ Ah, const bf16* __restrict__ Al, int lda,
    const bf16* __restrict__ Bh, const bf16* __restrict__ Bl, int ldb,
    int k0, uint32_t smb, int buf, int tid)
{
    uint32_t sb = smb + buf * STAGE_BYTES;
#pragma unroll
    for (int i = 0; i < 4; ++i) {
        int si  = tid + i * 128;
        int row = si >> 2;
        int seg = si & 3;
        uint32_t soff = row * 64 + ((seg ^ ((row >> 1) & 3)) << 4);
        size_t goA = (size_t)row * lda + k0 + seg * 8;
        size_t goB = (size_t)row * ldb + k0 + seg * 8;
        cp16(sb +     0 + soff, Ah + goA);
        cp16(sb +  8192 + soff, Al + goA);
        cp16(sb + 16384 + soff, Bh + goB);
        cp16(sb + 24576 + soff, Bl + goB);
    }
}

__device__ void gemm_hmma_tile(
    const bf16* __restrict__ Ah, const bf16* __restrict__ Al, int lda,
    const bf16* __restrict__ Bh, const bf16* __restrict__ Bl, int ldb,
    float* __restrict__ C, int ldc, int K)
{
    extern __shared__ char smem[];
    const uint32_t smb = smem_u32(smem);
    const int tid  = threadIdx.x;
    const int lane = tid & 31;
    const int wid  = tid >> 5;
    const int wm   = wid >> 1;
    const int wn   = wid & 1;
    const int la   = lane & 7;
    const int grp  = lane >> 3;

    float acc[4][8][4];
#pragma unroll
    for (int mi = 0; mi < 4; ++mi)
#pragma unroll
        for (int ni = 0; ni < 8; ++ni)
#pragma unroll
            for (int q = 0; q < 4; ++q) acc[mi][ni][q] = 0.0f;

    uint32_t offA[4], swA[4];
#pragma unroll
    for (int mi = 0; mi < 4; ++mi) {
        int r = wm * 64 + mi * 16 + la + (grp & 1) * 8;
        offA[mi] = r * 64;
        swA[mi]  = (r >> 1) & 3;
    }
    const int segselA = grp >> 1;
    uint32_t offB[4], swB[4];
#pragma unroll
    for (int p = 0; p < 4; ++p) {
        int r = wn * 64 + p * 16 + la + (grp >> 1) * 8;
        offB[p] = r * 64;
        swB[p]  = (r >> 1) & 3;
    }
    const int segselB = grp & 1;

    const int nK = K >> 5;
    stage_cp(Ah, Al, lda, Bh, Bl, ldb, 0, smb, 0, tid);
    CP_COMMIT();
    if (nK > 1) stage_cp(Ah, Al, lda, Bh, Bl, ldb, 32, smb, 1, tid);
    CP_COMMIT();

    int buf = 0;
    for (int ki = 0; ki < nK; ++ki) {
        __syncthreads();
        if (ki + 2 < nK)
            stage_cp(Ah, Al, lda, Bh, Bl, ldb, (ki + 2) << 5, smb, (ki + 2) % NSTAGE, tid);
        CP_COMMIT();
        asm volatile("cp.async.wait_group %0;" :: "n"(2) : "memory");
        __syncthreads();

        const uint32_t sA  = smb + buf * STAGE_BYTES;
        const uint32_t sAl = sA + 8192;
        const uint32_t sB  = sA + 16384;
        const uint32_t sBl = sA + 24576;

#pragma unroll
        for (int ks = 0; ks < 2; ++ks) {
            uint32_t ah[4][4], al[4][4];
#pragma unroll
            for (int mi = 0; mi < 4; ++mi) {
                uint32_t aoff = offA[mi] + ((((uint32_t)(ks * 2 + segselA) ^ swA[mi])) << 4);
                LDSM4(ah[mi][0], ah[mi][1], ah[mi][2], ah[mi][3], sA + aoff);
                LDSM4(al[mi][0], al[mi][1], al[mi][2], al[mi][3], sAl + aoff);
            }
#pragma unroll
            for (int p = 0; p < 4; ++p) {
                uint32_t boff = offB[p] + ((((uint32_t)(ks * 2 + segselB) ^ swB[p])) << 4);
                uint32_t bh0, bh1, bh2, bh3, bl0, bl1, bl2, bl3;
                LDSM4(bh0, bh1, bh2, bh3, sB  + boff);
                LDSM4(bl0, bl1, bl2, bl3, sBl + boff);
#pragma unroll
                for (int mi = 0; mi < 4; ++mi) {
                    float* c0 = acc[mi][2 * p];
                    float* c1 = acc[mi][2 * p + 1];
                    hmma(c0, ah[mi][0], ah[mi][1], ah[mi][2], ah[mi][3], bh0, bh1);
                    hmma(c0, ah[mi][0], ah[mi][1], ah[mi][2], ah[mi][3], bl0, bl1);
                    hmma(c0, al[mi][0], al[mi][1], al[mi][2], al[mi][3], bh0, bh1);
                    hmma(c1, ah[mi][0], ah[mi][1], ah[mi][2], ah[mi][3], bh2, bh3);
                    hmma(c1, ah[mi][0], ah[mi][1], ah[mi][2], ah[mi][3], bl2, bl3);
                    hmma(c1, al[mi][0], al[mi][1], al[mi][2], al[mi][3], bh2, bh3);
                }
            }
        }
        buf = (buf + 1) % NSTAGE;
    }

    const int g  = lane >> 2;
    const int t4 = lane & 3;
#pragma unroll
    for (int mi = 0; mi < 4; ++mi) {
        int R0 = wm * 64 + mi * 16 + g;
        int R1 = R0 + 8;
#pragma unroll
        for (int ni = 0; ni < 8; ++ni) {
            int col = wn * 64 + ni * 8 + t4 * 2;
            float* a = acc[mi][ni];
            *(float2*)(C + (size_t)R0 * ldc + col) = make_float2(a[0], a[1]);
            *(float2*)(C + (size_t)R1 * ldc + col) = make_float2(a[2], a[3]);
        }
    }
}

__global__ void __launch_bounds__(128, 2)
k_attn_s()
{
    int h = blockIdx.z, r = blockIdx.y, cx = blockIdx.x;
    int cbase = (r - 8 > 0) ? (r - 8) : 0;
    int ct = cbase + cx;
    if (ct > r) return;
    size_t aoff = (size_t)r * 128 * (NHQ * DH) + (size_t)h * DH;
    size_t boff = (size_t)ct * 128 * (NKV * DH) + (size_t)(h / GROUPS) * DH;
    float* C = g_S + ((size_t)h * S_LEN + (size_t)r * 128) * BANDW + (size_t)cx * 128;
    gemm_hmma_tile(g_QH + aoff, g_QL + aoff, NHQ * DH,
                   g_KH + boff, g_KL + boff, NKV * DH,
                   C, BANDW, DH);
}

// ---------------- elementwise kernels ----------------
__global__ void __launch_bounds__(256)
k_split(const float* __restrict__ x, bf16* __restrict__ hi, bf16* __restrict__ lo, int n4)
{
    int base = (blockIdx.x * 256 + threadIdx.x) * 4;
#pragma unroll
    for (int u = 0; u < 4; ++u) {
        int i = base + u;
        if (i >= n4) return;
        float4 v = ((const float4*)x)[i];
        bf16 h0 = __float2bfloat16(v.x), h1 = __float2bfloat16(v.y);
        bf16 h2 = __float2bfloat16(v.z), h3 = __float2bfloat16(v.w);
        __nv_bfloat162 H0; H0.x = h0; H0.y = h1;
        __nv_bfloat162 H1; H1.x = h2; H1.y = h3;
        ((__nv_bfloat162*)hi)[i * 2 + 0] = H0;
        ((__nv_bfloat162*)hi)[i * 2 + 1] = H1;
        __nv_bfloat162 L0, L1;
        L0.x = __float2bfloat16(v.x - __bfloat162float(h0));
        L0.y = __float2bfloat16(v.y - __bfloat162float(h1));
        L1.x = __float2bfloat16(v.z - __bfloat162float(h2));
        L1.y = __float2bfloat16(v.w - __bfloat162float(h3));
        ((__nv_bfloat162*)lo)[i * 2 + 0] = L0;
        ((__nv_bfloat162*)lo)[i * 2 + 1] = L1;
    }
}

__global__ void __launch_bounds__(256)
k_rope_split(const float* __restrict__ cosb, const float* __restrict__ sinb)
{
    int idx = blockIdx.x * 256 + threadIdx.x;
    int d = idx & 127;
    int t = idx >> 7;
    int slot = t % (NHQ + NKV);
    int s = t / (NHQ + NKV);

    float c0 = cosb[s * DH + d],       s0 = sinb[s * DH + d];
    float c1 = cosb[s * DH + d + 128], s1 = sinb[s * DH + d + 128];

    if (slot < NHQ) {
        size_t b = (size_t)s * (NHQ * DH) + slot * DH + d;
        float x0 = g_Q[b], x1 = g_Q[b + 128];
        float y0 = x0 * c0 - x1 * s0;
        float y1 = x1 * c1 + x0 * s1;
        bf16 h0 = __float2bfloat16(y0), h1 = __float2bfloat16(y1);
        g_QH[b] = h0;       g_QH[b + 128] = h1;
        g_QL[b] = __float2bfloat16(y0 - __bfloat162float(h0));
        g_QL[b + 128] = __float2bfloat16(y1 - __bfloat162float(h1));
    } else {
        size_t b = (size_t)s * (NKV * DH) + (slot - NHQ) * DH + d;
        float x0 = g_K[b], x1 = g_K[b + 128];
        float y0 = x0 * c0 - x1 * s0;
        float y1 = x1 * c1 + x0 * s1;
        bf16 h0 = __float2bfloat16(y0), h1 = __float2bfloat16(y1);
        g_KH[b] = h0;       g_KH[b + 128] = h1;
        g_KL[b] = __float2bfloat16(y0 - __bfloat162float(h0));
        g_KL[b + 128] = __float2bfloat16(y1 - __bfloat162float(h1));
    }
}

__global__ void __launch_bounds__(256)
k_vtrans()
{
    __shared__ float t[32][33];
    int bs = blockIdx.x * 32, bo = blockIdx.y * 32;
    int tx = threadIdx.x, ty = threadIdx.y;
#pragma unroll
    for (int j = 0; j < 32; j += 8)
        t[ty + j][tx] = g_V[(size_t)(bs + ty + j) * (NKV * DH) + bo + tx];
    __syncthreads();
#pragma unroll
    for (int j = 0; j < 32; j += 8) {
        float v = t[tx][ty + j];
        size_t o = (size_t)(bo + ty + j) * S_LEN + bs + tx;
        bf16 h = __float2bfloat16(v);
        g_VtH[o] = h;
        g_VtL[o] = __float2bfloat16(v - __bfloat162float(h));
    }
}

// band softmax: fast-math softcap tanh + mask + normalize -> split-bf16 P
__global__ void __launch_bounds__(256)
k_softmax()
{
    int row  = blockIdx.x * 8 + (threadIdx.x >> 5);
    int lane = threadIdx.x & 31;
    int h = row >> 11;
    int q = row & 2047;

    size_t base = ((size_t)h * S_LEN + q) * BANDW;
    const float* p = g_S + base;
    int r  = q >> 7;
    int c0 = ((r - 8 > 0) ? (r - 8) : 0) * 128;
    int kmin = (q - (WINDOW - 1) > 0) ? (q - (WINDOW - 1)) : 0;

    float v[36];
    float m = -1e30f;
#pragma unroll
    for (int i = 0; i < 36; ++i) {
        int j = lane + 32 * i;
        int k = c0 + j;
        float tt;
        if (k >= kmin && k <= q) {
            float x = p[j] * (SCALING / SOFTCAP);
            x = fminf(fmaxf(x, -15.0f), 15.0f);     // tanh saturated beyond
            float e2 = __expf(2.0f * x);
            tt = SOFTCAP * ((e2 - 1.0f) / (e2 + 1.0f));
        } else {
            tt = -1e30f;
        }
        v[i] = tt;
        m = fmaxf(m, tt);
    }
#pragma unroll
    for (int o = 16; o > 0; o >>= 1)
        m = fmaxf(m, __shfl_xor_sync(0xFFFFFFFFu, m, o));

    float l = 0.0f;
#pragma unroll
    for (int i = 0; i < 36; ++i) {
        v[i] = __expf(v[i] - m);                    // masked -> underflow to 0
        l += v[i];
    }
#pragma unroll
    for (int o = 16; o > 0; o >>= 1)
        l += __shfl_xor_sync(0xFFFFFFFFu, l, o);

    float inv = 1.0f / l;
#pragma unroll
    for (int i = 0; i < 36; ++i) {
        float pv = v[i] * inv;
        bf16 hh = __float2bfloat16(pv);
        g_PH[base + lane + 32 * i] = hh;
        g_PL[base + lane + 32 * i] = __float2bfloat16(pv - __bfloat162float(hh));
    }
}

// ---------------- launch ----------------
extern "C" void kernel_launch(void* const* d_in, const int* in_sizes, int n_in,
                              void* d_out, int out_size)
{
    const float* hs   = (const float*)d_in[0];
    const float* cosb = (const float*)d_in[1];
    const float* sinb = (const float*)d_in[2];
    const float* wq   = (const float*)d_in[3];
    const float* wk   = (const float*)d_in[4];
    const float* wv   = (const float*)d_in[5];
    const float* wo   = (const float*)d_in[6];
    float* out = (float*)d_out;

    void *pQ, *pK, *pV;
    void *phsH, *phsL, *pwqH, *pwqL, *pwkH, *pwkL, *pwvH, *pwvL, *pwoH, *pwoL, *pAOH, *pAOL;
    cudaGetSymbolAddress(&pQ, g_Q);   cudaGetSymbolAddress(&pK, g_K);
    cudaGetSymbolAddress(&pV, g_V);
    cudaGetSymbolAddress(&phsH, g_hsH); cudaGetSymbolAddress(&phsL, g_hsL);
    cudaGetSymbolAddress(&pwqH, g_wqH); cudaGetSymbolAddress(&pwqL, g_wqL);
    cudaGetSymbolAddress(&pwkH, g_wkH); cudaGetSymbolAddress(&pwkL, g_wkL);
    cudaGetSymbolAddress(&pwvH, g_wvH); cudaGetSymbolAddress(&pwvL, g_wvL);
    cudaGetSymbolAddress(&pwoH, g_woH); cudaGetSymbolAddress(&pwoL, g_woL);
    cudaGetSymbolAddress(&pAOH, g_AOH); cudaGetSymbolAddress(&pAOL, g_AOL);

    cudaFuncSetAttribute(k_gemm_nt256, cudaFuncAttributeMaxDynamicSharedMemorySize, SMEM256);
    cudaFuncSetAttribute(k_attn_pv256, cudaFuncAttributeMaxDynamicSharedMemorySize, SMEM256);
    cudaFuncSetAttribute(k_attn_s,     cudaFuncAttributeMaxDynamicSharedMemorySize, SMEM_BYTES);

    // split inputs to bf16 hi/lo (4x ILP)
    int n4;
    n4 = S_LEN * HID / 4;      k_split<<<(n4 + 1023) / 1024, 256>>>(hs, (bf16*)phsH, (bf16*)phsL, n4);
    n4 = NHQ * DH * HID / 4;   k_split<<<(n4 + 1023) / 1024, 256>>>(wq, (bf16*)pwqH, (bf16*)pwqL, n4);
    n4 = NKV * DH * HID / 4;   k_split<<<(n4 + 1023) / 1024, 256>>>(wk, (bf16*)pwkH, (bf16*)pwkL, n4);
    n4 = NKV * DH * HID / 4;   k_split<<<(n4 + 1023) / 1024, 256>>>(wv, (bf16*)pwvH, (bf16*)pwvL, n4);
    n4 = HID * NHQ * DH / 4;   k_split<<<(n4 + 1023) / 1024, 256>>>(wo, (bf16*)pwoH, (bf16*)pwoL, n4);

    // QKV projections (NT, 128x256 tiles)
    k_gemm_nt256<<<dim3(NHQ * DH / 256, S_LEN / 128), 256, SMEM256>>>(
        (bf16*)phsH, (bf16*)phsL, HID, (bf16*)pwqH, (bf16*)pwqL, HID, (float*)pQ, NHQ * DH, HID);
    k_gemm_nt256<<<dim3(NKV * DH / 256, S_LEN / 128), 256, SMEM256>>>(
        (bf16*)phsH, (bf16*)phsL, HID, (bf16*)pwkH, (bf16*)pwkL, HID, (float*)pK, NKV * DH, HID);
    k_gemm_nt256<<<dim3(NKV * DH / 256, S_LEN / 128), 256, SMEM256>>>(
        (bf16*)phsH, (bf16*)phsL, HID, (bf16*)pwvH, (bf16*)pwvL, HID, (float*)pV, NKV * DH, HID);

    // RoPE + split, V transpose + split
    k_rope_split<<<(S_LEN * (NHQ + NKV) * 128) / 256, 256>>>(cosb, sinb);
    k_vtrans<<<dim3(S_LEN / 32, (NKV * DH) / 32), dim3(32, 8)>>>();

    // banded scores (HMMA, 128x128)
    k_attn_s<<<dim3(9, S_LEN / 128, NHQ), 128, SMEM_BYTES>>>();

    // softcap + mask + softmax -> split-bf16 P
    k_softmax<<<(NHQ * S_LEN) / 8, 256>>>();

    // PV (128x256 tile, full head dim per CTA) -> split-bf16 AO
    k_attn_pv256<<<dim3(S_LEN / 128, NHQ), 256, SMEM256>>>();

    // output projection (128x256 tiles)
    k_gemm_nt256<<<dim3(HID / 256, S_LEN / 128), 256, SMEM256>>>(
        (bf16*)pAOH, (bf16*)pAOL, NHQ * DH, (bf16*)pwoH, (bf16*)pwoL, NHQ * DH, out, HID, NHQ * DH);
}

// round 11
// speedup vs baseline: 2.5604x; 1.1685x over previous
#include <cuda_runtime.h>
#include <cuda_fp16.h>
#include <math.h>
#include <stdint.h>

// ---------------- problem constants ----------------
#define S_LEN   2048
#define HID     3584
#define NHQ     16
#define NKV     8
#define DH      256
#define GROUPS  2
#define WINDOW  1024
#define BANDW   1152
#define SOFTCAP 50.0f
#define SCALING 0.0625f
#define LSCALE  2048.0f
#define INVLS   (1.0f / 2048.0f)

typedef __half h16;

// ---------------- device scratch ----------------
__device__ float g_Q [(size_t)S_LEN * NHQ * DH];
__device__ float g_K [(size_t)S_LEN * NKV * DH];
__device__ float g_V [(size_t)S_LEN * NKV * DH];
__device__ float g_S [(size_t)NHQ * S_LEN * BANDW];

__device__ h16 g_hsH[(size_t)S_LEN * HID],      g_hsL[(size_t)S_LEN * HID];
__device__ h16 g_wqH[(size_t)NHQ * DH * HID],   g_wqL[(size_t)NHQ * DH * HID];
__device__ h16 g_wkH[(size_t)NKV * DH * HID],   g_wkL[(size_t)NKV * DH * HID];
__device__ h16 g_wvH[(size_t)NKV * DH * HID],   g_wvL[(size_t)NKV * DH * HID];
__device__ h16 g_woH[(size_t)HID * NHQ * DH],   g_woL[(size_t)HID * NHQ * DH];
__device__ h16 g_QH [(size_t)S_LEN * NHQ * DH], g_QL [(size_t)S_LEN * NHQ * DH];
__device__ h16 g_KH [(size_t)S_LEN * NKV * DH], g_KL [(size_t)S_LEN * NKV * DH];
__device__ h16 g_VtH[(size_t)NKV * DH * S_LEN], g_VtL[(size_t)NKV * DH * S_LEN];
__device__ h16 g_PH [(size_t)NHQ * S_LEN * BANDW], g_PL[(size_t)NHQ * S_LEN * BANDW];
__device__ h16 g_AOH[(size_t)S_LEN * NHQ * DH], g_AOL[(size_t)S_LEN * NHQ * DH];

// ---------------- helpers ----------------
__device__ __forceinline__ uint32_t smem_u32(const void* p) {
    uint32_t a;
    asm("{ .reg .u64 t; cvta.to.shared.u64 t, %1; cvt.u32.u64 %0, t; }" : "=r"(a) : "l"(p));
    return a;
}
__device__ __forceinline__ void cp16(uint32_t saddr, const void* g) {
    asm volatile("cp.async.cg.shared.global [%0], [%1], 16;" :: "r"(saddr), "l"(g) : "memory");
}
#define CP_COMMIT() asm volatile("cp.async.commit_group;" ::: "memory")

#define LDSM4(r0, r1, r2, r3, addr) \
    asm volatile("ldmatrix.sync.aligned.m8n8.x4.shared.b16 {%0,%1,%2,%3}, [%4];" \
        : "=r"(r0), "=r"(r1), "=r"(r2), "=r"(r3) : "r"(addr))

// fp16 operands, fp32 accumulator
__device__ __forceinline__ void mma32(float* c,
    uint32_t a0, uint32_t a1, uint32_t a2, uint32_t a3,
    uint32_t b0, uint32_t b1)
{
    asm volatile(
        "mma.sync.aligned.m16n8k16.row.col.f32.f16.f16.f32 "
        "{%0,%1,%2,%3}, {%4,%5,%6,%7}, {%8,%9}, {%0,%1,%2,%3};"
        : "+f"(c[0]), "+f"(c[1]), "+f"(c[2]), "+f"(c[3])
        : "r"(a0), "r"(a1), "r"(a2), "r"(a3), "r"(b0), "r"(b1));
}

// fp16 operands, fp16 accumulator (2 packed regs)
__device__ __forceinline__ void mma16(uint32_t* c,
    uint32_t a0, uint32_t a1, uint32_t a2, uint32_t a3,
    uint32_t b0, uint32_t b1)
{
    asm volatile(
        "mma.sync.aligned.m16n8k16.row.col.f16.f16.f16.f16 "
        "{%0,%1}, {%2,%3,%4,%5}, {%6,%7}, {%0,%1};"
        : "+r"(c[0]), "+r"(c[1])
        : "r"(a0), "r"(a1), "r"(a2), "r"(a3), "r"(b0), "r"(b1));
}

// ---------------- stage layout ----------------
// Stage (32 KB): Ah[128][32] Al Bh Bl, each 8 KB, row pitch 64 B,
// 16B segments swizzled: seg_store = seg ^ ((row>>1)&3).
#define STAGE_BYTES 32768
#define NSTAGE      3
#define SMEM_BYTES  (NSTAGE * STAGE_BYTES)

__device__ __forceinline__ void stage_cp(
    const h16* __restrict__ Ah, const h16* __restrict__ Al, int lda,
    const h16* __restrict__ Bh, const h16* __restrict__ Bl, int ldb,
    int k0, uint32_t smb, int buf, int tid)
{
    uint32_t sb = smb + buf * STAGE_BYTES;
#pragma unroll
    for (int i = 0; i < 4; ++i) {
        int si  = tid + i * 128;
        int row = si >> 2;
        int seg = si & 3;
        uint32_t soff = row * 64 + ((seg ^ ((row >> 1) & 3)) << 4);
        size_t goA = (size_t)row * lda + k0 + seg * 8;
        size_t goB = (size_t)row * ldb + k0 + seg * 8;
        cp16(sb +     0 + soff, Ah + goA);
        cp16(sb +  8192 + soff, Al + goA);
        cp16(sb + 16384 + soff, Bh + goB);
        cp16(sb + 24576 + soff, Bl + goB);
    }
}

// ---------------- 128x128 NT GEMM: C = A*B^T, split-fp16, mixed accum ----------------
// 128 threads (4 warps, 2x2 grid, warp tile 64x64). K % 32 == 0.
// EPI=0: write fp32 C.  EPI=1: write split-fp16 (Ch, Cl scaled by LSCALE).
template <int EPI>
__device__ void gemm_tile(
    const h16* __restrict__ Ah, const h16* __restrict__ Al, int lda,
    const h16* __restrict__ Bh, const h16* __restrict__ Bl, int ldb,
    float* __restrict__ C, h16* __restrict__ Ch, h16* __restrict__ Cl,
    int ldc, int K)
{
    extern __shared__ char smem[];
    const uint32_t smb = smem_u32(smem);
    const int tid  = threadIdx.x;
    const int lane = tid & 31;
    const int wid  = tid >> 5;
    const int wm   = wid >> 1;
    const int wn   = wid & 1;
    const int la   = lane & 7;
    const int grp  = lane >> 3;

    float acc[4][8][4];
    uint32_t c16[4][8][2];
#pragma unroll
    for (int mi = 0; mi < 4; ++mi)
#pragma unroll
        for (int ni = 0; ni < 8; ++ni) {
#pragma unroll
            for (int q = 0; q < 4; ++q) acc[mi][ni][q] = 0.0f;
            c16[mi][ni][0] = 0u; c16[mi][ni][1] = 0u;
        }

    uint32_t offA[4], swA[4];
#pragma unroll
    for (int mi = 0; mi < 4; ++mi) {
        int r = wm * 64 + mi * 16 + la + (grp & 1) * 8;
        offA[mi] = r * 64;
        swA[mi]  = (r >> 1) & 3;
    }
    const int segselA = grp >> 1;
    uint32_t offB[4], swB[4];
#pragma unroll
    for (int p = 0; p < 4; ++p) {
        int r = wn * 64 + p * 16 + la + (grp >> 1) * 8;
        offB[p] = r * 64;
        swB[p]  = (r >> 1) & 3;
    }
    const int segselB = grp & 1;

    const int nK = K >> 5;
    stage_cp(Ah, Al, lda, Bh, Bl, ldb, 0, smb, 0, tid);
    CP_COMMIT();
    if (nK > 1) stage_cp(Ah, Al, lda, Bh, Bl, ldb, 32, smb, 1, tid);
    CP_COMMIT();

    int buf = 0;
    for (int ki = 0; ki < nK; ++ki) {
        __syncthreads();
        if (ki + 2 < nK)
            stage_cp(Ah, Al, lda, Bh, Bl, ldb, (ki + 2) << 5, smb, (ki + 2) % NSTAGE, tid);
        CP_COMMIT();
        asm volatile("cp.async.wait_group %0;" :: "n"(2) : "memory");
        __syncthreads();

        const uint32_t sA  = smb + buf * STAGE_BYTES;
        const uint32_t sAl = sA + 8192;
        const uint32_t sB  = sA + 16384;
        const uint32_t sBl = sA + 24576;

#pragma unroll
        for (int ks = 0; ks < 2; ++ks) {
            uint32_t ah[4][4], al[4][4];
#pragma unroll
            for (int mi = 0; mi < 4; ++mi) {
                uint32_t aoff = offA[mi] + ((((uint32_t)(ks * 2 + segselA) ^ swA[mi])) << 4);
                LDSM4(ah[mi][0], ah[mi][1], ah[mi][2], ah[mi][3], sA + aoff);
                LDSM4(al[mi][0], al[mi][1], al[mi][2], al[mi][3], sAl + aoff);
            }
#pragma unroll
            for (int p = 0; p < 4; ++p) {
                uint32_t boff = offB[p] + ((((uint32_t)(ks * 2 + segselB) ^ swB[p])) << 4);
                uint32_t bh0, bh1, bh2, bh3, bl0, bl1, bl2, bl3;
                LDSM4(bh0, bh1, bh2, bh3, sB  + boff);
                LDSM4(bl0, bl1, bl2, bl3, sBl + boff);
#pragma unroll
                for (int mi = 0; mi < 4; ++mi) {
                    mma32(acc[mi][2 * p], ah[mi][0], ah[mi][1], ah[mi][2], ah[mi][3], bh0, bh1);
                    mma16(c16[mi][2 * p], ah[mi][0], ah[mi][1], ah[mi][2], ah[mi][3], bl0, bl1);
                    mma16(c16[mi][2 * p], al[mi][0], al[mi][1], al[mi][2], al[mi][3], bh0, bh1);
                    mma32(acc[mi][2 * p + 1], ah[mi][0], ah[mi][1], ah[mi][2], ah[mi][3], bh2, bh3);
                    mma16(c16[mi][2 * p + 1], ah[mi][0], ah[mi][1], ah[mi][2], ah[mi][3], bl2, bl3);
                    mma16(c16[mi][2 * p + 1], al[mi][0], al[mi][1], al[mi][2], al[mi][3], bh2, bh3);
                }
            }
        }
        buf = (buf + 1) % NSTAGE;
    }

    // epilogue: C = acc32 + acc16 / LSCALE
    const int g  = lane >> 2;
    const int t4 = lane & 3;
#pragma unroll
    for (int mi = 0; mi < 4; ++mi) {
        int R0 = wm * 64 + mi * 16 + g;
        int R1 = R0 + 8;
#pragma unroll
        for (int ni = 0; ni < 8; ++ni) {
            int col = wn * 64 + ni * 8 + t4 * 2;
            float* a = acc[mi][ni];
            __half2 p0 = *reinterpret_cast<__half2*>(&c16[mi][ni][0]);
            __half2 p1 = *reinterpret_cast<__half2*>(&c16[mi][ni][1]);
            float f0 = a[0] + __low2float(p0)  * INVLS;
            float f1 = a[1] + __high2float(p0) * INVLS;
            float f2 = a[2] + __low2float(p1)  * INVLS;
            float f3 = a[3] + __high2float(p1) * INVLS;
            if (EPI == 0) {
                *(float2*)(C + (size_t)R0 * ldc + col) = make_float2(f0, f1);
                *(float2*)(C + (size_t)R1 * ldc + col) = make_float2(f2, f3);
            } else {
                h16 h0 = __float2half(f0), h1 = __float2half(f1);
                h16 h2 = __float2half(f2), h3 = __float2half(f3);
                __half2 H0; H0.x = h0; H0.y = h1;
                __half2 H1; H1.x = h2; H1.y = h3;
                __half2 L0, L1;
                L0.x = __float2half((f0 - __half2float(h0)) * LSCALE);
                L0.y = __float2half((f1 - __half2float(h1)) * LSCALE);
                L1.x = __float2half((f2 - __half2float(h2)) * LSCALE);
                L1.y = __float2half((f3 - __half2float(h3)) * LSCALE);
                *(__half2*)(Ch + (size_t)R0 * ldc + col) = H0;
                *(__half2*)(Ch + (size_t)R1 * ldc + col) = H1;
                *(__half2*)(Cl + (size_t)R0 * ldc + col) = L0;
                *(__half2*)(Cl + (size_t)R1 * ldc + col) = L1;
            }
        }
    }
}

// ---------------- GEMM wrapper kernels ----------------
__global__ void __launch_bounds__(128, 1)
k_gemm_nt(const h16* Ah, const h16* Al, int lda,
          const h16* Bh, const h16* Bl, int ldb,
          float* C, int ldc, int K)
{
    size_t m0 = (size_t)blockIdx.y * 128, n0 = (size_t)blockIdx.x * 128;
    gemm_tile<0>(Ah + m0 * lda, Al + m0 * lda, lda,
                 Bh + n0 * ldb, Bl + n0 * ldb, ldb,
                 C + m0 * ldc + n0, nullptr, nullptr, ldc, K);
}

__global__ void __launch_bounds__(128, 1)
k_attn_s()
{
    int h = blockIdx.z, r = blockIdx.y, cx = blockIdx.x;
    int cbase = (r - 8 > 0) ? (r - 8) : 0;
    int ct = cbase + cx;
    if (ct > r) return;
    size_t aoff = (size_t)r * 128 * (NHQ * DH) + (size_t)h * DH;
    size_t boff = (size_t)ct * 128 * (NKV * DH) + (size_t)(h / GROUPS) * DH;
    float* C = g_S + ((size_t)h * S_LEN + (size_t)r * 128) * BANDW + (size_t)cx * 128;
    gemm_tile<0>(g_QH + aoff, g_QL + aoff, NHQ * DH,
                 g_KH + boff, g_KL + boff, NKV * DH,
                 C, nullptr, nullptr, BANDW, DH);
}

__global__ void __launch_bounds__(128, 1)
k_attn_pv()
{
    int h = blockIdx.z, r = blockIdx.y, nx = blockIdx.x;
    int c0 = ((r - 8 > 0) ? (r - 8) : 0) * 128;
    size_t aoff = ((size_t)h * S_LEN + (size_t)r * 128) * BANDW;
    size_t boff = ((size_t)(h / GROUPS) * DH + (size_t)nx * 128) * S_LEN + (size_t)c0;
    size_t coff = (size_t)r * 128 * (NHQ * DH) + (size_t)h * DH + (size_t)nx * 128;
    gemm_tile<1>(g_PH + aoff, g_PL + aoff, BANDW,
                 g_VtH + boff, g_VtL + boff, S_LEN,
                 nullptr, g_AOH + coff, g_AOL + coff, NHQ * DH, BANDW);
}

// ---------------- elementwise kernels ----------------
__global__ void __launch_bounds__(256)
k_split(const float* __restrict__ x, h16* __restrict__ hi, h16* __restrict__ lo, int n4)
{
    int i = blockIdx.x * 256 + threadIdx.x;
    if (i >= n4) return;
    float4 v = ((const float4*)x)[i];
    h16 h0 = __float2half(v.x), h1 = __float2half(v.y);
    h16 h2 = __float2half(v.z), h3 = __float2half(v.w);
    __half2 H0; H0.x = h0; H0.y = h1;
    __half2 H1; H1.x = h2; H1.y = h3;
    ((__half2*)hi)[i * 2 + 0] = H0;
    ((__half2*)hi)[i * 2 + 1] = H1;
    __half2 L0, L1;
    L0.x = __float2half((v.x - __half2float(h0)) * LSCALE);
    L0.y = __float2half((v.y - __half2float(h1)) * LSCALE);
    L1.x = __float2half((v.z - __half2float(h2)) * LSCALE);
    L1.y = __float2half((v.w - __half2float(h3)) * LSCALE);
    ((__half2*)lo)[i * 2 + 0] = L0;
    ((__half2*)lo)[i * 2 + 1] = L1;
}

__global__ void __launch_bounds__(256)
k_rope_split(const float* __restrict__ cosb, const float* __restrict__ sinb)
{
    int idx = blockIdx.x * 256 + threadIdx.x;
    int d = idx & 127;
    int t = idx >> 7;
    int slot = t % (NHQ + NKV);
    int s = t / (NHQ + NKV);

    float c0 = cosb[s * DH + d],       s0 = sinb[s * DH + d];
    float c1 = cosb[s * DH + d + 128], s1 = sinb[s * DH + d + 128];

    if (slot < NHQ) {
        size_t b = (size_t)s * (NHQ * DH) + slot * DH + d;
        float x0 = g_Q[b], x1 = g_Q[b + 128];
        float y0 = x0 * c0 - x1 * s0;
        float y1 = x1 * c1 + x0 * s1;
        h16 h0 = __float2half(y0), h1 = __float2half(y1);
        g_QH[b] = h0;       g_QH[b + 128] = h1;
        g_QL[b] = __float2half((y0 - __half2float(h0)) * LSCALE);
        g_QL[b + 128] = __float2half((y1 - __half2float(h1)) * LSCALE);
    } else {
        size_t b = (size_t)s * (NKV * DH) + (slot - NHQ) * DH + d;
        float x0 = g_K[b], x1 = g_K[b + 128];
        float y0 = x0 * c0 - x1 * s0;
        float y1 = x1 * c1 + x0 * s1;
        h16 h0 = __float2half(y0), h1 = __float2half(y1);
        g_KH[b] = h0;       g_KH[b + 128] = h1;
        g_KL[b] = __float2half((y0 - __half2float(h0)) * LSCALE);
        g_KL[b + 128] = __float2half((y1 - __half2float(h1)) * LSCALE);
    }
}

__global__ void __launch_bounds__(256)
k_vtrans()
{
    __shared__ float t[32][33];
    int bs = blockIdx.x * 32, bo = blockIdx.y * 32;
    int tx = threadIdx.x, ty = threadIdx.y;
#pragma unroll
    for (int j = 0; j < 32; j += 8)
        t[ty + j][tx] = g_V[(size_t)(bs + ty + j) * (NKV * DH) + bo + tx];
    __syncthreads();
#pragma unroll
    for (int j = 0; j < 32; j += 8) {
        float v = t[tx][ty + j];
        size_t o = (size_t)(bo + ty + j) * S_LEN + bs + tx;
        h16 h = __float2half(v);
        g_VtH[o] = h;
        g_VtL[o] = __float2half((v - __half2float(h)) * LSCALE);
    }
}

// band softmax: fast-math softcap tanh + mask + normalize -> split-fp16 P
__global__ void __launch_bounds__(256)
k_softmax()
{
    int row  = blockIdx.x * 8 + (threadIdx.x >> 5);
    int lane = threadIdx.x & 31;
    int h = row >> 11;
    int q = row & 2047;

    size_t base = ((size_t)h * S_LEN + q) * BANDW;
    const float* p = g_S + base;
    int r  = q >> 7;
    int c0 = ((r - 8 > 0) ? (r - 8) : 0) * 128;
    int kmin = (q - (WINDOW - 1) > 0) ? (q - (WINDOW - 1)) : 0;

    float v[36];
    float m = -1e30f;
#pragma unroll
    for (int i = 0; i < 36; ++i) {
        int j = lane + 32 * i;
        int k = c0 + j;
        float tt;
        if (k >= kmin && k <= q) {
            float x = p[j] * (SCALING / SOFTCAP);
            x = fminf(fmaxf(x, -15.0f), 15.0f);
            float e2 = __expf(2.0f * x);
            tt = SOFTCAP * ((e2 - 1.0f) / (e2 + 1.0f));
        } else {
            tt = -1e30f;
        }
        v[i] = tt;
        m = fmaxf(m, tt);
    }
#pragma unroll
    for (int o = 16; o > 0; o >>= 1)
        m = fmaxf(m, __shfl_xor_sync(0xFFFFFFFFu, m, o));

    float l = 0.0f;
#pragma unroll
    for (int i = 0; i < 36; ++i) {
        v[i] = __expf(v[i] - m);
        l += v[i];
    }
#pragma unroll
    for (int o = 16; o > 0; o >>= 1)
        l += __shfl_xor_sync(0xFFFFFFFFu, l, o);

    float inv = 1.0f / l;
#pragma unroll
    for (int i = 0; i < 36; ++i) {
        float pv = v[i] * inv;
        h16 hh = __float2half(pv);
        g_PH[base + lane + 32 * i] = hh;
        g_PL[base + lane + 32 * i] = __float2half((pv - __half2float(hh)) * LSCALE);
    }
}

// ---------------- launch ----------------
extern "C" void kernel_launch(void* const* d_in, const int* in_sizes, int n_in,
                              void* d_out, int out_size)
{
    const float* hs   = (const float*)d_in[0];
    const float* cosb = (const float*)d_in[1];
    const float* sinb = (const float*)d_in[2];
    const float* wq   = (const float*)d_in[3];
    const float* wk   = (const float*)d_in[4];
    const float* wv   = (const float*)d_in[5];
    const float* wo   = (const float*)d_in[6];
    float* out = (float*)d_out;

    void *pQ, *pK, *pV;
    void *phsH, *phsL, *pwqH, *pwqL, *pwkH, *pwkL, *pwvH, *pwvL, *pwoH, *pwoL, *pAOH, *pAOL;
    cudaGetSymbolAddress(&pQ, g_Q);   cudaGetSymbolAddress(&pK, g_K);
    cudaGetSymbolAddress(&pV, g_V);
    cudaGetSymbolAddress(&phsH, g_hsH); cudaGetSymbolAddress(&phsL, g_hsL);
    cudaGetSymbolAddress(&pwqH, g_wqH); cudaGetSymbolAddress(&pwqL, g_wqL);
    cudaGetSymbolAddress(&pwkH, g_wkH); cudaGetSymbolAddress(&pwkL, g_wkL);
    cudaGetSymbolAddress(&pwvH, g_wvH); cudaGetSymbolAddress(&pwvL, g_wvL);
    cudaGetSymbolAddress(&pwoH, g_woH); cudaGetSymbolAddress(&pwoL, g_woL);
    cudaGetSymbolAddress(&pAOH, g_AOH); cudaGetSymbolAddress(&pAOL, g_AOL);

    cudaFuncSetAttribute(k_gemm_nt, cudaFuncAttributeMaxDynamicSharedMemorySize, SMEM_BYTES);
    cudaFuncSetAttribute(k_attn_s,  cudaFuncAttributeMaxDynamicSharedMemorySize, SMEM_BYTES);
    cudaFuncSetAttribute(k_attn_pv, cudaFuncAttributeMaxDynamicSharedMemorySize, SMEM_BYTES);

    // split inputs to fp16 hi/lo
    int n4;
    n4 = S_LEN * HID / 4;      k_split<<<(n4 + 255) / 256, 256>>>(hs, (h16*)phsH, (h16*)phsL, n4);
    n4 = NHQ * DH * HID / 4;   k_split<<<(n4 + 255) / 256, 256>>>(wq, (h16*)pwqH, (h16*)pwqL, n4);
    n4 = NKV * DH * HID / 4;   k_split<<<(n4 + 255) / 256, 256>>>(wk, (h16*)pwkH, (h16*)pwkL, n4);
    n4 = NKV * DH * HID / 4;   k_split<<<(n4 + 255) / 256, 256>>>(wv, (h16*)pwvH, (h16*)pwvL, n4);
    n4 = HID * NHQ * DH / 4;   k_split<<<(n4 + 255) / 256, 256>>>(wo, (h16*)pwoH, (h16*)pwoL, n4);

    // QKV projections (NT)
    k_gemm_nt<<<dim3(NHQ * DH / 128, S_LEN / 128), 128, SMEM_BYTES>>>(
        (h16*)phsH, (h16*)phsL, HID, (h16*)pwqH, (h16*)pwqL, HID, (float*)pQ, NHQ * DH, HID);
    k_gemm_nt<<<dim3(NKV * DH / 128, S_LEN / 128), 128, SMEM_BYTES>>>(
        (h16*)phsH, (h16*)phsL, HID, (h16*)pwkH, (h16*)pwkL, HID, (float*)pK, NKV * DH, HID);
    k_gemm_nt<<<dim3(NKV * DH / 128, S_LEN / 128), 128, SMEM_BYTES>>>(
        (h16*)phsH, (h16*)phsL, HID, (h16*)pwvH, (h16*)pwvL, HID, (float*)pV, NKV * DH, HID);

    // RoPE + split, V transpose + split
    k_rope_split<<<(S_LEN * (NHQ + NKV) * 128) / 256, 256>>>(cosb, sinb);
    k_vtrans<<<dim3(S_LEN / 32, (NKV * DH) / 32), dim3(32, 8)>>>();

    // banded scores
    k_attn_s<<<dim3(9, S_LEN / 128, NHQ), 128, SMEM_BYTES>>>();

    // softcap + mask + softmax -> split-fp16 P
    k_softmax<<<(NHQ * S_LEN) / 8, 256>>>();

    // PV — epilogue writes split-fp16 AO directly
    k_attn_pv<<<dim3(2, S_LEN / 128, NHQ), 128, SMEM_BYTES>>>();

    // output projection
    k_gemm_nt<<<dim3(HID / 128, S_LEN / 128), 128, SMEM_BYTES>>>(
        (h16*)pAOH, (h16*)pAOL, NHQ * DH, (h16*)pwoH, (h16*)pwoL, NHQ * DH, out, HID, NHQ * DH);
}

// round 12
// speedup vs baseline: 2.9696x; 1.1598x over previous
#include <cuda_runtime.h>
#include <cuda_fp16.h>
#include <math.h>
#include <stdint.h>

// ---------------- problem constants ----------------
#define S_LEN   2048
#define HID     3584
#define NHQ     16
#define NKV     8
#define DH      256
#define GROUPS  2
#define WINDOW  1024
#define BANDW   1152
#define SOFTCAP 50.0f
#define SCALING 0.0625f

typedef __half h16;

// ---------------- device scratch ----------------
__device__ float g_Q [(size_t)S_LEN * NHQ * DH];
__device__ float g_K [(size_t)S_LEN * NKV * DH];
__device__ float g_V [(size_t)S_LEN * NKV * DH];
__device__ float g_S [(size_t)NHQ * S_LEN * BANDW];

__device__ h16 g_hsH[(size_t)S_LEN * HID],      g_hsL[(size_t)S_LEN * HID];
__device__ h16 g_wqH[(size_t)NHQ * DH * HID],   g_wqL[(size_t)NHQ * DH * HID];
__device__ h16 g_wkH[(size_t)NKV * DH * HID],   g_wkL[(size_t)NKV * DH * HID];
__device__ h16 g_wvH[(size_t)NKV * DH * HID];                    // hi only (2-product)
__device__ h16 g_woH[(size_t)HID * NHQ * DH];                    // hi only (2-product)
__device__ h16 g_QH [(size_t)S_LEN * NHQ * DH], g_QL [(size_t)S_LEN * NHQ * DH];
__device__ h16 g_KH [(size_t)S_LEN * NKV * DH], g_KL [(size_t)S_LEN * NKV * DH];
__device__ h16 g_VtH[(size_t)NKV * DH * S_LEN], g_VtL[(size_t)NKV * DH * S_LEN];
__device__ h16 g_PH [(size_t)NHQ * S_LEN * BANDW], g_PL[(size_t)NHQ * S_LEN * BANDW];
__device__ h16 g_AOH[(size_t)S_LEN * NHQ * DH], g_AOL[(size_t)S_LEN * NHQ * DH];

// ---------------- helpers ----------------
__device__ __forceinline__ uint32_t smem_u32(const void* p) {
    uint32_t a;
    asm("{ .reg .u64 t; cvta.to.shared.u64 t, %1; cvt.u32.u64 %0, t; }" : "=r"(a) : "l"(p));
    return a;
}
__device__ __forceinline__ void cp16(uint32_t saddr, const void* g) {
    asm volatile("cp.async.cg.shared.global [%0], [%1], 16;" :: "r"(saddr), "l"(g) : "memory");
}
#define CP_COMMIT() asm volatile("cp.async.commit_group;" ::: "memory")

#define LDSM4(r0, r1, r2, r3, addr) \
    asm volatile("ldmatrix.sync.aligned.m8n8.x4.shared.b16 {%0,%1,%2,%3}, [%4];" \
        : "=r"(r0), "=r"(r1), "=r"(r2), "=r"(r3) : "r"(addr))

// fp16 operands, fp32 accumulator
__device__ __forceinline__ void mma32(float* c,
    uint32_t a0, uint32_t a1, uint32_t a2, uint32_t a3,
    uint32_t b0, uint32_t b1)
{
    asm volatile(
        "mma.sync.aligned.m16n8k16.row.col.f32.f16.f16.f32 "
        "{%0,%1,%2,%3}, {%4,%5,%6,%7}, {%8,%9}, {%0,%1,%2,%3};"
        : "+f"(c[0]), "+f"(c[1]), "+f"(c[2]), "+f"(c[3])
        : "r"(a0), "r"(a1), "r"(a2), "r"(a3), "r"(b0), "r"(b1));
}

// ---------------- stage layout ----------------
// NPROD==3 stage (32 KB): Ah[128][32] Al Bh Bl (8 KB each)
// NPROD==2 stage (24 KB): Ah Al Bh
// row pitch 64 B, 16B segs swizzled seg ^ ((row>>1)&3). 3 stages.
#define NSTAGE 3

template <int NPROD>
__device__ __forceinline__ void stage_cp(
    const h16* __restrict__ Ah, const h16* __restrict__ Al, int lda,
    const h16* __restrict__ Bh, const h16* __restrict__ Bl, int ldb,
    int k0, uint32_t smb, int buf, int tid)
{
    const int STG = (NPROD == 3) ? 32768 : 24576;
    uint32_t sb = smb + buf * STG;
#pragma unroll
    for (int i = 0; i < 4; ++i) {
        int si  = tid + i * 128;
        int row = si >> 2;
        int seg = si & 3;
        uint32_t soff = row * 64 + ((seg ^ ((row >> 1) & 3)) << 4);
        size_t goA = (size_t)row * lda + k0 + seg * 8;
        size_t goB = (size_t)row * ldb + k0 + seg * 8;
        cp16(sb +     0 + soff, Ah + goA);
        cp16(sb +  8192 + soff, Al + goA);
        cp16(sb + 16384 + soff, Bh + goB);
        if (NPROD == 3) cp16(sb + 24576 + soff, Bl + goB);
    }
}

// ---------------- 128x128 NT GEMM tile, fp16 split, fp32 accum ----------------
// 128 threads (4 warps, 2x2, warp tile 64x64). K % 32 == 0.
// NPROD=3: Ah*Bh + Ah*Bl + Al*Bh.  NPROD=2: Ah*Bh + Al*Bh.
// EPI=0: fp32 C.  EPI=1: split-fp16 (Ch,Cl), lo unscaled.
template <int NPROD, int EPI>
__device__ void gemm_tile(
    const h16* __restrict__ Ah, const h16* __restrict__ Al, int lda,
    const h16* __restrict__ Bh, const h16* __restrict__ Bl, int ldb,
    float* __restrict__ C, h16* __restrict__ Ch, h16* __restrict__ Cl,
    int ldc, int K)
{
    const int STG = (NPROD == 3) ? 32768 : 24576;
    extern __shared__ char smem[];
    const uint32_t smb = smem_u32(smem);
    const int tid  = threadIdx.x;
    const int lane = tid & 31;
    const int wid  = tid >> 5;
    const int wm   = wid >> 1;
    const int wn   = wid & 1;
    const int la   = lane & 7;
    const int grp  = lane >> 3;

    float acc[4][8][4];
#pragma unroll
    for (int mi = 0; mi < 4; ++mi)
#pragma unroll
        for (int ni = 0; ni < 8; ++ni)
#pragma unroll
            for (int q = 0; q < 4; ++q) acc[mi][ni][q] = 0.0f;

    uint32_t offA[4], swA[4];
#pragma unroll
    for (int mi = 0; mi < 4; ++mi) {
        int r = wm * 64 + mi * 16 + la + (grp & 1) * 8;
        offA[mi] = r * 64;
        swA[mi]  = (r >> 1) & 3;
    }
    const int segselA = grp >> 1;
    uint32_t offB[4], swB[4];
#pragma unroll
    for (int p = 0; p < 4; ++p) {
        int r = wn * 64 + p * 16 + la + (grp >> 1) * 8;
        offB[p] = r * 64;
        swB[p]  = (r >> 1) & 3;
    }
    const int segselB = grp & 1;

    const int nK = K >> 5;
    stage_cp<NPROD>(Ah, Al, lda, Bh, Bl, ldb, 0, smb, 0, tid);
    CP_COMMIT();
    stage_cp<NPROD>(Ah, Al, lda, Bh, Bl, ldb, 32, smb, 1, tid);
    CP_COMMIT();

    for (int ki = 0; ki < nK; ++ki) {
        asm volatile("cp.async.wait_group 1;" ::: "memory");   // stage ki arrived
        __syncthreads();                                       // visible + prev consume done
        if (ki + 2 < nK)
            stage_cp<NPROD>(Ah, Al, lda, Bh, Bl, ldb, (ki + 2) << 5, smb, (ki + 2) % NSTAGE, tid);
        CP_COMMIT();

        const uint32_t sA  = smb + (ki % NSTAGE) * STG;
        const uint32_t sAl = sA + 8192;
        const uint32_t sB  = sA + 16384;
        const uint32_t sBl = sA + 24576;

#pragma unroll
        for (int ks = 0; ks < 2; ++ks) {
            uint32_t ah[4][4], al[4][4];
#pragma unroll
            for (int mi = 0; mi < 4; ++mi) {
                uint32_t aoff = offA[mi] + ((((uint32_t)(ks * 2 + segselA) ^ swA[mi])) << 4);
                LDSM4(ah[mi][0], ah[mi][1], ah[mi][2], ah[mi][3], sA + aoff);
                LDSM4(al[mi][0], al[mi][1], al[mi][2], al[mi][3], sAl + aoff);
            }
#pragma unroll
            for (int p = 0; p < 4; ++p) {
                uint32_t boff = offB[p] + ((((uint32_t)(ks * 2 + segselB) ^ swB[p])) << 4);
                uint32_t bh0, bh1, bh2, bh3;
                LDSM4(bh0, bh1, bh2, bh3, sB + boff);
                uint32_t bl0, bl1, bl2, bl3;
                if (NPROD == 3) { LDSM4(bl0, bl1, bl2, bl3, sBl + boff); }
#pragma unroll
                for (int mi = 0; mi < 4; ++mi) {
                    float* c0 = acc[mi][2 * p];
                    float* c1 = acc[mi][2 * p + 1];
                    mma32(c0, ah[mi][0], ah[mi][1], ah[mi][2], ah[mi][3], bh0, bh1);
                    mma32(c0, al[mi][0], al[mi][1], al[mi][2], al[mi][3], bh0, bh1);
                    mma32(c1, ah[mi][0], ah[mi][1], ah[mi][2], ah[mi][3], bh2, bh3);
                    mma32(c1, al[mi][0], al[mi][1], al[mi][2], al[mi][3], bh2, bh3);
                    if (NPROD == 3) {
                        mma32(c0, ah[mi][0], ah[mi][1], ah[mi][2], ah[mi][3], bl0, bl1);
                        mma32(c1, ah[mi][0], ah[mi][1], ah[mi][2], ah[mi][3], bl2, bl3);
                    }
                }
            }
        }
    }

    const int g  = lane >> 2;
    const int t4 = lane & 3;
#pragma unroll
    for (int mi = 0; mi < 4; ++mi) {
        int R0 = wm * 64 + mi * 16 + g;
        int R1 = R0 + 8;
#pragma unroll
        for (int ni = 0; ni < 8; ++ni) {
            int col = wn * 64 + ni * 8 + t4 * 2;
            float* a = acc[mi][ni];
            if (EPI == 0) {
                *(float2*)(C + (size_t)R0 * ldc + col) = make_float2(a[0], a[1]);
                *(float2*)(C + (size_t)R1 * ldc + col) = make_float2(a[2], a[3]);
            } else {
                h16 h0 = __float2half(a[0]), h1 = __float2half(a[1]);
                h16 h2 = __float2half(a[2]), h3 = __float2half(a[3]);
                __half2 H0; H0.x = h0; H0.y = h1;
                __half2 H1; H1.x = h2; H1.y = h3;
                __half2 L0, L1;
                L0.x = __float2half(a[0] - __half2float(h0));
                L0.y = __float2half(a[1] - __half2float(h1));
                L1.x = __float2half(a[2] - __half2float(h2));
                L1.y = __float2half(a[3] - __half2float(h3));
                *(__half2*)(Ch + (size_t)R0 * ldc + col) = H0;
                *(__half2*)(Ch + (size_t)R1 * ldc + col) = H1;
                *(__half2*)(Cl + (size_t)R0 * ldc + col) = L0;
                *(__half2*)(Cl + (size_t)R1 * ldc + col) = L1;
            }
        }
    }
}

// ---------------- GEMM wrapper kernels ----------------
#define SMEM3 (NSTAGE * 32768)
#define SMEM2 (NSTAGE * 24576)

__global__ void __launch_bounds__(128, 2)
k_gemm_nt3(const h16* Ah, const h16* Al, int lda,
           const h16* Bh, const h16* Bl, int ldb,
           float* C, int ldc, int K)
{
    size_t m0 = (size_t)blockIdx.y * 128, n0 = (size_t)blockIdx.x * 128;
    gemm_tile<3, 0>(Ah + m0 * lda, Al + m0 * lda, lda,
                    Bh + n0 * ldb, Bl + n0 * ldb, ldb,
                    C + m0 * ldc + n0, nullptr, nullptr, ldc, K);
}

__global__ void __launch_bounds__(128, 2)
k_gemm_nt2(const h16* Ah, const h16* Al, int lda,
           const h16* Bh, int ldb,
           float* C, int ldc, int K)
{
    size_t m0 = (size_t)blockIdx.y * 128, n0 = (size_t)blockIdx.x * 128;
    gemm_tile<2, 0>(Ah + m0 * lda, Al + m0 * lda, lda,
                    Bh + n0 * ldb, nullptr, ldb,
                    C + m0 * ldc + n0, nullptr, nullptr, ldc, K);
}

__global__ void __launch_bounds__(128, 2)
k_attn_s()
{
    int h = blockIdx.z, r = blockIdx.y, cx = blockIdx.x;
    int cbase = (r - 8 > 0) ? (r - 8) : 0;
    int ct = cbase + cx;
    if (ct > r) return;
    size_t aoff = (size_t)r * 128 * (NHQ * DH) + (size_t)h * DH;
    size_t boff = (size_t)ct * 128 * (NKV * DH) + (size_t)(h / GROUPS) * DH;
    float* C = g_S + ((size_t)h * S_LEN + (size_t)r * 128) * BANDW + (size_t)cx * 128;
    gemm_tile<3, 0>(g_QH + aoff, g_QL + aoff, NHQ * DH,
                    g_KH + boff, g_KL + boff, NKV * DH,
                    C, nullptr, nullptr, BANDW, DH);
}

__global__ void __launch_bounds__(128, 2)
k_attn_pv()
{
    int h = blockIdx.z, r = blockIdx.y, nx = blockIdx.x;
    int c0 = ((r - 8 > 0) ? (r - 8) : 0) * 128;
    size_t aoff = ((size_t)h * S_LEN + (size_t)r * 128) * BANDW;
    size_t boff = ((size_t)(h / GROUPS) * DH + (size_t)nx * 128) * S_LEN + (size_t)c0;
    size_t coff = (size_t)r * 128 * (NHQ * DH) + (size_t)h * DH + (size_t)nx * 128;
    gemm_tile<3, 1>(g_PH + aoff, g_PL + aoff, BANDW,
                    g_VtH + boff, g_VtL + boff, S_LEN,
                    nullptr, g_AOH + coff, g_AOL + coff, NHQ * DH, BANDW);
}

// ---------------- fused split of all 5 inputs ----------------
// segment sizes in float4 units
#define N_HS 1835008   // 2048*3584/4
#define N_WQ 3670016   // 4096*3584/4
#define N_WK 1835008
#define N_WV 1835008
#define N_WO 3670016
#define N_SPLIT_TOTAL (N_HS + N_WQ + N_WK + N_WV + N_WO)

__global__ void __launch_bounds__(256)
k_split_all(const float* __restrict__ hs, const float* __restrict__ wq,
            const float* __restrict__ wk, const float* __restrict__ wv,
            const float* __restrict__ wo)
{
    int i = blockIdx.x * 256 + threadIdx.x;
    const float* src;
    h16 *hi, *lo;
    int j = i;
    if (j < N_HS)                 { src = hs; hi = g_hsH; lo = g_hsL; }
    else if ((j -= N_HS) < N_WQ)  { src = wq; hi = g_wqH; lo = g_wqL; }
    else if ((j -= N_WQ) < N_WK)  { src = wk; hi = g_wkH; lo = g_wkL; }
    else if ((j -= N_WK) < N_WV)  { src = wv; hi = g_wvH; lo = nullptr; }
    else                          { j -= N_WV; src = wo; hi = g_woH; lo = nullptr; }

    float4 v = ((const float4*)src)[j];
    h16 h0 = __float2half(v.x), h1 = __float2half(v.y);
    h16 h2 = __float2half(v.z), h3 = __float2half(v.w);
    __half2 H0; H0.x = h0; H0.y = h1;
    __half2 H1; H1.x = h2; H1.y = h3;
    ((__half2*)hi)[j * 2 + 0] = H0;
    ((__half2*)hi)[j * 2 + 1] = H1;
    if (lo) {
        __half2 L0, L1;
        L0.x = __float2half(v.x - __half2float(h0));
        L0.y = __float2half(v.y - __half2float(h1));
        L1.x = __float2half(v.z - __half2float(h2));
        L1.y = __float2half(v.w - __half2float(h3));
        ((__half2*)lo)[j * 2 + 0] = L0;
        ((__half2*)lo)[j * 2 + 1] = L1;
    }
}

// ---------------- RoPE + split ----------------
__global__ void __launch_bounds__(256)
k_rope_split(const float* __restrict__ cosb, const float* __restrict__ sinb)
{
    int idx = blockIdx.x * 256 + threadIdx.x;
    int d = idx & 127;
    int t = idx >> 7;
    int slot = t % (NHQ + NKV);
    int s = t / (NHQ + NKV);

    float c0 = cosb[s * DH + d],       s0 = sinb[s * DH + d];
    float c1 = cosb[s * DH + d + 128], s1 = sinb[s * DH + d + 128];

    if (slot < NHQ) {
        size_t b = (size_t)s * (NHQ * DH) + slot * DH + d;
        float x0 = g_Q[b], x1 = g_Q[b + 128];
        float y0 = x0 * c0 - x1 * s0;
        float y1 = x1 * c1 + x0 * s1;
        h16 h0 = __float2half(y0), h1 = __float2half(y1);
        g_QH[b] = h0;       g_QH[b + 128] = h1;
        g_QL[b] = __float2half(y0 - __half2float(h0));
        g_QL[b + 128] = __float2half(y1 - __half2float(h1));
    } else {
        size_t b = (size_t)s * (NKV * DH) + (slot - NHQ) * DH + d;
        float x0 = g_K[b], x1 = g_K[b + 128];
        float y0 = x0 * c0 - x1 * s0;
        float y1 = x1 * c1 + x0 * s1;
        h16 h0 = __float2half(y0), h1 = __float2half(y1);
        g_KH[b] = h0;       g_KH[b + 128] = h1;
        g_KL[b] = __float2half(y0 - __half2float(h0));
        g_KL[b + 128] = __float2half(y1 - __half2float(h1));
    }
}

// ---------------- V transpose + split ----------------
__global__ void __launch_bounds__(256)
k_vtrans()
{
    __shared__ float t[32][33];
    int bs = blockIdx.x * 32, bo = blockIdx.y * 32;
    int tx = threadIdx.x, ty = threadIdx.y;
#pragma unroll
    for (int j = 0; j < 32; j += 8)
        t[ty + j][tx] = g_V[(size_t)(bs + ty + j) * (NKV * DH) + bo + tx];
    __syncthreads();
#pragma unroll
    for (int j = 0; j < 32; j += 8) {
        float v = t[tx][ty + j];
        size_t o = (size_t)(bo + ty + j) * S_LEN + bs + tx;
        h16 h = __float2half(v);
        g_VtH[o] = h;
        g_VtL[o] = __float2half(v - __half2float(h));
    }
}

// ---------------- band softmax (fast-math) ----------------
__global__ void __launch_bounds__(256)
k_softmax()
{
    int row  = blockIdx.x * 8 + (threadIdx.x >> 5);
    int lane = threadIdx.x & 31;
    int h = row >> 11;
    int q = row & 2047;

    size_t base = ((size_t)h * S_LEN + q) * BANDW;
    const float* p = g_S + base;
    int r  = q >> 7;
    int c0 = ((r - 8 > 0) ? (r - 8) : 0) * 128;
    int kmin = (q - (WINDOW - 1) > 0) ? (q - (WINDOW - 1)) : 0;

    float v[36];
    float m = -1e30f;
#pragma unroll
    for (int i = 0; i < 36; ++i) {
        int j = lane + 32 * i;
        int k = c0 + j;
        float tt;
        if (k >= kmin && k <= q) {
            float x = p[j] * (SCALING / SOFTCAP);
            x = fminf(fmaxf(x, -15.0f), 15.0f);
            float e2 = __expf(2.0f * x);
            tt = SOFTCAP * ((e2 - 1.0f) / (e2 + 1.0f));
        } else {
            tt = -1e30f;
        }
        v[i] = tt;
        m = fmaxf(m, tt);
    }
#pragma unroll
    for (int o = 16; o > 0; o >>= 1)
        m = fmaxf(m, __shfl_xor_sync(0xFFFFFFFFu, m, o));

    float l = 0.0f;
#pragma unroll
    for (int i = 0; i < 36; ++i) {
        v[i] = __expf(v[i] - m);
        l += v[i];
    }
#pragma unroll
    for (int o = 16; o > 0; o >>= 1)
        l += __shfl_xor_sync(0xFFFFFFFFu, l, o);

    float inv = 1.0f / l;
#pragma unroll
    for (int i = 0; i < 36; ++i) {
        float pv = v[i] * inv;
        h16 hh = __float2half(pv);
        g_PH[base + lane + 32 * i] = hh;
        g_PL[base + lane + 32 * i] = __float2half(pv - __half2float(hh));
    }
}

// ---------------- launch ----------------
extern "C" void kernel_launch(void* const* d_in, const int* in_sizes, int n_in,
                              void* d_out, int out_size)
{
    const float* hs   = (const float*)d_in[0];
    const float* cosb = (const float*)d_in[1];
    const float* sinb = (const float*)d_in[2];
    const float* wq   = (const float*)d_in[3];
    const float* wk   = (const float*)d_in[4];
    const float* wv   = (const float*)d_in[5];
    const float* wo   = (const float*)d_in[6];
    float* out = (float*)d_out;

    void *pQ, *pK, *pV;
    void *phsH, *phsL, *pwqH, *pwqL, *pwkH, *pwkL, *pwvH, *pwoH, *pAOH, *pAOL;
    cudaGetSymbolAddress(&pQ, g_Q);   cudaGetSymbolAddress(&pK, g_K);
    cudaGetSymbolAddress(&pV, g_V);
    cudaGetSymbolAddress(&phsH, g_hsH); cudaGetSymbolAddress(&phsL, g_hsL);
    cudaGetSymbolAddress(&pwqH, g_wqH); cudaGetSymbolAddress(&pwqL, g_wqL);
    cudaGetSymbolAddress(&pwkH, g_wkH); cudaGetSymbolAddress(&pwkL, g_wkL);
    cudaGetSymbolAddress(&pwvH, g_wvH); cudaGetSymbolAddress(&pwoH, g_woH);
    cudaGetSymbolAddress(&pAOH, g_AOH); cudaGetSymbolAddress(&pAOL, g_AOL);

    cudaFuncSetAttribute(k_gemm_nt3, cudaFuncAttributeMaxDynamicSharedMemorySize, SMEM3);
    cudaFuncSetAttribute(k_gemm_nt2, cudaFuncAttributeMaxDynamicSharedMemorySize, SMEM2);
    cudaFuncSetAttribute(k_attn_s,   cudaFuncAttributeMaxDynamicSharedMemorySize, SMEM3);
    cudaFuncSetAttribute(k_attn_pv,  cudaFuncAttributeMaxDynamicSharedMemorySize, SMEM3);

    // fused split of all inputs
    k_split_all<<<N_SPLIT_TOTAL / 256, 256>>>(hs, wq, wk, wv, wo);

    // Q, K projections (3-product); V projection (2-product)
    k_gemm_nt3<<<dim3(NHQ * DH / 128, S_LEN / 128), 128, SMEM3>>>(
        (h16*)phsH, (h16*)phsL, HID, (h16*)pwqH, (h16*)pwqL, HID, (float*)pQ, NHQ * DH, HID);
    k_gemm_nt3<<<dim3(NKV * DH / 128, S_LEN / 128), 128, SMEM3>>>(
        (h16*)phsH, (h16*)phsL, HID, (h16*)pwkH, (h16*)pwkL, HID, (float*)pK, NKV * DH, HID);
    k_gemm_nt2<<<dim3(NKV * DH / 128, S_LEN / 128), 128, SMEM2>>>(
        (h16*)phsH, (h16*)phsL, HID, (h16*)pwvH, HID, (float*)pV, NKV * DH, HID);

    // RoPE + split, V transpose + split
    k_rope_split<<<(S_LEN * (NHQ + NKV) * 128) / 256, 256>>>(cosb, sinb);
    k_vtrans<<<dim3(S_LEN / 32, (NKV * DH) / 32), dim3(32, 8)>>>();

    // banded scores (3-product)
    k_attn_s<<<dim3(9, S_LEN / 128, NHQ), 128, SMEM3>>>();

    // softcap + mask + softmax -> split-fp16 P
    k_softmax<<<(NHQ * S_LEN) / 8, 256>>>();

    // PV (3-product) -> split-fp16 AO
    k_attn_pv<<<dim3(2, S_LEN / 128, NHQ), 128, SMEM3>>>();

    // output projection (2-product)
    k_gemm_nt2<<<dim3(HID / 128, S_LEN / 128), 128, SMEM2>>>(
        (h16*)pAOH, (h16*)pAOL, NHQ * DH, (h16*)pwoH, NHQ * DH, out, HID, NHQ * DH);
}

// round 13
// speedup vs baseline: 3.6565x; 1.2313x over previous
#include <cuda_runtime.h>
#include <cuda_fp16.h>
#include <math.h>
#include <stdint.h>

// ---------------- problem constants ----------------
#define S_LEN   2048
#define HID     3584
#define NHQ     16
#define NKV     8
#define DH      256
#define GROUPS  2
#define WINDOW  1024
#define BANDW   1152
#define SOFTCAP 50.0f
#define SCALING 0.0625f

typedef __half h16;

// ---------------- device scratch ----------------
__device__ float g_Q [(size_t)S_LEN * NHQ * DH];
__device__ float g_K [(size_t)S_LEN * NKV * DH];
__device__ float g_V [(size_t)S_LEN * NKV * DH];
__device__ float g_S [(size_t)NHQ * S_LEN * BANDW];

__device__ h16 g_hsH[(size_t)S_LEN * HID],      g_hsL[(size_t)S_LEN * HID];
__device__ h16 g_wqH[(size_t)NHQ * DH * HID];                    // hi only
__device__ h16 g_wkH[(size_t)NKV * DH * HID];                    // hi only
__device__ h16 g_wvH[(size_t)NKV * DH * HID];                    // hi only
__device__ h16 g_woH[(size_t)HID * NHQ * DH];                    // hi only
__device__ h16 g_QH [(size_t)S_LEN * NHQ * DH], g_QL [(size_t)S_LEN * NHQ * DH];
__device__ h16 g_KH [(size_t)S_LEN * NKV * DH], g_KL [(size_t)S_LEN * NKV * DH];
__device__ h16 g_VtH[(size_t)NKV * DH * S_LEN], g_VtL[(size_t)NKV * DH * S_LEN];
__device__ h16 g_PH [(size_t)NHQ * S_LEN * BANDW], g_PL[(size_t)NHQ * S_LEN * BANDW];
__device__ h16 g_AOH[(size_t)S_LEN * NHQ * DH], g_AOL[(size_t)S_LEN * NHQ * DH];

// ---------------- helpers ----------------
__device__ __forceinline__ uint32_t smem_u32(const void* p) {
    uint32_t a;
    asm("{ .reg .u64 t; cvta.to.shared.u64 t, %1; cvt.u32.u64 %0, t; }" : "=r"(a) : "l"(p));
    return a;
}
__device__ __forceinline__ void cp16(uint32_t saddr, const void* g) {
    asm volatile("cp.async.cg.shared.global [%0], [%1], 16;" :: "r"(saddr), "l"(g) : "memory");
}
#define CP_COMMIT() asm volatile("cp.async.commit_group;" ::: "memory")

#define LDSM4(r0, r1, r2, r3, addr) \
    asm volatile("ldmatrix.sync.aligned.m8n8.x4.shared.b16 {%0,%1,%2,%3}, [%4];" \
        : "=r"(r0), "=r"(r1), "=r"(r2), "=r"(r3) : "r"(addr))

__device__ __forceinline__ void mma32(float* c,
    uint32_t a0, uint32_t a1, uint32_t a2, uint32_t a3,
    uint32_t b0, uint32_t b1)
{
    asm volatile(
        "mma.sync.aligned.m16n8k16.row.col.f32.f16.f16.f32 "
        "{%0,%1,%2,%3}, {%4,%5,%6,%7}, {%8,%9}, {%0,%1,%2,%3};"
        : "+f"(c[0]), "+f"(c[1]), "+f"(c[2]), "+f"(c[3])
        : "r"(a0), "r"(a1), "r"(a2), "r"(a3), "r"(b0), "r"(b1));
}

// ---------------- stage layout ----------------
#define NSTAGE 3

template <int NPROD>
__device__ __forceinline__ void stage_cp(
    const h16* __restrict__ Ah, const h16* __restrict__ Al, int lda,
    const h16* __restrict__ Bh, const h16* __restrict__ Bl, int ldb,
    int k0, uint32_t smb, int buf, int tid)
{
    const int STG = (NPROD == 3) ? 32768 : 24576;
    uint32_t sb = smb + buf * STG;
#pragma unroll
    for (int i = 0; i < 4; ++i) {
        int si  = tid + i * 128;
        int row = si >> 2;
        int seg = si & 3;
        uint32_t soff = row * 64 + ((seg ^ ((row >> 1) & 3)) << 4);
        size_t goA = (size_t)row * lda + k0 + seg * 8;
        size_t goB = (size_t)row * ldb + k0 + seg * 8;
        cp16(sb +     0 + soff, Ah + goA);
        cp16(sb +  8192 + soff, Al + goA);
        cp16(sb + 16384 + soff, Bh + goB);
        if (NPROD == 3) cp16(sb + 24576 + soff, Bl + goB);
    }
}

// ---------------- 128x128 NT GEMM tile, fp16 split, fp32 accum ----------------
// 128 threads (4 warps, 2x2, warp tile 64x64). K % 32 == 0.
// NPROD=3: Ah*Bh + Ah*Bl + Al*Bh.  NPROD=2: Ah*Bh + Al*Bh.
// EPI=0: fp32 C.  EPI=1: split-fp16 (Ch, Cl).
template <int NPROD, int EPI>
__device__ void gemm_tile(
    const h16* __restrict__ Ah, const h16* __restrict__ Al, int lda,
    const h16* __restrict__ Bh, const h16* __restrict__ Bl, int ldb,
    float* __restrict__ C, h16* __restrict__ Ch, h16* __restrict__ Cl,
    int ldc, int K)
{
    const int STG = (NPROD == 3) ? 32768 : 24576;
    extern __shared__ char smem[];
    const uint32_t smb = smem_u32(smem);
    const int tid  = threadIdx.x;
    const int lane = tid & 31;
    const int wid  = tid >> 5;
    const int wm   = wid >> 1;
    const int wn   = wid & 1;
    const int la   = lane & 7;
    const int grp  = lane >> 3;

    float acc[4][8][4];
#pragma unroll
    for (int mi = 0; mi < 4; ++mi)
#pragma unroll
        for (int ni = 0; ni < 8; ++ni)
#pragma unroll
            for (int q = 0; q < 4; ++q) acc[mi][ni][q] = 0.0f;

    uint32_t offA[4], swA[4];
#pragma unroll
    for (int mi = 0; mi < 4; ++mi) {
        int r = wm * 64 + mi * 16 + la + (grp & 1) * 8;
        offA[mi] = r * 64;
        swA[mi]  = (r >> 1) & 3;
    }
    const int segselA = grp >> 1;
    uint32_t offB[4], swB[4];
#pragma unroll
    for (int p = 0; p < 4; ++p) {
        int r = wn * 64 + p * 16 + la + (grp >> 1) * 8;
        offB[p] = r * 64;
        swB[p]  = (r >> 1) & 3;
    }
    const int segselB = grp & 1;

    const int nK = K >> 5;
    stage_cp<NPROD>(Ah, Al, lda, Bh, Bl, ldb, 0, smb, 0, tid);
    CP_COMMIT();
    stage_cp<NPROD>(Ah, Al, lda, Bh, Bl, ldb, 32, smb, 1, tid);
    CP_COMMIT();

    for (int ki = 0; ki < nK; ++ki) {
        asm volatile("cp.async.wait_group 1;" ::: "memory");
        __syncthreads();
        if (ki + 2 < nK)
            stage_cp<NPROD>(Ah, Al, lda, Bh, Bl, ldb, (ki + 2) << 5, smb, (ki + 2) % NSTAGE, tid);
        CP_COMMIT();

        const uint32_t sA  = smb + (ki % NSTAGE) * STG;
        const uint32_t sAl = sA + 8192;
        const uint32_t sB  = sA + 16384;
        const uint32_t sBl = sA + 24576;

#pragma unroll
        for (int ks = 0; ks < 2; ++ks) {
            uint32_t ah[4][4], al[4][4];
#pragma unroll
            for (int mi = 0; mi < 4; ++mi) {
                uint32_t aoff = offA[mi] + ((((uint32_t)(ks * 2 + segselA) ^ swA[mi])) << 4);
                LDSM4(ah[mi][0], ah[mi][1], ah[mi][2], ah[mi][3], sA + aoff);
                LDSM4(al[mi][0], al[mi][1], al[mi][2], al[mi][3], sAl + aoff);
            }
#pragma unroll
            for (int p = 0; p < 4; ++p) {
                uint32_t boff = offB[p] + ((((uint32_t)(ks * 2 + segselB) ^ swB[p])) << 4);
                uint32_t bh0, bh1, bh2, bh3;
                LDSM4(bh0, bh1, bh2, bh3, sB + boff);
                uint32_t bl0, bl1, bl2, bl3;
                if (NPROD == 3) { LDSM4(bl0, bl1, bl2, bl3, sBl + boff); }
#pragma unroll
                for (int mi = 0; mi < 4; ++mi) {
                    float* c0 = acc[mi][2 * p];
                    float* c1 = acc[mi][2 * p + 1];
                    mma32(c0, ah[mi][0], ah[mi][1], ah[mi][2], ah[mi][3], bh0, bh1);
                    mma32(c0, al[mi][0], al[mi][1], al[mi][2], al[mi][3], bh0, bh1);
                    mma32(c1, ah[mi][0], ah[mi][1], ah[mi][2], ah[mi][3], bh2, bh3);
                    mma32(c1, al[mi][0], al[mi][1], al[mi][2], al[mi][3], bh2, bh3);
                    if (NPROD == 3) {
                        mma32(c0, ah[mi][0], ah[mi][1], ah[mi][2], ah[mi][3], bl0, bl1);
                        mma32(c1, ah[mi][0], ah[mi][1], ah[mi][2], ah[mi][3], bl2, bl3);
                    }
                }
            }
        }
    }

    const int g  = lane >> 2;
    const int t4 = lane & 3;
#pragma unroll
    for (int mi = 0; mi < 4; ++mi) {
        int R0 = wm * 64 + mi * 16 + g;
        int R1 = R0 + 8;
#pragma unroll
        for (int ni = 0; ni < 8; ++ni) {
            int col = wn * 64 + ni * 8 + t4 * 2;
            float* a = acc[mi][ni];
            if (EPI == 0) {
                *(float2*)(C + (size_t)R0 * ldc + col) = make_float2(a[0], a[1]);
                *(float2*)(C + (size_t)R1 * ldc + col) = make_float2(a[2], a[3]);
            } else {
                h16 h0 = __float2half(a[0]), h1 = __float2half(a[1]);
                h16 h2 = __float2half(a[2]), h3 = __float2half(a[3]);
                __half2 H0; H0.x = h0; H0.y = h1;
                __half2 H1; H1.x = h2; H1.y = h3;
                __half2 L0, L1;
                L0.x = __float2half(a[0] - __half2float(h0));
                L0.y = __float2half(a[1] - __half2float(h1));
                L1.x = __float2half(a[2] - __half2float(h2));
                L1.y = __float2half(a[3] - __half2float(h3));
                *(__half2*)(Ch + (size_t)R0 * ldc + col) = H0;
                *(__half2*)(Ch + (size_t)R1 * ldc + col) = H1;
                *(__half2*)(Cl + (size_t)R0 * ldc + col) = L0;
                *(__half2*)(Cl + (size_t)R1 * ldc + col) = L1;
            }
        }
    }
}

// ---------------- GEMM wrapper kernels ----------------
#define SMEM3 (NSTAGE * 32768)
#define SMEM2 (NSTAGE * 24576)

// Fused QKV projection: grid (64, 16). bx 0..31 -> Q, 32..47 -> K, 48..63 -> V.
__global__ void __launch_bounds__(128, 2)
k_gemm_qkv()
{
    int bx = blockIdx.x, by = blockIdx.y;
    size_t m0 = (size_t)by * 128;
    const h16* Bh;
    float* C;
    int ldc;
    if (bx < 32) {
        Bh  = g_wqH + (size_t)bx * 128 * HID;
        C   = g_Q + m0 * (NHQ * DH) + (size_t)bx * 128;
        ldc = NHQ * DH;
    } else if (bx < 48) {
        int b = bx - 32;
        Bh  = g_wkH + (size_t)b * 128 * HID;
        C   = g_K + m0 * (NKV * DH) + (size_t)b * 128;
        ldc = NKV * DH;
    } else {
        int b = bx - 48;
        Bh  = g_wvH + (size_t)b * 128 * HID;
        C   = g_V + m0 * (NKV * DH) + (size_t)b * 128;
        ldc = NKV * DH;
    }
    gemm_tile<2, 0>(g_hsH + m0 * HID, g_hsL + m0 * HID, HID,
                    Bh, nullptr, HID, C, nullptr, nullptr, ldc, HID);
}

__global__ void __launch_bounds__(128, 2)
k_gemm_nt2(const h16* Ah, const h16* Al, int lda,
           const h16* Bh, int ldb,
           float* C, int ldc, int K)
{
    size_t m0 = (size_t)blockIdx.y * 128, n0 = (size_t)blockIdx.x * 128;
    gemm_tile<2, 0>(Ah + m0 * lda, Al + m0 * lda, lda,
                    Bh + n0 * ldb, nullptr, ldb,
                    C + m0 * ldc + n0, nullptr, nullptr, ldc, K);
}

__global__ void __launch_bounds__(128, 2)
k_attn_s()
{
    int h = blockIdx.z, r = blockIdx.y, cx = blockIdx.x;
    int cbase = (r - 8 > 0) ? (r - 8) : 0;
    int ct = cbase + cx;
    if (ct > r) return;
    size_t aoff = (size_t)r * 128 * (NHQ * DH) + (size_t)h * DH;
    size_t boff = (size_t)ct * 128 * (NKV * DH) + (size_t)(h / GROUPS) * DH;
    float* C = g_S + ((size_t)h * S_LEN + (size_t)r * 128) * BANDW + (size_t)cx * 128;
    gemm_tile<3, 0>(g_QH + aoff, g_QL + aoff, NHQ * DH,
                    g_KH + boff, g_KL + boff, NKV * DH,
                    C, nullptr, nullptr, BANDW, DH);
}

__global__ void __launch_bounds__(128, 2)
k_attn_pv()
{
    int h = blockIdx.z, r = blockIdx.y, nx = blockIdx.x;
    int c0 = ((r - 8 > 0) ? (r - 8) : 0) * 128;
    size_t aoff = ((size_t)h * S_LEN + (size_t)r * 128) * BANDW;
    size_t boff = ((size_t)(h / GROUPS) * DH + (size_t)nx * 128) * S_LEN + (size_t)c0;
    size_t coff = (size_t)r * 128 * (NHQ * DH) + (size_t)h * DH + (size_t)nx * 128;
    gemm_tile<3, 1>(g_PH + aoff, g_PL + aoff, BANDW,
                    g_VtH + boff, g_VtL + boff, S_LEN,
                    nullptr, g_AOH + coff, g_AOL + coff, NHQ * DH, BANDW);
}

// ---------------- fused split of all 5 inputs ----------------
#define N_HS 1835008   // 2048*3584/4
#define N_WQ 3670016   // 4096*3584/4
#define N_WK 1835008
#define N_WV 1835008
#define N_WO 3670016
#define N_SPLIT_TOTAL (N_HS + N_WQ + N_WK + N_WV + N_WO)

__global__ void __launch_bounds__(256)
k_split_all(const float* __restrict__ hs, const float* __restrict__ wq,
            const float* __restrict__ wk, const float* __restrict__ wv,
            const float* __restrict__ wo)
{
    int i = blockIdx.x * 256 + threadIdx.x;
    const float* src;
    h16 *hi, *lo;
    int j = i;
    if (j < N_HS)                 { src = hs; hi = g_hsH; lo = g_hsL; }
    else if ((j -= N_HS) < N_WQ)  { src = wq; hi = g_wqH; lo = nullptr; }
    else if ((j -= N_WQ) < N_WK)  { src = wk; hi = g_wkH; lo = nullptr; }
    else if ((j -= N_WK) < N_WV)  { src = wv; hi = g_wvH; lo = nullptr; }
    else                          { j -= N_WV; src = wo; hi = g_woH; lo = nullptr; }

    float4 v = ((const float4*)src)[j];
    h16 h0 = __float2half(v.x), h1 = __float2half(v.y);
    h16 h2 = __float2half(v.z), h3 = __float2half(v.w);
    __half2 H0; H0.x = h0; H0.y = h1;
    __half2 H1; H1.x = h2; H1.y = h3;
    ((__half2*)hi)[j * 2 + 0] = H0;
    ((__half2*)hi)[j * 2 + 1] = H1;
    if (lo) {
        __half2 L0, L1;
        L0.x = __float2half(v.x - __half2float(h0));
        L0.y = __float2half(v.y - __half2float(h1));
        L1.x = __float2half(v.z - __half2float(h2));
        L1.y = __float2half(v.w - __half2float(h3));
        ((__half2*)lo)[j * 2 + 0] = L0;
        ((__half2*)lo)[j * 2 + 1] = L1;
    }
}

// ---------------- RoPE + split ----------------
__global__ void __launch_bounds__(256)
k_rope_split(const float* __restrict__ cosb, const float* __restrict__ sinb)
{
    int idx = blockIdx.x * 256 + threadIdx.x;
    int d = idx & 127;
    int t = idx >> 7;
    int slot = t % (NHQ + NKV);
    int s = t / (NHQ + NKV);

    float c0 = cosb[s * DH + d],       s0 = sinb[s * DH + d];
    float c1 = cosb[s * DH + d + 128], s1 = sinb[s * DH + d + 128];

    if (slot < NHQ) {
        size_t b = (size_t)s * (NHQ * DH) + slot * DH + d;
        float x0 = g_Q[b], x1 = g_Q[b + 128];
        float y0 = x0 * c0 - x1 * s0;
        float y1 = x1 * c1 + x0 * s1;
        h16 h0 = __float2half(y0), h1 = __float2half(y1);
        g_QH[b] = h0;       g_QH[b + 128] = h1;
        g_QL[b] = __float2half(y0 - __half2float(h0));
        g_QL[b + 128] = __float2half(y1 - __half2float(h1));
    } else {
        size_t b = (size_t)s * (NKV * DH) + (slot - NHQ) * DH + d;
        float x0 = g_K[b], x1 = g_K[b + 128];
        float y0 = x0 * c0 - x1 * s0;
        float y1 = x1 * c1 + x0 * s1;
        h16 h0 = __float2half(y0), h1 = __float2half(y1);
        g_KH[b] = h0;       g_KH[b + 128] = h1;
        g_KL[b] = __float2half(y0 - __half2float(h0));
        g_KL[b + 128] = __float2half(y1 - __half2float(h1));
    }
}

// ---------------- V transpose + split ----------------
__global__ void __launch_bounds__(256)
k_vtrans()
{
    __shared__ float t[32][33];
    int bs = blockIdx.x * 32, bo = blockIdx.y * 32;
    int tx = threadIdx.x, ty = threadIdx.y;
#pragma unroll
    for (int j = 0; j < 32; j += 8)
        t[ty + j][tx] = g_V[(size_t)(bs + ty + j) * (NKV * DH) + bo + tx];
    __syncthreads();
#pragma unroll
    for (int j = 0; j < 32; j += 8) {
        float v = t[tx][ty + j];
        size_t o = (size_t)(bo + ty + j) * S_LEN + bs + tx;
        h16 h = __float2half(v);
        g_VtH[o] = h;
        g_VtL[o] = __float2half(v - __half2float(h));
    }
}

// ---------------- band softmax (fast-math) ----------------
__global__ void __launch_bounds__(256)
k_softmax()
{
    int row  = blockIdx.x * 8 + (threadIdx.x >> 5);
    int lane = threadIdx.x & 31;
    int h = row >> 11;
    int q = row & 2047;

    size_t base = ((size_t)h * S_LEN + q) * BANDW;
    const float* p = g_S + base;
    int r  = q >> 7;
    int c0 = ((r - 8 > 0) ? (r - 8) : 0) * 128;
    int kmin = (q - (WINDOW - 1) > 0) ? (q - (WINDOW - 1)) : 0;

    float v[36];
    float m = -1e30f;
#pragma unroll
    for (int i = 0; i < 36; ++i) {
        int j = lane + 32 * i;
        int k = c0 + j;
        float tt;
        if (k >= kmin && k <= q) {
            float x = p[j] * (SCALING / SOFTCAP);
            x = fminf(fmaxf(x, -15.0f), 15.0f);
            float e2 = __expf(2.0f * x);
            tt = SOFTCAP * ((e2 - 1.0f) / (e2 + 1.0f));
        } else {
            tt = -1e30f;
        }
        v[i] = tt;
        m = fmaxf(m, tt);
    }
#pragma unroll
    for (int o = 16; o > 0; o >>= 1)
        m = fmaxf(m, __shfl_xor_sync(0xFFFFFFFFu, m, o));

    float l = 0.0f;
#pragma unroll
    for (int i = 0; i < 36; ++i) {
        v[i] = __expf(v[i] - m);
        l += v[i];
    }
#pragma unroll
    for (int o = 16; o > 0; o >>= 1)
        l += __shfl_xor_sync(0xFFFFFFFFu, l, o);

    float inv = 1.0f / l;
#pragma unroll
    for (int i = 0; i < 36; ++i) {
        float pv = v[i] * inv;
        h16 hh = __float2half(pv);
        g_PH[base + lane + 32 * i] = hh;
        g_PL[base + lane + 32 * i] = __float2half(pv - __half2float(hh));
    }
}

// ---------------- launch ----------------
extern "C" void kernel_launch(void* const* d_in, const int* in_sizes, int n_in,
                              void* d_out, int out_size)
{
    const float* hs   = (const float*)d_in[0];
    const float* cosb = (const float*)d_in[1];
    const float* sinb = (const float*)d_in[2];
    const float* wq   = (const float*)d_in[3];
    const float* wk   = (const float*)d_in[4];
    const float* wv   = (const float*)d_in[5];
    const float* wo   = (const float*)d_in[6];
    float* out = (float*)d_out;

    void *pwoH, *pAOH, *pAOL;
    cudaGetSymbolAddress(&pwoH, g_woH);
    cudaGetSymbolAddress(&pAOH, g_AOH); cudaGetSymbolAddress(&pAOL, g_AOL);

    cudaFuncSetAttribute(k_gemm_qkv, cudaFuncAttributeMaxDynamicSharedMemorySize, SMEM2);
    cudaFuncSetAttribute(k_gemm_nt2, cudaFuncAttributeMaxDynamicSharedMemorySize, SMEM2);
    cudaFuncSetAttribute(k_attn_s,   cudaFuncAttributeMaxDynamicSharedMemorySize, SMEM3);
    cudaFuncSetAttribute(k_attn_pv,  cudaFuncAttributeMaxDynamicSharedMemorySize, SMEM3);

    // fused split of all inputs (hs gets lo; weights hi-only)
    k_split_all<<<N_SPLIT_TOTAL / 256, 256>>>(hs, wq, wk, wv, wo);

    // fused QKV projections (2-product)
    k_gemm_qkv<<<dim3(64, S_LEN / 128), 128, SMEM2>>>();

    // RoPE + split, V transpose + split
    k_rope_split<<<(S_LEN * (NHQ + NKV) * 128) / 256, 256>>>(cosb, sinb);
    k_vtrans<<<dim3(S_LEN / 32, (NKV * DH) / 32), dim3(32, 8)>>>();

    // banded scores (3-product)
    k_attn_s<<<dim3(9, S_LEN / 128, NHQ), 128, SMEM3>>>();

    // softcap + mask + softmax -> split-fp16 P
    k_softmax<<<(NHQ * S_LEN) / 8, 256>>>();

    // PV (3-product) -> split-fp16 AO
    k_attn_pv<<<dim3(2, S_LEN / 128, NHQ), 128, SMEM3>>>();

    // output projection (2-product)
    k_gemm_nt2<<<dim3(HID / 128, S_LEN / 128), 128, SMEM2>>>(
        (h16*)pAOH, (h16*)pAOL, NHQ * DH, (h16*)pwoH, NHQ * DH, out, HID, NHQ * DH);
}

// round 14
// speedup vs baseline: 4.2336x; 1.1578x over previous
#include <cuda_runtime.h>
#include <cuda_fp16.h>
#include <math.h>
#include <stdint.h>

// ---------------- problem constants ----------------
#define S_LEN   2048
#define HID     3584
#define NHQ     16
#define NKV     8
#define DH      256
#define GROUPS  2
#define WINDOW  1024
#define BANDW   1152
#define SOFTCAP 50.0f
#define SCALING 0.0625f

typedef __half h16;

// ---------------- device scratch ----------------
__device__ float g_Q [(size_t)S_LEN * NHQ * DH];
__device__ float g_K [(size_t)S_LEN * NKV * DH];
__device__ float g_V [(size_t)S_LEN * NKV * DH];
__device__ float g_S [(size_t)NHQ * S_LEN * BANDW];

__device__ h16 g_hsH[(size_t)S_LEN * HID],      g_hsL[(size_t)S_LEN * HID];
__device__ h16 g_wqH[(size_t)NHQ * DH * HID];
__device__ h16 g_wkH[(size_t)NKV * DH * HID];
__device__ h16 g_wvH[(size_t)NKV * DH * HID];
__device__ h16 g_woH[(size_t)HID * NHQ * DH];
__device__ h16 g_QH [(size_t)S_LEN * NHQ * DH], g_QL [(size_t)S_LEN * NHQ * DH];
__device__ h16 g_KH [(size_t)S_LEN * NKV * DH];                 // hi only
__device__ h16 g_VtH[(size_t)NKV * DH * S_LEN];                 // hi only
__device__ h16 g_PH [(size_t)NHQ * S_LEN * BANDW], g_PL[(size_t)NHQ * S_LEN * BANDW];
__device__ h16 g_AOH[(size_t)S_LEN * NHQ * DH];                 // hi only

// ---------------- helpers ----------------
__device__ __forceinline__ uint32_t smem_u32(const void* p) {
    uint32_t a;
    asm("{ .reg .u64 t; cvta.to.shared.u64 t, %1; cvt.u32.u64 %0, t; }" : "=r"(a) : "l"(p));
    return a;
}
__device__ __forceinline__ void cp16(uint32_t saddr, const void* g) {
    asm volatile("cp.async.cg.shared.global [%0], [%1], 16;" :: "r"(saddr), "l"(g) : "memory");
}
#define CP_COMMIT() asm volatile("cp.async.commit_group;" ::: "memory")

#define LDSM4(r0, r1, r2, r3, addr) \
    asm volatile("ldmatrix.sync.aligned.m8n8.x4.shared.b16 {%0,%1,%2,%3}, [%4];" \
        : "=r"(r0), "=r"(r1), "=r"(r2), "=r"(r3) : "r"(addr))

__device__ __forceinline__ void mma32(float* c,
    uint32_t a0, uint32_t a1, uint32_t a2, uint32_t a3,
    uint32_t b0, uint32_t b1)
{
    asm volatile(
        "mma.sync.aligned.m16n8k16.row.col.f32.f16.f16.f32 "
        "{%0,%1,%2,%3}, {%4,%5,%6,%7}, {%8,%9}, {%0,%1,%2,%3};"
        : "+f"(c[0]), "+f"(c[1]), "+f"(c[2]), "+f"(c[3])
        : "r"(a0), "r"(a1), "r"(a2), "r"(a3), "r"(b0), "r"(b1));
}

// ---------------- stage layout ----------------
// NPROD==3 (32 KB): Ah | Al | Bh | Bl   (8 KB each)
// NPROD==2 (24 KB): Ah | Al | Bh
// NPROD==1 (16 KB): Ah | Bh
#define NSTAGE 3

template <int NPROD>
__device__ __forceinline__ void stage_cp(
    const h16* __restrict__ Ah, const h16* __restrict__ Al, int lda,
    const h16* __restrict__ Bh, const h16* __restrict__ Bl, int ldb,
    int k0, uint32_t smb, int buf, int tid)
{
    const int STG = (NPROD == 3) ? 32768 : (NPROD == 2) ? 24576 : 16384;
    const uint32_t OBH = (NPROD >= 2) ? 16384u : 8192u;
    uint32_t sb = smb + buf * STG;
#pragma unroll
    for (int i = 0; i < 4; ++i) {
        int si  = tid + i * 128;
        int row = si >> 2;
        int seg = si & 3;
        uint32_t soff = row * 64 + ((seg ^ ((row >> 1) & 3)) << 4);
        size_t goA = (size_t)row * lda + k0 + seg * 8;
        size_t goB = (size_t)row * ldb + k0 + seg * 8;
        cp16(sb + soff, Ah + goA);
        if (NPROD >= 2) cp16(sb + 8192 + soff, Al + goA);
        cp16(sb + OBH + soff, Bh + goB);
        if (NPROD == 3) cp16(sb + 24576 + soff, Bl + goB);
    }
}

// ---------------- 128x128 NT GEMM tile, fp16 split, fp32 accum ----------------
// 128 threads (4 warps, 2x2, warp tile 64x64). K % 32 == 0.
// NPROD=3: Ah*Bh + Al*Bh + Ah*Bl.  NPROD=2: Ah*Bh + Al*Bh.  NPROD=1: Ah*Bh.
// EPI=0: fp32 C.  EPI=1: split-fp16 (Ch, Cl).  EPI=2: fp16 hi only (Ch).
template <int NPROD, int EPI>
__device__ void gemm_tile(
    const h16* __restrict__ Ah, const h16* __restrict__ Al, int lda,
    const h16* __restrict__ Bh, const h16* __restrict__ Bl, int ldb,
    float* __restrict__ C, h16* __restrict__ Ch, h16* __restrict__ Cl,
    int ldc, int K)
{
    const int STG = (NPROD == 3) ? 32768 : (NPROD == 2) ? 24576 : 16384;
    const uint32_t OBH = (NPROD >= 2) ? 16384u : 8192u;
    extern __shared__ char smem[];
    const uint32_t smb = smem_u32(smem);
    const int tid  = threadIdx.x;
    const int lane = tid & 31;
    const int wid  = tid >> 5;
    const int wm   = wid >> 1;
    const int wn   = wid & 1;
    const int la   = lane & 7;
    const int grp  = lane >> 3;

    float acc[4][8][4];
#pragma unroll
    for (int mi = 0; mi < 4; ++mi)
#pragma unroll
        for (int ni = 0; ni < 8; ++ni)
#pragma unroll
            for (int q = 0; q < 4; ++q) acc[mi][ni][q] = 0.0f;

    uint32_t offA[4], swA[4];
#pragma unroll
    for (int mi = 0; mi < 4; ++mi) {
        int r = wm * 64 + mi * 16 + la + (grp & 1) * 8;
        offA[mi] = r * 64;
        swA[mi]  = (r >> 1) & 3;
    }
    const int segselA = grp >> 1;
    uint32_t offB[4], swB[4];
#pragma unroll
    for (int p = 0; p < 4; ++p) {
        int r = wn * 64 + p * 16 + la + (grp >> 1) * 8;
        offB[p] = r * 64;
        swB[p]  = (r >> 1) & 3;
    }
    const int segselB = grp & 1;

    const int nK = K >> 5;
    stage_cp<NPROD>(Ah, Al, lda, Bh, Bl, ldb, 0, smb, 0, tid);
    CP_COMMIT();
    stage_cp<NPROD>(Ah, Al, lda, Bh, Bl, ldb, 32, smb, 1, tid);
    CP_COMMIT();

    for (int ki = 0; ki < nK; ++ki) {
        asm volatile("cp.async.wait_group 1;" ::: "memory");
        __syncthreads();
        if (ki + 2 < nK)
            stage_cp<NPROD>(Ah, Al, lda, Bh, Bl, ldb, (ki + 2) << 5, smb, (ki + 2) % NSTAGE, tid);
        CP_COMMIT();

        const uint32_t sA  = smb + (ki % NSTAGE) * STG;
        const uint32_t sAl = sA + 8192;
        const uint32_t sB  = sA + OBH;
        const uint32_t sBl = sA + 24576;

#pragma unroll
        for (int ks = 0; ks < 2; ++ks) {
            uint32_t ah[4][4], al[4][4];
#pragma unroll
            for (int mi = 0; mi < 4; ++mi) {
                uint32_t aoff = offA[mi] + ((((uint32_t)(ks * 2 + segselA) ^ swA[mi])) << 4);
                LDSM4(ah[mi][0], ah[mi][1], ah[mi][2], ah[mi][3], sA + aoff);
                if (NPROD >= 2) { LDSM4(al[mi][0], al[mi][1], al[mi][2], al[mi][3], sAl + aoff); }
            }
#pragma unroll
            for (int p = 0; p < 4; ++p) {
                uint32_t boff = offB[p] + ((((uint32_t)(ks * 2 + segselB) ^ swB[p])) << 4);
                uint32_t bh0, bh1, bh2, bh3;
                LDSM4(bh0, bh1, bh2, bh3, sB + boff);
                uint32_t bl0, bl1, bl2, bl3;
                if (NPROD == 3) { LDSM4(bl0, bl1, bl2, bl3, sBl + boff); }
#pragma unroll
                for (int mi = 0; mi < 4; ++mi) {
                    float* c0 = acc[mi][2 * p];
                    float* c1 = acc[mi][2 * p + 1];
                    mma32(c0, ah[mi][0], ah[mi][1], ah[mi][2], ah[mi][3], bh0, bh1);
                    mma32(c1, ah[mi][0], ah[mi][1], ah[mi][2], ah[mi][3], bh2, bh3);
                    if (NPROD >= 2) {
                        mma32(c0, al[mi][0], al[mi][1], al[mi][2], al[mi][3], bh0, bh1);
                        mma32(c1, al[mi][0], al[mi][1], al[mi][2], al[mi][3], bh2, bh3);
                    }
                    if (NPROD == 3) {
                        mma32(c0, ah[mi][0], ah[mi][1], ah[mi][2], ah[mi][3], bl0, bl1);
                        mma32(c1, ah[mi][0], ah[mi][1], ah[mi][2], ah[mi][3], bl2, bl3);
                    }
                }
            }
        }
    }

    const int g  = lane >> 2;
    const int t4 = lane & 3;
#pragma unroll
    for (int mi = 0; mi < 4; ++mi) {
        int R0 = wm * 64 + mi * 16 + g;
        int R1 = R0 + 8;
#pragma unroll
        for (int ni = 0; ni < 8; ++ni) {
            int col = wn * 64 + ni * 8 + t4 * 2;
            float* a = acc[mi][ni];
            if (EPI == 0) {
                *(float2*)(C + (size_t)R0 * ldc + col) = make_float2(a[0], a[1]);
                *(float2*)(C + (size_t)R1 * ldc + col) = make_float2(a[2], a[3]);
            } else {
                h16 h0 = __float2half(a[0]), h1 = __float2half(a[1]);
                h16 h2 = __float2half(a[2]), h3 = __float2half(a[3]);
                __half2 H0; H0.x = h0; H0.y = h1;
                __half2 H1; H1.x = h2; H1.y = h3;
                *(__half2*)(Ch + (size_t)R0 * ldc + col) = H0;
                *(__half2*)(Ch + (size_t)R1 * ldc + col) = H1;
                if (EPI == 1) {
                    __half2 L0, L1;
                    L0.x = __float2half(a[0] - __half2float(h0));
                    L0.y = __float2half(a[1] - __half2float(h1));
                    L1.x = __float2half(a[2] - __half2float(h2));
                    L1.y = __float2half(a[3] - __half2float(h3));
                    *(__half2*)(Cl + (size_t)R0 * ldc + col) = L0;
                    *(__half2*)(Cl + (size_t)R1 * ldc + col) = L1;
                }
            }
        }
    }
}

// ---------------- GEMM wrapper kernels ----------------
#define SMEM3 (NSTAGE * 32768)
#define SMEM2 (NSTAGE * 24576)
#define SMEM1 (NSTAGE * 16384)

// Fused QKV projection: grid (64, 16). bx 0..31 -> Q, 32..47 -> K, 48..63 -> V.
__global__ void __launch_bounds__(128, 2)
k_gemm_qkv()
{
    int bx = blockIdx.x, by = blockIdx.y;
    size_t m0 = (size_t)by * 128;
    const h16* Bh;
    float* C;
    int ldc;
    if (bx < 32) {
        Bh  = g_wqH + (size_t)bx * 128 * HID;
        C   = g_Q + m0 * (NHQ * DH) + (size_t)bx * 128;
        ldc = NHQ * DH;
    } else if (bx < 48) {
        int b = bx - 32;
        Bh  = g_wkH + (size_t)b * 128 * HID;
        C   = g_K + m0 * (NKV * DH) + (size_t)b * 128;
        ldc = NKV * DH;
    } else {
        int b = bx - 48;
        Bh  = g_wvH + (size_t)b * 128 * HID;
        C   = g_V + m0 * (NKV * DH) + (size_t)b * 128;
        ldc = NKV * DH;
    }
    gemm_tile<2, 0>(g_hsH + m0 * HID, g_hsL + m0 * HID, HID,
                    Bh, nullptr, HID, C, nullptr, nullptr, ldc, HID);
}

// O projection: 1-product (AO hi x wo hi)
__global__ void __launch_bounds__(128, 2)
k_gemm_o(float* __restrict__ out)
{
    size_t m0 = (size_t)blockIdx.y * 128, n0 = (size_t)blockIdx.x * 128;
    gemm_tile<1, 0>(g_AOH + m0 * (NHQ * DH), nullptr, NHQ * DH,
                    g_woH + n0 * (NHQ * DH), nullptr, NHQ * DH,
                    out + m0 * HID + n0, nullptr, nullptr, HID, NHQ * DH);
}

// banded scores: 2-product (Q split x K hi)
__global__ void __launch_bounds__(128, 2)
k_attn_s()
{
    int h = blockIdx.z, r = blockIdx.y, cx = blockIdx.x;
    int cbase = (r - 8 > 0) ? (r - 8) : 0;
    int ct = cbase + cx;
    if (ct > r) return;
    size_t aoff = (size_t)r * 128 * (NHQ * DH) + (size_t)h * DH;
    size_t boff = (size_t)ct * 128 * (NKV * DH) + (size_t)(h / GROUPS) * DH;
    float* C = g_S + ((size_t)h * S_LEN + (size_t)r * 128) * BANDW + (size_t)cx * 128;
    gemm_tile<2, 0>(g_QH + aoff, g_QL + aoff, NHQ * DH,
                    g_KH + boff, nullptr, NKV * DH,
                    C, nullptr, nullptr, BANDW, DH);
}

// PV: 2-product (P split x Vt hi) -> AO hi only
__global__ void __launch_bounds__(128, 2)
k_attn_pv()
{
    int h = blockIdx.z, r = blockIdx.y, nx = blockIdx.x;
    int c0 = ((r - 8 > 0) ? (r - 8) : 0) * 128;
    size_t aoff = ((size_t)h * S_LEN + (size_t)r * 128) * BANDW;
    size_t boff = ((size_t)(h / GROUPS) * DH + (size_t)nx * 128) * S_LEN + (size_t)c0;
    size_t coff = (size_t)r * 128 * (NHQ * DH) + (size_t)h * DH + (size_t)nx * 128;
    gemm_tile<2, 2>(g_PH + aoff, g_PL + aoff, BANDW,
                    g_VtH + boff, nullptr, S_LEN,
                    nullptr, g_AOH + coff, nullptr, NHQ * DH, BANDW);
}

// ---------------- fused split of all 5 inputs ----------------
#define N_HS 1835008   // 2048*3584/4
#define N_WQ 3670016
#define N_WK 1835008
#define N_WV 1835008
#define N_WO 3670016
#define N_SPLIT_TOTAL (N_HS + N_WQ + N_WK + N_WV + N_WO)

__global__ void __launch_bounds__(256)
k_split_all(const float* __restrict__ hs, const float* __restrict__ wq,
            const float* __restrict__ wk, const float* __restrict__ wv,
            const float* __restrict__ wo)
{
    int i = blockIdx.x * 256 + threadIdx.x;
    const float* src;
    h16 *hi, *lo;
    int j = i;
    if (j < N_HS)                 { src = hs; hi = g_hsH; lo = g_hsL; }
    else if ((j -= N_HS) < N_WQ)  { src = wq; hi = g_wqH; lo = nullptr; }
    else if ((j -= N_WQ) < N_WK)  { src = wk; hi = g_wkH; lo = nullptr; }
    else if ((j -= N_WK) < N_WV)  { src = wv; hi = g_wvH; lo = nullptr; }
    else                          { j -= N_WV; src = wo; hi = g_woH; lo = nullptr; }

    float4 v = ((const float4*)src)[j];
    h16 h0 = __float2half(v.x), h1 = __float2half(v.y);
    h16 h2 = __float2half(v.z), h3 = __float2half(v.w);
    __half2 H0; H0.x = h0; H0.y = h1;
    __half2 H1; H1.x = h2; H1.y = h3;
    ((__half2*)hi)[j * 2 + 0] = H0;
    ((__half2*)hi)[j * 2 + 1] = H1;
    if (lo) {
        __half2 L0, L1;
        L0.x = __float2half(v.x - __half2float(h0));
        L0.y = __float2half(v.y - __half2float(h1));
        L1.x = __float2half(v.z - __half2float(h2));
        L1.y = __float2half(v.w - __half2float(h3));
        ((__half2*)lo)[j * 2 + 0] = L0;
        ((__half2*)lo)[j * 2 + 1] = L1;
    }
}

// ---------------- RoPE + split (Q split, K hi only) ----------------
__global__ void __launch_bounds__(256)
k_rope_split(const float* __restrict__ cosb, const float* __restrict__ sinb)
{
    int idx = blockIdx.x * 256 + threadIdx.x;
    int d = idx & 127;
    int t = idx >> 7;
    int slot = t % (NHQ + NKV);
    int s = t / (NHQ + NKV);

    float c0 = cosb[s * DH + d],       s0 = sinb[s * DH + d];
    float c1 = cosb[s * DH + d + 128], s1 = sinb[s * DH + d + 128];

    if (slot < NHQ) {
        size_t b = (size_t)s * (NHQ * DH) + slot * DH + d;
        float x0 = g_Q[b], x1 = g_Q[b + 128];
        float y0 = x0 * c0 - x1 * s0;
        float y1 = x1 * c1 + x0 * s1;
        h16 h0 = __float2half(y0), h1 = __float2half(y1);
        g_QH[b] = h0;       g_QH[b + 128] = h1;
        g_QL[b] = __float2half(y0 - __half2float(h0));
        g_QL[b + 128] = __float2half(y1 - __half2float(h1));
    } else {
        size_t b = (size_t)s * (NKV * DH) + (slot - NHQ) * DH + d;
        float x0 = g_K[b], x1 = g_K[b + 128];
        float y0 = x0 * c0 - x1 * s0;
        float y1 = x1 * c1 + x0 * s1;
        g_KH[b]       = __float2half(y0);
        g_KH[b + 128] = __float2half(y1);
    }
}

// ---------------- V transpose (hi only) ----------------
__global__ void __launch_bounds__(256)
k_vtrans()
{
    __shared__ float t[32][33];
    int bs = blockIdx.x * 32, bo = blockIdx.y * 32;
    int tx = threadIdx.x, ty = threadIdx.y;
#pragma unroll
    for (int j = 0; j < 32; j += 8)
        t[ty + j][tx] = g_V[(size_t)(bs + ty + j) * (NKV * DH) + bo + tx];
    __syncthreads();
#pragma unroll
    for (int j = 0; j < 32; j += 8) {
        float v = t[tx][ty + j];
        g_VtH[(size_t)(bo + ty + j) * S_LEN + bs + tx] = __float2half(v);
    }
}

// ---------------- band softmax (fast-math) ----------------
__global__ void __launch_bounds__(256)
k_softmax()
{
    int row  = blockIdx.x * 8 + (threadIdx.x >> 5);
    int lane = threadIdx.x & 31;
    int h = row >> 11;
    int q = row & 2047;

    size_t base = ((size_t)h * S_LEN + q) * BANDW;
    const float* p = g_S + base;
    int r  = q >> 7;
    int c0 = ((r - 8 > 0) ? (r - 8) : 0) * 128;
    int kmin = (q - (WINDOW - 1) > 0) ? (q - (WINDOW - 1)) : 0;

    float v[36];
    float m = -1e30f;
#pragma unroll
    for (int i = 0; i < 36; ++i) {
        int j = lane + 32 * i;
        int k = c0 + j;
        float tt;
        if (k >= kmin && k <= q) {
            float x = p[j] * (SCALING / SOFTCAP);
            x = fminf(fmaxf(x, -15.0f), 15.0f);
            float e2 = __expf(2.0f * x);
            tt = SOFTCAP * ((e2 - 1.0f) / (e2 + 1.0f));
        } else {
            tt = -1e30f;
        }
        v[i] = tt;
        m = fmaxf(m, tt);
    }
#pragma unroll
    for (int o = 16; o > 0; o >>= 1)
        m = fmaxf(m, __shfl_xor_sync(0xFFFFFFFFu, m, o));

    float l = 0.0f;
#pragma unroll
    for (int i = 0; i < 36; ++i) {
        v[i] = __expf(v[i] - m);
        l += v[i];
    }
#pragma unroll
    for (int o = 16; o > 0; o >>= 1)
        l += __shfl_xor_sync(0xFFFFFFFFu, l, o);

    float inv = 1.0f / l;
#pragma unroll
    for (int i = 0; i < 36; ++i) {
        float pv = v[i] * inv;
        h16 hh = __float2half(pv);
        g_PH[base + lane + 32 * i] = hh;
        g_PL[base + lane + 32 * i] = __float2half(pv - __half2float(hh));
    }
}

// ---------------- launch ----------------
extern "C" void kernel_launch(void* const* d_in, const int* in_sizes, int n_in,
                              void* d_out, int out_size)
{
    const float* hs   = (const float*)d_in[0];
    const float* cosb = (const float*)d_in[1];
    const float* sinb = (const float*)d_in[2];
    const float* wq   = (const float*)d_in[3];
    const float* wk   = (const float*)d_in[4];
    const float* wv   = (const float*)d_in[5];
    const float* wo   = (const float*)d_in[6];
    float* out = (float*)d_out;

    cudaFuncSetAttribute(k_gemm_qkv, cudaFuncAttributeMaxDynamicSharedMemorySize, SMEM2);
    cudaFuncSetAttribute(k_gemm_o,   cudaFuncAttributeMaxDynamicSharedMemorySize, SMEM1);
    cudaFuncSetAttribute(k_attn_s,   cudaFuncAttributeMaxDynamicSharedMemorySize, SMEM2);
    cudaFuncSetAttribute(k_attn_pv,  cudaFuncAttributeMaxDynamicSharedMemorySize, SMEM2);

    // fused split of all inputs (hs gets lo; weights hi-only)
    k_split_all<<<N_SPLIT_TOTAL / 256, 256>>>(hs, wq, wk, wv, wo);

    // fused QKV projections (2-product)
    k_gemm_qkv<<<dim3(64, S_LEN / 128), 128, SMEM2>>>();

    // RoPE + split, V transpose
    k_rope_split<<<(S_LEN * (NHQ + NKV) * 128) / 256, 256>>>(cosb, sinb);
    k_vtrans<<<dim3(S_LEN / 32, (NKV * DH) / 32), dim3(32, 8)>>>();

    // banded scores (2-product)
    k_attn_s<<<dim3(9, S_LEN / 128, NHQ), 128, SMEM2>>>();

    // softcap + mask + softmax -> split-fp16 P
    k_softmax<<<(NHQ * S_LEN) / 8, 256>>>();

    // PV (2-product) -> AO hi
    k_attn_pv<<<dim3(2, S_LEN / 128, NHQ), 128, SMEM2>>>();

    // output projection (1-product)
    k_gemm_o<<<dim3(HID / 128, S_LEN / 128), 128, SMEM1>>>(out);
}

// round 15
// speedup vs baseline: 4.4969x; 1.0622x over previous
#include <cuda_runtime.h>
#include <cuda_fp16.h>
#include <math.h>
#include <stdint.h>

// ---------------- problem constants ----------------
#define S_LEN   2048
#define HID     3584
#define NHQ     16
#define NKV     8
#define DH      256
#define GROUPS  2
#define WINDOW  1024
#define BANDW   1152
#define SOFTCAP 50.0f
#define SCALING 0.0625f

typedef __half h16;

// ---------------- device scratch ----------------
__device__ float g_Q [(size_t)S_LEN * NHQ * DH];
__device__ float g_K [(size_t)S_LEN * NKV * DH];
__device__ float g_V [(size_t)S_LEN * NKV * DH];
__device__ float g_S [(size_t)NHQ * S_LEN * BANDW];

__device__ h16 g_hsH[(size_t)S_LEN * HID],      g_hsL[(size_t)S_LEN * HID];
__device__ h16 g_wqH[(size_t)NHQ * DH * HID];
__device__ h16 g_wkH[(size_t)NKV * DH * HID];
__device__ h16 g_wvH[(size_t)NKV * DH * HID];
__device__ h16 g_woH[(size_t)HID * NHQ * DH];
__device__ h16 g_QH [(size_t)S_LEN * NHQ * DH], g_QL [(size_t)S_LEN * NHQ * DH];
__device__ h16 g_KH [(size_t)S_LEN * NKV * DH];                 // hi only
__device__ h16 g_VtH[(size_t)NKV * DH * S_LEN];                 // hi only
__device__ h16 g_PH [(size_t)NHQ * S_LEN * BANDW];              // hi only
__device__ h16 g_AOH[(size_t)S_LEN * NHQ * DH];                 // hi only

// ---------------- helpers ----------------
__device__ __forceinline__ uint32_t smem_u32(const void* p) {
    uint32_t a;
    asm("{ .reg .u64 t; cvta.to.shared.u64 t, %1; cvt.u32.u64 %0, t; }" : "=r"(a) : "l"(p));
    return a;
}
__device__ __forceinline__ void cp16(uint32_t saddr, const void* g) {
    asm volatile("cp.async.cg.shared.global [%0], [%1], 16;" :: "r"(saddr), "l"(g) : "memory");
}
#define CP_COMMIT() asm volatile("cp.async.commit_group;" ::: "memory")

#define LDSM4(r0, r1, r2, r3, addr) \
    asm volatile("ldmatrix.sync.aligned.m8n8.x4.shared.b16 {%0,%1,%2,%3}, [%4];" \
        : "=r"(r0), "=r"(r1), "=r"(r2), "=r"(r3) : "r"(addr))

__device__ __forceinline__ void mma32(float* c,
    uint32_t a0, uint32_t a1, uint32_t a2, uint32_t a3,
    uint32_t b0, uint32_t b1)
{
    asm volatile(
        "mma.sync.aligned.m16n8k16.row.col.f32.f16.f16.f32 "
        "{%0,%1,%2,%3}, {%4,%5,%6,%7}, {%8,%9}, {%0,%1,%2,%3};"
        : "+f"(c[0]), "+f"(c[1]), "+f"(c[2]), "+f"(c[3])
        : "r"(a0), "r"(a1), "r"(a2), "r"(a3), "r"(b0), "r"(b1));
}

// ---------------- stage layout ----------------
// NPROD==2 (24 KB): Ah | Al | Bh.   NPROD==1 (16 KB): Ah | Bh.
#define NSTAGE 3

template <int NPROD>
__device__ __forceinline__ void stage_cp(
    const h16* __restrict__ Ah, const h16* __restrict__ Al, int lda,
    const h16* __restrict__ Bh, int ldb,
    int k0, uint32_t smb, int buf, int tid)
{
    const int STG = (NPROD == 2) ? 24576 : 16384;
    const uint32_t OBH = (NPROD == 2) ? 16384u : 8192u;
    uint32_t sb = smb + buf * STG;
#pragma unroll
    for (int i = 0; i < 4; ++i) {
        int si  = tid + i * 128;
        int row = si >> 2;
        int seg = si & 3;
        uint32_t soff = row * 64 + ((seg ^ ((row >> 1) & 3)) << 4);
        size_t goA = (size_t)row * lda + k0 + seg * 8;
        size_t goB = (size_t)row * ldb + k0 + seg * 8;
        cp16(sb + soff, Ah + goA);
        if (NPROD == 2) cp16(sb + 8192 + soff, Al + goA);
        cp16(sb + OBH + soff, Bh + goB);
    }
}

// ---------------- 128x128 NT GEMM tile, fp16, fp32 accum ----------------
// 128 threads (4 warps, 2x2, warp tile 64x64). K % 32 == 0.
// NPROD=2: Ah*Bh + Al*Bh.  NPROD=1: Ah*Bh.
// EPI=0: fp32 C.  EPI=2: fp16 hi only (Ch).
template <int NPROD, int EPI>
__device__ void gemm_tile(
    const h16* __restrict__ Ah, const h16* __restrict__ Al, int lda,
    const h16* __restrict__ Bh, int ldb,
    float* __restrict__ C, h16* __restrict__ Ch,
    int ldc, int K)
{
    const int STG = (NPROD == 2) ? 24576 : 16384;
    const uint32_t OBH = (NPROD == 2) ? 16384u : 8192u;
    extern __shared__ char smem[];
    const uint32_t smb = smem_u32(smem);
    const int tid  = threadIdx.x;
    const int lane = tid & 31;
    const int wid  = tid >> 5;
    const int wm   = wid >> 1;
    const int wn   = wid & 1;
    const int la   = lane & 7;
    const int grp  = lane >> 3;

    float acc[4][8][4];
#pragma unroll
    for (int mi = 0; mi < 4; ++mi)
#pragma unroll
        for (int ni = 0; ni < 8; ++ni)
#pragma unroll
            for (int q = 0; q < 4; ++q) acc[mi][ni][q] = 0.0f;

    uint32_t offA[4], swA[4];
#pragma unroll
    for (int mi = 0; mi < 4; ++mi) {
        int r = wm * 64 + mi * 16 + la + (grp & 1) * 8;
        offA[mi] = r * 64;
        swA[mi]  = (r >> 1) & 3;
    }
    const int segselA = grp >> 1;
    uint32_t offB[4], swB[4];
#pragma unroll
    for (int p = 0; p < 4; ++p) {
        int r = wn * 64 + p * 16 + la + (grp >> 1) * 8;
        offB[p] = r * 64;
        swB[p]  = (r >> 1) & 3;
    }
    const int segselB = grp & 1;

    const int nK = K >> 5;
    stage_cp<NPROD>(Ah, Al, lda, Bh, ldb, 0, smb, 0, tid);
    CP_COMMIT();
    stage_cp<NPROD>(Ah, Al, lda, Bh, ldb, 32, smb, 1, tid);
    CP_COMMIT();

    for (int ki = 0; ki < nK; ++ki) {
        asm volatile("cp.async.wait_group 1;" ::: "memory");
        __syncthreads();
        if (ki + 2 < nK)
            stage_cp<NPROD>(Ah, Al, lda, Bh, ldb, (ki + 2) << 5, smb, (ki + 2) % NSTAGE, tid);
        CP_COMMIT();

        const uint32_t sA  = smb + (ki % NSTAGE) * STG;
        const uint32_t sAl = sA + 8192;
        const uint32_t sB  = sA + OBH;

#pragma unroll
        for (int ks = 0; ks < 2; ++ks) {
            uint32_t ah[4][4], al[4][4];
#pragma unroll
            for (int mi = 0; mi < 4; ++mi) {
                uint32_t aoff = offA[mi] + ((((uint32_t)(ks * 2 + segselA) ^ swA[mi])) << 4);
                LDSM4(ah[mi][0], ah[mi][1], ah[mi][2], ah[mi][3], sA + aoff);
                if (NPROD == 2) { LDSM4(al[mi][0], al[mi][1], al[mi][2], al[mi][3], sAl + aoff); }
            }
#pragma unroll
            for (int p = 0; p < 4; ++p) {
                uint32_t boff = offB[p] + ((((uint32_t)(ks * 2 + segselB) ^ swB[p])) << 4);
                uint32_t bh0, bh1, bh2, bh3;
                LDSM4(bh0, bh1, bh2, bh3, sB + boff);
#pragma unroll
                for (int mi = 0; mi < 4; ++mi) {
                    float* c0 = acc[mi][2 * p];
                    float* c1 = acc[mi][2 * p + 1];
                    mma32(c0, ah[mi][0], ah[mi][1], ah[mi][2], ah[mi][3], bh0, bh1);
                    mma32(c1, ah[mi][0], ah[mi][1], ah[mi][2], ah[mi][3], bh2, bh3);
                    if (NPROD == 2) {
                        mma32(c0, al[mi][0], al[mi][1], al[mi][2], al[mi][3], bh0, bh1);
                        mma32(c1, al[mi][0], al[mi][1], al[mi][2], al[mi][3], bh2, bh3);
                    }
                }
            }
        }
    }

    const int g  = lane >> 2;
    const int t4 = lane & 3;
#pragma unroll
    for (int mi = 0; mi < 4; ++mi) {
        int R0 = wm * 64 + mi * 16 + g;
        int R1 = R0 + 8;
#pragma unroll
        for (int ni = 0; ni < 8; ++ni) {
            int col = wn * 64 + ni * 8 + t4 * 2;
            float* a = acc[mi][ni];
            if (EPI == 0) {
                *(float2*)(C + (size_t)R0 * ldc + col) = make_float2(a[0], a[1]);
                *(float2*)(C + (size_t)R1 * ldc + col) = make_float2(a[2], a[3]);
            } else {
                __half2 H0; H0.x = __float2half(a[0]); H0.y = __float2half(a[1]);
                __half2 H1; H1.x = __float2half(a[2]); H1.y = __float2half(a[3]);
                *(__half2*)(Ch + (size_t)R0 * ldc + col) = H0;
                *(__half2*)(Ch + (size_t)R1 * ldc + col) = H1;
            }
        }
    }
}

// ---------------- GEMM wrapper kernels ----------------
#define SMEM2 (NSTAGE * 24576)
#define SMEM1 (NSTAGE * 16384)

// Fused QKV projection: grid (64, 16). bx 0..31 -> Q (2-prod), 32..47 -> K (2-prod),
// 48..63 -> V (1-prod, hs hi only).
__global__ void __launch_bounds__(128, 2)
k_gemm_qkv()
{
    int bx = blockIdx.x, by = blockIdx.y;
    size_t m0 = (size_t)by * 128;
    if (bx < 32) {
        gemm_tile<2, 0>(g_hsH + m0 * HID, g_hsL + m0 * HID, HID,
                        g_wqH + (size_t)bx * 128 * HID, HID,
                        g_Q + m0 * (NHQ * DH) + (size_t)bx * 128, nullptr, NHQ * DH, HID);
    } else if (bx < 48) {
        int b = bx - 32;
        gemm_tile<2, 0>(g_hsH + m0 * HID, g_hsL + m0 * HID, HID,
                        g_wkH + (size_t)b * 128 * HID, HID,
                        g_K + m0 * (NKV * DH) + (size_t)b * 128, nullptr, NKV * DH, HID);
    } else {
        int b = bx - 48;
        gemm_tile<1, 0>(g_hsH + m0 * HID, nullptr, HID,
                        g_wvH + (size_t)b * 128 * HID, HID,
                        g_V + m0 * (NKV * DH) + (size_t)b * 128, nullptr, NKV * DH, HID);
    }
}

// O projection: 1-product
__global__ void __launch_bounds__(128, 2)
k_gemm_o(float* __restrict__ out)
{
    size_t m0 = (size_t)blockIdx.y * 128, n0 = (size_t)blockIdx.x * 128;
    gemm_tile<1, 0>(g_AOH + m0 * (NHQ * DH), nullptr, NHQ * DH,
                    g_woH + n0 * (NHQ * DH), NHQ * DH,
                    out + m0 * HID + n0, nullptr, HID, NHQ * DH);
}

// banded scores: 2-product (Q split x K hi)
__global__ void __launch_bounds__(128, 2)
k_attn_s()
{
    int h = blockIdx.z, r = blockIdx.y, cx = blockIdx.x;
    int cbase = (r - 8 > 0) ? (r - 8) : 0;
    int ct = cbase + cx;
    if (ct > r) return;
    size_t aoff = (size_t)r * 128 * (NHQ * DH) + (size_t)h * DH;
    size_t boff = (size_t)ct * 128 * (NKV * DH) + (size_t)(h / GROUPS) * DH;
    float* C = g_S + ((size_t)h * S_LEN + (size_t)r * 128) * BANDW + (size_t)cx * 128;
    gemm_tile<2, 0>(g_QH + aoff, g_QL + aoff, NHQ * DH,
                    g_KH + boff, NKV * DH,
                    C, nullptr, BANDW, DH);
}

// PV: 1-product (P hi x Vt hi) -> AO hi
__global__ void __launch_bounds__(128, 2)
k_attn_pv()
{
    int h = blockIdx.z, r = blockIdx.y, nx = blockIdx.x;
    int c0 = ((r - 8 > 0) ? (r - 8) : 0) * 128;
    size_t aoff = ((size_t)h * S_LEN + (size_t)r * 128) * BANDW;
    size_t boff = ((size_t)(h / GROUPS) * DH + (size_t)nx * 128) * S_LEN + (size_t)c0;
    size_t coff = (size_t)r * 128 * (NHQ * DH) + (size_t)h * DH + (size_t)nx * 128;
    gemm_tile<1, 2>(g_PH + aoff, nullptr, BANDW,
                    g_VtH + boff, S_LEN,
                    nullptr, g_AOH + coff, NHQ * DH, BANDW);
}

// ---------------- fused split of all 5 inputs ----------------
#define N_HS 1835008   // 2048*3584/4
#define N_WQ 3670016
#define N_WK 1835008
#define N_WV 1835008
#define N_WO 3670016
#define N_SPLIT_TOTAL (N_HS + N_WQ + N_WK + N_WV + N_WO)

__global__ void __launch_bounds__(256)
k_split_all(const float* __restrict__ hs, const float* __restrict__ wq,
            const float* __restrict__ wk, const float* __restrict__ wv,
            const float* __restrict__ wo)
{
    int i = blockIdx.x * 256 + threadIdx.x;
    const float* src;
    h16 *hi, *lo;
    int j = i;
    if (j < N_HS)                 { src = hs; hi = g_hsH; lo = g_hsL; }
    else if ((j -= N_HS) < N_WQ)  { src = wq; hi = g_wqH; lo = nullptr; }
    else if ((j -= N_WQ) < N_WK)  { src = wk; hi = g_wkH; lo = nullptr; }
    else if ((j -= N_WK) < N_WV)  { src = wv; hi = g_wvH; lo = nullptr; }
    else                          { j -= N_WV; src = wo; hi = g_woH; lo = nullptr; }

    float4 v = ((const float4*)src)[j];
    h16 h0 = __float2half(v.x), h1 = __float2half(v.y);
    h16 h2 = __float2half(v.z), h3 = __float2half(v.w);
    __half2 H0; H0.x = h0; H0.y = h1;
    __half2 H1; H1.x = h2; H1.y = h3;
    ((__half2*)hi)[j * 2 + 0] = H0;
    ((__half2*)hi)[j * 2 + 1] = H1;
    if (lo) {
        __half2 L0, L1;
        L0.x = __float2half(v.x - __half2float(h0));
        L0.y = __float2half(v.y - __half2float(h1));
        L1.x = __float2half(v.z - __half2float(h2));
        L1.y = __float2half(v.w - __half2float(h3));
        ((__half2*)lo)[j * 2 + 0] = L0;
        ((__half2*)lo)[j * 2 + 1] = L1;
    }
}

// ---------------- RoPE + split (Q split, K hi only) ----------------
__global__ void __launch_bounds__(256)
k_rope_split(const float* __restrict__ cosb, const float* __restrict__ sinb)
{
    int idx = blockIdx.x * 256 + threadIdx.x;
    int d = idx & 127;
    int t = idx >> 7;
    int slot = t % (NHQ + NKV);
    int s = t / (NHQ + NKV);

    float c0 = cosb[s * DH + d],       s0 = sinb[s * DH + d];
    float c1 = cosb[s * DH + d + 128], s1 = sinb[s * DH + d + 128];

    if (slot < NHQ) {
        size_t b = (size_t)s * (NHQ * DH) + slot * DH + d;
        float x0 = g_Q[b], x1 = g_Q[b + 128];
        float y0 = x0 * c0 - x1 * s0;
        float y1 = x1 * c1 + x0 * s1;
        h16 h0 = __float2half(y0), h1 = __float2half(y1);
        g_QH[b] = h0;       g_QH[b + 128] = h1;
        g_QL[b] = __float2half(y0 - __half2float(h0));
        g_QL[b + 128] = __float2half(y1 - __half2float(h1));
    } else {
        size_t b = (size_t)s * (NKV * DH) + (slot - NHQ) * DH + d;
        float x0 = g_K[b], x1 = g_K[b + 128];
        float y0 = x0 * c0 - x1 * s0;
        float y1 = x1 * c1 + x0 * s1;
        g_KH[b]       = __float2half(y0);
        g_KH[b + 128] = __float2half(y1);
    }
}

// ---------------- V transpose (hi only) ----------------
__global__ void __launch_bounds__(256)
k_vtrans()
{
    __shared__ float t[32][33];
    int bs = blockIdx.x * 32, bo = blockIdx.y * 32;
    int tx = threadIdx.x, ty = threadIdx.y;
#pragma unroll
    for (int j = 0; j < 32; j += 8)
        t[ty + j][tx] = g_V[(size_t)(bs + ty + j) * (NKV * DH) + bo + tx];
    __syncthreads();
#pragma unroll
    for (int j = 0; j < 32; j += 8) {
        float v = t[tx][ty + j];
        g_VtH[(size_t)(bo + ty + j) * S_LEN + bs + tx] = __float2half(v);
    }
}

// ---------------- band softmax (fast-math) -> P hi only ----------------
__global__ void __launch_bounds__(256)
k_softmax()
{
    int row  = blockIdx.x * 8 + (threadIdx.x >> 5);
    int lane = threadIdx.x & 31;
    int h = row >> 11;
    int q = row & 2047;

    size_t base = ((size_t)h * S_LEN + q) * BANDW;
    const float* p = g_S + base;
    int r  = q >> 7;
    int c0 = ((r - 8 > 0) ? (r - 8) : 0) * 128;
    int kmin = (q - (WINDOW - 1) > 0) ? (q - (WINDOW - 1)) : 0;

    float v[36];
    float m = -1e30f;
#pragma unroll
    for (int i = 0; i < 36; ++i) {
        int j = lane + 32 * i;
        int k = c0 + j;
        float tt;
        if (k >= kmin && k <= q) {
            float x = p[j] * (SCALING / SOFTCAP);
            x = fminf(fmaxf(x, -15.0f), 15.0f);
            float e2 = __expf(2.0f * x);
            tt = SOFTCAP * ((e2 - 1.0f) / (e2 + 1.0f));
        } else {
            tt = -1e30f;
        }
        v[i] = tt;
        m = fmaxf(m, tt);
    }
#pragma unroll
    for (int o = 16; o > 0; o >>= 1)
        m = fmaxf(m, __shfl_xor_sync(0xFFFFFFFFu, m, o));

    float l = 0.0f;
#pragma unroll
    for (int i = 0; i < 36; ++i) {
        v[i] = __expf(v[i] - m);
        l += v[i];
    }
#pragma unroll
    for (int o = 16; o > 0; o >>= 1)
        l += __shfl_xor_sync(0xFFFFFFFFu, l, o);

    float inv = 1.0f / l;
#pragma unroll
    for (int i = 0; i < 36; ++i)
        g_PH[base + lane + 32 * i] = __float2half(v[i] * inv);
}

// ---------------- launch ----------------
extern "C" void kernel_launch(void* const* d_in, const int* in_sizes, int n_in,
                              void* d_out, int out_size)
{
    const float* hs   = (const float*)d_in[0];
    const float* cosb = (const float*)d_in[1];
    const float* sinb = (const float*)d_in[2];
    const float* wq   = (const float*)d_in[3];
    const float* wk   = (const float*)d_in[4];
    const float* wv   = (const float*)d_in[5];
    const float* wo   = (const float*)d_in[6];
    float* out = (float*)d_out;

    cudaFuncSetAttribute(k_gemm_qkv, cudaFuncAttributeMaxDynamicSharedMemorySize, SMEM2);
    cudaFuncSetAttribute(k_gemm_o,   cudaFuncAttributeMaxDynamicSharedMemorySize, SMEM1);
    cudaFuncSetAttribute(k_attn_s,   cudaFuncAttributeMaxDynamicSharedMemorySize, SMEM2);
    cudaFuncSetAttribute(k_attn_pv,  cudaFuncAttributeMaxDynamicSharedMemorySize, SMEM1);

    // fused split of all inputs
    k_split_all<<<N_SPLIT_TOTAL / 256, 256>>>(hs, wq, wk, wv, wo);

    // fused QKV projections (Q/K 2-product, V 1-product)
    k_gemm_qkv<<<dim3(64, S_LEN / 128), 128, SMEM2>>>();

    // RoPE + split, V transpose
    k_rope_split<<<(S_LEN * (NHQ + NKV) * 128) / 256, 256>>>(cosb, sinb);
    k_vtrans<<<dim3(S_LEN / 32, (NKV * DH) / 32), dim3(32, 8)>>>();

    // banded scores (2-product)
    k_attn_s<<<dim3(9, S_LEN / 128, NHQ), 128, SMEM2>>>();

    // softcap + mask + softmax -> P hi
    k_softmax<<<(NHQ * S_LEN) / 8, 256>>>();

    // PV (1-product) -> AO hi
    k_attn_pv<<<dim3(2, S_LEN / 128, NHQ), 128, SMEM1>>>();

    // output projection (1-product)
    k_gemm_o<<<dim3(HID / 128, S_LEN / 128), 128, SMEM1>>>(out);
}

// round 16
// speedup vs baseline: 4.6409x; 1.0320x over previous
#include <cuda_runtime.h>
#include <cuda_fp16.h>
#include <math.h>
#include <stdint.h>

// ---------------- problem constants ----------------
#define S_LEN   2048
#define HID     3584
#define NHQ     16
#define NKV     8
#define DH      256
#define GROUPS  2
#define WINDOW  1024
#define BANDW   1152
#define SOFTCAP 50.0f
#define SCALING 0.0625f

typedef __half h16;

// ---------------- device scratch ----------------
__device__ float g_Q [(size_t)S_LEN * NHQ * DH];
__device__ float g_K [(size_t)S_LEN * NKV * DH];
__device__ float g_V [(size_t)S_LEN * NKV * DH];
__device__ float g_S [(size_t)NHQ * S_LEN * BANDW];

__device__ h16 g_hsH[(size_t)S_LEN * HID],      g_hsL[(size_t)S_LEN * HID];
__device__ h16 g_wqH[(size_t)NHQ * DH * HID];
__device__ h16 g_wkH[(size_t)NKV * DH * HID];
__device__ h16 g_wvH[(size_t)NKV * DH * HID];
__device__ h16 g_woH[(size_t)HID * NHQ * DH];
__device__ h16 g_QH [(size_t)S_LEN * NHQ * DH], g_QL [(size_t)S_LEN * NHQ * DH];
__device__ h16 g_KH [(size_t)S_LEN * NKV * DH];
__device__ h16 g_VtH[(size_t)NKV * DH * S_LEN];
__device__ h16 g_PH [(size_t)NHQ * S_LEN * BANDW];
__device__ h16 g_AOH[(size_t)S_LEN * NHQ * DH];

// ---------------- helpers ----------------
__device__ __forceinline__ uint32_t smem_u32(const void* p) {
    uint32_t a;
    asm("{ .reg .u64 t; cvta.to.shared.u64 t, %1; cvt.u32.u64 %0, t; }" : "=r"(a) : "l"(p));
    return a;
}
__device__ __forceinline__ void cp16(uint32_t saddr, const void* g) {
    asm volatile("cp.async.cg.shared.global [%0], [%1], 16;" :: "r"(saddr), "l"(g) : "memory");
}
#define CP_COMMIT() asm volatile("cp.async.commit_group;" ::: "memory")

#define LDSM4(r0, r1, r2, r3, addr) \
    asm volatile("ldmatrix.sync.aligned.m8n8.x4.shared.b16 {%0,%1,%2,%3}, [%4];" \
        : "=r"(r0), "=r"(r1), "=r"(r2), "=r"(r3) : "r"(addr))

__device__ __forceinline__ void mma32(float* c,
    uint32_t a0, uint32_t a1, uint32_t a2, uint32_t a3,
    uint32_t b0, uint32_t b1)
{
    asm volatile(
        "mma.sync.aligned.m16n8k16.row.col.f32.f16.f16.f32 "
        "{%0,%1,%2,%3}, {%4,%5,%6,%7}, {%8,%9}, {%0,%1,%2,%3};"
        : "+f"(c[0]), "+f"(c[1]), "+f"(c[2]), "+f"(c[3])
        : "r"(a0), "r"(a1), "r"(a2), "r"(a3), "r"(b0), "r"(b1));
}

// ---------------- stage layout (K-chunk 64, row pitch 128 B) ----------------
// NPROD==2 (48 KB): Ah | Al | Bh  (16 KB each).  NPROD==1 (32 KB): Ah | Bh.
// 8 x 16B segments per row, swizzle: seg_store = seg ^ (row & 7).
#define NSTAGE 3

template <int NPROD>
__device__ __forceinline__ void stage_cp(
    const h16* __restrict__ Ah, const h16* __restrict__ Al, int lda,
    const h16* __restrict__ Bh, int ldb,
    int k0, uint32_t smb, int buf, int tid)
{
    const int STG = (NPROD == 2) ? 49152 : 32768;
    const uint32_t OBH = (NPROD == 2) ? 32768u : 16384u;
    uint32_t sb = smb + buf * STG;
#pragma unroll
    for (int i = 0; i < 8; ++i) {
        int si  = tid + i * 128;      // 0..1023
        int row = si >> 3;            // 0..127
        int seg = si & 7;             // 0..7
        uint32_t soff = row * 128 + ((seg ^ (row & 7)) << 4);
        size_t goA = (size_t)row * lda + k0 + seg * 8;
        size_t goB = (size_t)row * ldb + k0 + seg * 8;
        cp16(sb + soff, Ah + goA);
        if (NPROD == 2) cp16(sb + 16384 + soff, Al + goA);
        cp16(sb + OBH + soff, Bh + goB);
    }
}

// ---------------- 128x128 NT GEMM tile, fp16, fp32 accum ----------------
// 128 threads (4 warps, 2x2, warp tile 64x64). K % 64 == 0.
// NPROD=2: Ah*Bh + Al*Bh.  NPROD=1: Ah*Bh.
// EPI=0: fp32 C.  EPI=2: fp16 hi only (Ch).
template <int NPROD, int EPI>
__device__ void gemm_tile(
    const h16* __restrict__ Ah, const h16* __restrict__ Al, int lda,
    const h16* __restrict__ Bh, int ldb,
    float* __restrict__ C, h16* __restrict__ Ch,
    int ldc, int K)
{
    const int STG = (NPROD == 2) ? 49152 : 32768;
    const uint32_t OBH = (NPROD == 2) ? 32768u : 16384u;
    extern __shared__ char smem[];
    const uint32_t smb = smem_u32(smem);
    const int tid  = threadIdx.x;
    const int lane = tid & 31;
    const int wid  = tid >> 5;
    const int wm   = wid >> 1;
    const int wn   = wid & 1;
    const int la   = lane & 7;
    const int grp  = lane >> 3;

    float acc[4][8][4];
#pragma unroll
    for (int mi = 0; mi < 4; ++mi)
#pragma unroll
        for (int ni = 0; ni < 8; ++ni)
#pragma unroll
            for (int q = 0; q < 4; ++q) acc[mi][ni][q] = 0.0f;

    uint32_t offA[4], swA[4];
#pragma unroll
    for (int mi = 0; mi < 4; ++mi) {
        int r = wm * 64 + mi * 16 + la + (grp & 1) * 8;
        offA[mi] = r * 128;
        swA[mi]  = r & 7;
    }
    const int segselA = grp >> 1;
    uint32_t offB[4], swB[4];
#pragma unroll
    for (int p = 0; p < 4; ++p) {
        int r = wn * 64 + p * 16 + la + (grp >> 1) * 8;
        offB[p] = r * 128;
        swB[p]  = r & 7;
    }
    const int segselB = grp & 1;

    const int nK = K >> 6;
    stage_cp<NPROD>(Ah, Al, lda, Bh, ldb, 0, smb, 0, tid);
    CP_COMMIT();
    stage_cp<NPROD>(Ah, Al, lda, Bh, ldb, 64, smb, 1, tid);
    CP_COMMIT();

    for (int ki = 0; ki < nK; ++ki) {
        asm volatile("cp.async.wait_group 1;" ::: "memory");   // stage ki arrived
        __syncthreads();                                       // prior consume done
        if (ki + 2 < nK)
            stage_cp<NPROD>(Ah, Al, lda, Bh, ldb, (ki + 2) << 6, smb, (ki + 2) % NSTAGE, tid);
        CP_COMMIT();

        const uint32_t sA  = smb + (ki % NSTAGE) * STG;
        const uint32_t sAl = sA + 16384;
        const uint32_t sB  = sA + OBH;

#pragma unroll
        for (int ks = 0; ks < 4; ++ks) {                       // 4 x k16 per stage
            uint32_t ah[4][4], al[4][4];
#pragma unroll
            for (int mi = 0; mi < 4; ++mi) {
                uint32_t aoff = offA[mi] + ((((uint32_t)(ks * 2 + segselA) ^ swA[mi])) << 4);
                LDSM4(ah[mi][0], ah[mi][1], ah[mi][2], ah[mi][3], sA + aoff);
                if (NPROD == 2) { LDSM4(al[mi][0], al[mi][1], al[mi][2], al[mi][3], sAl + aoff); }
            }
#pragma unroll
            for (int p = 0; p < 4; ++p) {
                uint32_t boff = offB[p] + ((((uint32_t)(ks * 2 + segselB) ^ swB[p])) << 4);
                uint32_t bh0, bh1, bh2, bh3;
                LDSM4(bh0, bh1, bh2, bh3, sB + boff);
                // hi products: 8 MMAs across distinct accumulators
#pragma unroll
                for (int mi = 0; mi < 4; ++mi) {
                    mma32(acc[mi][2 * p],     ah[mi][0], ah[mi][1], ah[mi][2], ah[mi][3], bh0, bh1);
                    mma32(acc[mi][2 * p + 1], ah[mi][0], ah[mi][1], ah[mi][2], ah[mi][3], bh2, bh3);
                }
                // lo products: another 8 MMAs, each accumulator reused only after 8 others
                if (NPROD == 2) {
#pragma unroll
                    for (int mi = 0; mi < 4; ++mi) {
                        mma32(acc[mi][2 * p],     al[mi][0], al[mi][1], al[mi][2], al[mi][3], bh0, bh1);
                        mma32(acc[mi][2 * p + 1], al[mi][0], al[mi][1], al[mi][2], al[mi][3], bh2, bh3);
                    }
                }
            }
        }
    }

    const int g  = lane >> 2;
    const int t4 = lane & 3;
#pragma unroll
    for (int mi = 0; mi < 4; ++mi) {
        int R0 = wm * 64 + mi * 16 + g;
        int R1 = R0 + 8;
#pragma unroll
        for (int ni = 0; ni < 8; ++ni) {
            int col = wn * 64 + ni * 8 + t4 * 2;
            float* a = acc[mi][ni];
            if (EPI == 0) {
                *(float2*)(C + (size_t)R0 * ldc + col) = make_float2(a[0], a[1]);
                *(float2*)(C + (size_t)R1 * ldc + col) = make_float2(a[2], a[3]);
            } else {
                __half2 H0; H0.x = __float2half(a[0]); H0.y = __float2half(a[1]);
                __half2 H1; H1.x = __float2half(a[2]); H1.y = __float2half(a[3]);
                *(__half2*)(Ch + (size_t)R0 * ldc + col) = H0;
                *(__half2*)(Ch + (size_t)R1 * ldc + col) = H1;
            }
        }
    }
}

// ---------------- GEMM wrapper kernels ----------------
#define SMEM2 (NSTAGE * 49152)
#define SMEM1 (NSTAGE * 32768)

// Fused QKV projection: grid (64, 16). bx 0..31 -> Q (2-prod), 32..47 -> K (2-prod),
// 48..63 -> V (1-prod).
__global__ void __launch_bounds__(128, 2)
k_gemm_qkv()
{
    int bx = blockIdx.x, by = blockIdx.y;
    size_t m0 = (size_t)by * 128;
    if (bx < 32) {
        gemm_tile<2, 0>(g_hsH + m0 * HID, g_hsL + m0 * HID, HID,
                        g_wqH + (size_t)bx * 128 * HID, HID,
                        g_Q + m0 * (NHQ * DH) + (size_t)bx * 128, nullptr, NHQ * DH, HID);
    } else if (bx < 48) {
        int b = bx - 32;
        gemm_tile<2, 0>(g_hsH + m0 * HID, g_hsL + m0 * HID, HID,
                        g_wkH + (size_t)b * 128 * HID, HID,
                        g_K + m0 * (NKV * DH) + (size_t)b * 128, nullptr, NKV * DH, HID);
    } else {
        int b = bx - 48;
        gemm_tile<1, 0>(g_hsH + m0 * HID, nullptr, HID,
                        g_wvH + (size_t)b * 128 * HID, HID,
                        g_V + m0 * (NKV * DH) + (size_t)b * 128, nullptr, NKV * DH, HID);
    }
}

// O projection: 1-product
__global__ void __launch_bounds__(128, 2)
k_gemm_o(float* __restrict__ out)
{
    size_t m0 = (size_t)blockIdx.y * 128, n0 = (size_t)blockIdx.x * 128;
    gemm_tile<1, 0>(g_AOH + m0 * (NHQ * DH), nullptr, NHQ * DH,
                    g_woH + n0 * (NHQ * DH), NHQ * DH,
                    out + m0 * HID + n0, nullptr, HID, NHQ * DH);
}

// banded scores: 2-product (Q split x K hi)
__global__ void __launch_bounds__(128, 2)
k_attn_s()
{
    int h = blockIdx.z, r = blockIdx.y, cx = blockIdx.x;
    int cbase = (r - 8 > 0) ? (r - 8) : 0;
    int ct = cbase + cx;
    if (ct > r) return;
    size_t aoff = (size_t)r * 128 * (NHQ * DH) + (size_t)h * DH;
    size_t boff = (size_t)ct * 128 * (NKV * DH) + (size_t)(h / GROUPS) * DH;
    float* C = g_S + ((size_t)h * S_LEN + (size_t)r * 128) * BANDW + (size_t)cx * 128;
    gemm_tile<2, 0>(g_QH + aoff, g_QL + aoff, NHQ * DH,
                    g_KH + boff, NKV * DH,
                    C, nullptr, BANDW, DH);
}

// PV: 1-product (P hi x Vt hi) -> AO hi
__global__ void __launch_bounds__(128, 2)
k_attn_pv()
{
    int h = blockIdx.z, r = blockIdx.y, nx = blockIdx.x;
    int c0 = ((r - 8 > 0) ? (r - 8) : 0) * 128;
    size_t aoff = ((size_t)h * S_LEN + (size_t)r * 128) * BANDW;
    size_t boff = ((size_t)(h / GROUPS) * DH + (size_t)nx * 128) * S_LEN + (size_t)c0;
    size_t coff = (size_t)r * 128 * (NHQ * DH) + (size_t)h * DH + (size_t)nx * 128;
    gemm_tile<1, 2>(g_PH + aoff, nullptr, BANDW,
                    g_VtH + boff, S_LEN,
                    nullptr, g_AOH + coff, NHQ * DH, BANDW);
}

// ---------------- fused split of all 5 inputs ----------------
#define N_HS 1835008   // 2048*3584/4
#define N_WQ 3670016
#define N_WK 1835008
#define N_WV 1835008
#define N_WO 3670016
#define N_SPLIT_TOTAL (N_HS + N_WQ + N_WK + N_WV + N_WO)

__global__ void __launch_bounds__(256)
k_split_all(const float* __restrict__ hs, const float* __restrict__ wq,
            const float* __restrict__ wk, const float* __restrict__ wv,
            const float* __restrict__ wo)
{
    int i = blockIdx.x * 256 + threadIdx.x;
    const float* src;
    h16 *hi, *lo;
    int j = i;
    if (j < N_HS)                 { src = hs; hi = g_hsH; lo = g_hsL; }
    else if ((j -= N_HS) < N_WQ)  { src = wq; hi = g_wqH; lo = nullptr; }
    else if ((j -= N_WQ) < N_WK)  { src = wk; hi = g_wkH; lo = nullptr; }
    else if ((j -= N_WK) < N_WV)  { src = wv; hi = g_wvH; lo = nullptr; }
    else                          { j -= N_WV; src = wo; hi = g_woH; lo = nullptr; }

    float4 v = ((const float4*)src)[j];
    h16 h0 = __float2half(v.x), h1 = __float2half(v.y);
    h16 h2 = __float2half(v.z), h3 = __float2half(v.w);
    __half2 H0; H0.x = h0; H0.y = h1;
    __half2 H1; H1.x = h2; H1.y = h3;
    ((__half2*)hi)[j * 2 + 0] = H0;
    ((__half2*)hi)[j * 2 + 1] = H1;
    if (lo) {
        __half2 L0, L1;
        L0.x = __float2half(v.x - __half2float(h0));
        L0.y = __float2half(v.y - __half2float(h1));
        L1.x = __float2half(v.z - __half2float(h2));
        L1.y = __float2half(v.w - __half2float(h3));
        ((__half2*)lo)[j * 2 + 0] = L0;
        ((__half2*)lo)[j * 2 + 1] = L1;
    }
}

// ---------------- RoPE + split (Q split, K hi only) ----------------
__global__ void __launch_bounds__(256)
k_rope_split(const float* __restrict__ cosb, const float* __restrict__ sinb)
{
    int idx = blockIdx.x * 256 + threadIdx.x;
    int d = idx & 127;
    int t = idx >> 7;
    int slot = t % (NHQ + NKV);
    int s = t / (NHQ + NKV);

    float c0 = cosb[s * DH + d],       s0 = sinb[s * DH + d];
    float c1 = cosb[s * DH + d + 128], s1 = sinb[s * DH + d + 128];

    if (slot < NHQ) {
        size_t b = (size_t)s * (NHQ * DH) + slot * DH + d;
        float x0 = g_Q[b], x1 = g_Q[b + 128];
        float y0 = x0 * c0 - x1 * s0;
        float y1 = x1 * c1 + x0 * s1;
        h16 h0 = __float2half(y0), h1 = __float2half(y1);
        g_QH[b] = h0;       g_QH[b + 128] = h1;
        g_QL[b] = __float2half(y0 - __half2float(h0));
        g_QL[b + 128] = __float2half(y1 - __half2float(h1));
    } else {
        size_t b = (size_t)s * (NKV * DH) + (slot - NHQ) * DH + d;
        float x0 = g_K[b], x1 = g_K[b + 128];
        float y0 = x0 * c0 - x1 * s0;
        float y1 = x1 * c1 + x0 * s1;
        g_KH[b]       = __float2half(y0);
        g_KH[b + 128] = __float2half(y1);
    }
}

// ---------------- V transpose (hi only) ----------------
__global__ void __launch_bounds__(256)
k_vtrans()
{
    __shared__ float t[32][33];
    int bs = blockIdx.x * 32, bo = blockIdx.y * 32;
    int tx = threadIdx.x, ty = threadIdx.y;
#pragma unroll
    for (int j = 0; j < 32; j += 8)
        t[ty + j][tx] = g_V[(size_t)(bs + ty + j) * (NKV * DH) + bo + tx];
    __syncthreads();
#pragma unroll
    for (int j = 0; j < 32; j += 8) {
        float v = t[tx][ty + j];
        g_VtH[(size_t)(bo + ty + j) * S_LEN + bs + tx] = __float2half(v);
    }
}

// ---------------- band softmax (fast-math) -> P hi only ----------------
__global__ void __launch_bounds__(256)
k_softmax()
{
    int row  = blockIdx.x * 8 + (threadIdx.x >> 5);
    int lane = threadIdx.x & 31;
    int h = row >> 11;
    int q = row & 2047;

    size_t base = ((size_t)h * S_LEN + q) * BANDW;
    const float* p = g_S + base;
    int r  = q >> 7;
    int c0 = ((r - 8 > 0) ? (r - 8) : 0) * 128;
    int kmin = (q - (WINDOW - 1) > 0) ? (q - (WINDOW - 1)) : 0;

    float v[36];
    float m = -1e30f;
#pragma unroll
    for (int i = 0; i < 36; ++i) {
        int j = lane + 32 * i;
        int k = c0 + j;
        float tt;
        if (k >= kmin && k <= q) {
            float x = p[j] * (SCALING / SOFTCAP);
            x = fminf(fmaxf(x, -15.0f), 15.0f);
            float e2 = __expf(2.0f * x);
            tt = SOFTCAP * ((e2 - 1.0f) / (e2 + 1.0f));
        } else {
            tt = -1e30f;
        }
        v[i] = tt;
        m = fmaxf(m, tt);
    }
#pragma unroll
    for (int o = 16; o > 0; o >>= 1)
        m = fmaxf(m, __shfl_xor_sync(0xFFFFFFFFu, m, o));

    float l = 0.0f;
#pragma unroll
    for (int i = 0; i < 36; ++i) {
        v[i] = __expf(v[i] - m);
        l += v[i];
    }
#pragma unroll
    for (int o = 16; o > 0; o >>= 1)
        l += __shfl_xor_sync(0xFFFFFFFFu, l, o);

    float inv = 1.0f / l;
#pragma unroll
    for (int i = 0; i < 36; ++i)
        g_PH[base + lane + 32 * i] = __float2half(v[i] * inv);
}

// ---------------- launch ----------------
extern "C" void kernel_launch(void* const* d_in, const int* in_sizes, int n_in,
                              void* d_out, int out_size)
{
    const float* hs   = (const float*)d_in[0];
    const float* cosb = (const float*)d_in[1];
    const float* sinb = (const float*)d_in[2];
    const float* wq   = (const float*)d_in[3];
    const float* wk   = (const float*)d_in[4];
    const float* wv   = (const float*)d_in[5];
    const float* wo   = (const float*)d_in[6];
    float* out = (float*)d_out;

    cudaFuncSetAttribute(k_gemm_qkv, cudaFuncAttributeMaxDynamicSharedMemorySize, SMEM2);
    cudaFuncSetAttribute(k_gemm_o,   cudaFuncAttributeMaxDynamicSharedMemorySize, SMEM1);
    cudaFuncSetAttribute(k_attn_s,   cudaFuncAttributeMaxDynamicSharedMemorySize, SMEM2);
    cudaFuncSetAttribute(k_attn_pv,  cudaFuncAttributeMaxDynamicSharedMemorySize, SMEM1);

    // fused split of all inputs
    k_split_all<<<N_SPLIT_TOTAL / 256, 256>>>(hs, wq, wk, wv, wo);

    // fused QKV projections (Q/K 2-product, V 1-product)
    k_gemm_qkv<<<dim3(64, S_LEN / 128), 128, SMEM2>>>();

    // RoPE + split, V transpose
    k_rope_split<<<(S_LEN * (NHQ + NKV) * 128) / 256, 256>>>(cosb, sinb);
    k_vtrans<<<dim3(S_LEN / 32, (NKV * DH) / 32), dim3(32, 8)>>>();

    // banded scores (2-product)
    k_attn_s<<<dim3(9, S_LEN / 128, NHQ), 128, SMEM2>>>();

    // softcap + mask + softmax -> P hi
    k_softmax<<<(NHQ * S_LEN) / 8, 256>>>();

    // PV (1-product) -> AO hi
    k_attn_pv<<<dim3(2, S_LEN / 128, NHQ), 128, SMEM1>>>();

    // output projection (1-product)
    k_gemm_o<<<dim3(HID / 128, S_LEN / 128), 128, SMEM1>>>(out);
}